// round 2
// baseline (speedup 1.0000x reference)
#include <cuda_runtime.h>
#include <math.h>

#define T_STEPS 8
#define NN      20000
#define FIN_DIM 32
#define EE      160000
#define HID     128
#define G3      384

typedef unsigned long long u64;

// ------------------------- scratch (device globals) -------------------------
__device__ float g_h[(size_t)T_STEPS * NN * HID];   // gru_out then h_stack
__device__ float g_tmp[(size_t)NN * HID];           // conv ping buffer
__device__ float g_q[(size_t)NN * HID];
__device__ float g_k[(size_t)NN * HID];
__device__ float g_v[(size_t)NN * HID];
__device__ float g_macc[(size_t)NN * HID];          // unnormalized message accum
__device__ float g_gi[(size_t)T_STEPS * NN * G3];   // batched GRU input gates
__device__ float g_gh[(size_t)NN * G3];
__device__ float g_hprev[(size_t)NN * HID];
__device__ float g_alpha[EE];
__device__ int   g_amax[NN];
__device__ float g_denom[NN];
__device__ float g_coef[NN];                        // sum a_e * ea_e per dst
__device__ float g_qwe[NN];                         // (q . We)/sqrt(C) per node
__device__ float g_hattn[(size_t)NN * HID];

// ------------------------------- helpers ------------------------------------
__device__ __forceinline__ float warp_sum(float v) {
#pragma unroll
    for (int o = 16; o; o >>= 1) v += __shfl_xor_sync(0xffffffffu, v, o);
    return v;
}
__device__ __forceinline__ int f2ord(float f) { int i = __float_as_int(f); return i >= 0 ? i : i ^ 0x7fffffff; }
__device__ __forceinline__ float ord2f(int i) { return __int_as_float(i >= 0 ? i : i ^ 0x7fffffff); }
__device__ __forceinline__ void ffma2(u64& d, u64 a, u64 b) {
    asm("fma.rn.f32x2 %0,%1,%2,%0;" : "+l"(d) : "l"(a), "l"(b));
}
// 128-bit shared load as two packed u64 (pre-paired FFMA2 operands)
__device__ __forceinline__ void lds2(u64& x, u64& y, const float* p) {
    unsigned a = (unsigned)__cvta_generic_to_shared(p);
    asm volatile("ld.shared.v2.u64 {%0,%1},[%2];" : "=l"(x), "=l"(y) : "r"(a));
}
__device__ __forceinline__ float half_lo(u64 v) { return __int_as_float((int)(unsigned)v); }
__device__ __forceinline__ float half_hi(u64 v) { return __int_as_float((int)(unsigned)(v >> 32)); }
__device__ __forceinline__ float sigf(float x) { return 1.0f / (1.0f + expf(-x)); }

// --------------------------- SGEMM core (128x128 tile) -----------------------
// Computes Cb[r, 0..127] = A[r,:K] . Wb[c,:K] + bb[c] for one 128-col block.
// 256 threads, 8x8 microtile, double-buffered, FFMA2 throughout.
__device__ __forceinline__ void gemm_body(
    const float* __restrict__ A, const float* __restrict__ Wb,
    const float* __restrict__ bb, float* __restrict__ Cb,
    int nrows, int K, int ldC)
{
    __shared__ float As[2][8][132];
    __shared__ float Bs[2][8][260];   // duplicated cols: value c at 2c and 2c+1

    const int tid = threadIdx.x;
    const int tx = tid & 15, ty = tid >> 4;
    const int brow = blockIdx.y << 7;
    const int lrow = tid >> 1;            // 0..127
    const int kq = (tid & 1) << 2;        // 0 or 4

    const int arow = brow + lrow;
    const bool avalid = arow < nrows;
    const float* Ap = A + (size_t)arow * K + kq;
    const float* Wp = Wb + (size_t)lrow * K + kq;

    u64 acc[4][8];
#pragma unroll
    for (int i = 0; i < 4; i++)
#pragma unroll
        for (int j = 0; j < 8; j++) acc[i][j] = 0ull;

    float4 af = avalid ? *(const float4*)Ap : make_float4(0.f, 0.f, 0.f, 0.f);
    float4 wf = *(const float4*)Wp;

    {
        const float* a = (const float*)&af;
        const float* w = (const float*)&wf;
#pragma unroll
        for (int j = 0; j < 4; j++) {
            As[0][kq + j][lrow] = a[j];
            Bs[0][kq + j][2 * lrow] = w[j];
            Bs[0][kq + j][2 * lrow + 1] = w[j];
        }
    }
    __syncthreads();

    int buf = 0;
    for (int k0 = 0; k0 < K; k0 += 8) {
        const bool more = (k0 + 8) < K;
        if (more) {
            af = avalid ? *(const float4*)(Ap + k0 + 8) : make_float4(0.f, 0.f, 0.f, 0.f);
            wf = *(const float4*)(Wp + k0 + 8);
        }
#pragma unroll
        for (int kk = 0; kk < 8; kk++) {
            u64 ap[4], bd[8];
            lds2(ap[0], ap[1], &As[buf][kk][ty * 4]);
            lds2(ap[2], ap[3], &As[buf][kk][ty * 4 + 64]);
            lds2(bd[0], bd[1], &Bs[buf][kk][tx * 8]);
            lds2(bd[2], bd[3], &Bs[buf][kk][tx * 8 + 4]);
            lds2(bd[4], bd[5], &Bs[buf][kk][tx * 8 + 128]);
            lds2(bd[6], bd[7], &Bs[buf][kk][tx * 8 + 132]);
#pragma unroll
            for (int rp = 0; rp < 4; rp++)
#pragma unroll
                for (int c = 0; c < 8; c++) ffma2(acc[rp][c], ap[rp], bd[c]);
        }
        if (more) {
            const int nb = buf ^ 1;
            const float* a = (const float*)&af;
            const float* w = (const float*)&wf;
#pragma unroll
            for (int j = 0; j < 4; j++) {
                As[nb][kq + j][lrow] = a[j];
                Bs[nb][kq + j][2 * lrow] = w[j];
                Bs[nb][kq + j][2 * lrow + 1] = w[j];
            }
            __syncthreads();
            buf = nb;
        }
    }

    // epilogue
    float bv[8];
#pragma unroll
    for (int c = 0; c < 4; c++) { bv[c] = bb[tx * 4 + c]; bv[4 + c] = bb[tx * 4 + 64 + c]; }
    const int rowoff[4] = {0, 2, 64, 66};
#pragma unroll
    for (int rp = 0; rp < 4; rp++) {
        const int rb = brow + ty * 4 + rowoff[rp];
#pragma unroll
        for (int p = 0; p < 2; p++) {
            const int r = rb + p;
            if (r >= nrows) continue;
            float4 o0, o1;
            if (p == 0) {
                o0 = make_float4(half_lo(acc[rp][0]) + bv[0], half_lo(acc[rp][1]) + bv[1],
                                 half_lo(acc[rp][2]) + bv[2], half_lo(acc[rp][3]) + bv[3]);
                o1 = make_float4(half_lo(acc[rp][4]) + bv[4], half_lo(acc[rp][5]) + bv[5],
                                 half_lo(acc[rp][6]) + bv[6], half_lo(acc[rp][7]) + bv[7]);
            } else {
                o0 = make_float4(half_hi(acc[rp][0]) + bv[0], half_hi(acc[rp][1]) + bv[1],
                                 half_hi(acc[rp][2]) + bv[2], half_hi(acc[rp][3]) + bv[3]);
                o1 = make_float4(half_hi(acc[rp][4]) + bv[4], half_hi(acc[rp][5]) + bv[5],
                                 half_hi(acc[rp][6]) + bv[6], half_hi(acc[rp][7]) + bv[7]);
            }
            *(float4*)&Cb[(size_t)r * ldC + tx * 4] = o0;
            *(float4*)&Cb[(size_t)r * ldC + tx * 4 + 64] = o1;
        }
    }
}

// generic: grid (M/128, ceil(nrows/128))
__global__ void __launch_bounds__(256, 2) sgemm128(
    const float* __restrict__ A, const float* __restrict__ W,
    const float* __restrict__ bias, float* __restrict__ C,
    int nrows, int K, int M)
{
    const int cb = blockIdx.x << 7;
    gemm_body(A, W + (size_t)cb * K, bias + cb, C + cb, nrows, K, M);
}

// fused conv projections: blockIdx.x selects q/k/v/skip. grid (4, ceil(nrows/128))
__global__ void __launch_bounds__(256, 2) sgemm_conv4(
    const float* __restrict__ A,
    const float* __restrict__ Wq, const float* __restrict__ bq,
    const float* __restrict__ Wk, const float* __restrict__ bk,
    const float* __restrict__ Wv, const float* __restrict__ bv,
    const float* __restrict__ Ws, const float* __restrict__ bs,
    float* __restrict__ q, float* __restrict__ k,
    float* __restrict__ v, float* __restrict__ o, int nrows)
{
    const float* W; const float* b; float* C;
    switch (blockIdx.x) {
        case 0:  W = Wq; b = bq; C = q; break;
        case 1:  W = Wk; b = bk; C = k; break;
        case 2:  W = Wv; b = bv; C = v; break;
        default: W = Ws; b = bs; C = o; break;
    }
    gemm_body(A, W, b, C, nrows, 128, 128);
}

// ------------------------------- GRU gates ----------------------------------
__global__ void gru_gate(const float* __restrict__ gi, const float* __restrict__ gh,
                         float* __restrict__ hprev, float* __restrict__ hout)
{
    int idx = blockIdx.x * blockDim.x + threadIdx.x;
    if (idx >= NN * HID) return;
    int n = idx / HID, c = idx % HID;
    const float* gin = gi + (size_t)n * G3;
    const float* ghn = gh + (size_t)n * G3;
    float r = sigf(gin[c] + ghn[c]);
    float z = sigf(gin[HID + c] + ghn[HID + c]);
    float nn = tanhf(gin[2 * HID + c] + r * ghn[2 * HID + c]);
    float hp = hprev[idx];
    float hn = (1.0f - z) * nn + z * hp;
    hprev[idx] = hn;
    hout[idx] = hn;
}

// ------------------------- conv edge phase ----------------------------------
// per-node prep: qwe = (q.We)/sqrt(C); init segment state
__global__ void __launch_bounds__(256) prep_seg(
    const float* __restrict__ q, const float* __restrict__ We,
    float* __restrict__ qwe, int* __restrict__ amax,
    float* __restrict__ denom, float* __restrict__ coef)
{
    int n = (blockIdx.x * blockDim.x + threadIdx.x) >> 5;
    int lane = threadIdx.x & 31;
    if (n >= NN) return;
    float4 qq = *(const float4*)(q + (size_t)n * HID + lane * 4);
    float4 ww = *(const float4*)(We + lane * 4);
    float p = qq.x * ww.x + qq.y * ww.y + qq.z * ww.z + qq.w * ww.w;
    p = warp_sum(p);
    if (lane == 0) {
        qwe[n] = p * 0.08838834764831845f;
        amax[n] = f2ord(-INFINITY);
        denom[n] = 0.0f;
        coef[n] = 0.0f;
    }
}

// alpha[e] = (q[d].k[s])/sqrt(C) + ea*qwe[d]; segment max over dst
__global__ void __launch_bounds__(256) edge_alpha2(
    const float* __restrict__ q, const float* __restrict__ k,
    const int* __restrict__ src, const int* __restrict__ dst,
    const float* __restrict__ ea, const float* __restrict__ qwe,
    float* __restrict__ alpha, int* __restrict__ amax)
{
    int e = (blockIdx.x * blockDim.x + threadIdx.x) >> 5;
    int lane = threadIdx.x & 31;
    if (e >= EE) return;
    int s = src[e], d = dst[e];
    float4 qd = *(const float4*)(q + (size_t)d * HID + lane * 4);
    float4 ks = *(const float4*)(k + (size_t)s * HID + lane * 4);
    float p = qd.x * ks.x + qd.y * ks.y + qd.z * ks.z + qd.w * ks.w;
    p = warp_sum(p);
    if (lane == 0) {
        float al = p * 0.08838834764831845f + ea[e] * qwe[d];
        alpha[e] = al;
        atomicMax(&amax[d], f2ord(al));
    }
}

// unnormalized: macc[d] += ex*v[s]; denom[d] += ex; coef[d] += ex*ea
__global__ void __launch_bounds__(256) edge_msg2(
    const float* __restrict__ v,
    const int* __restrict__ src, const int* __restrict__ dst,
    const float* __restrict__ ea, const float* __restrict__ alpha,
    const int* __restrict__ amax, float* __restrict__ denom,
    float* __restrict__ coef, float* __restrict__ macc)
{
    int e = (blockIdx.x * blockDim.x + threadIdx.x) >> 5;
    int lane = threadIdx.x & 31;
    if (e >= EE) return;
    int s = src[e], d = dst[e];
    float a = expf(alpha[e] - ord2f(amax[d]));
    if (lane == 0) {
        atomicAdd(&denom[d], a);
        atomicAdd(&coef[d], a * ea[e]);
    }
    int i = lane << 2;
    float4 vv = *(const float4*)(v + (size_t)s * HID + i);
    float m0 = a * vv.x, m1 = a * vv.y, m2 = a * vv.z, m3 = a * vv.w;
    float* p = macc + (size_t)d * HID + i;
    asm volatile("red.global.add.v4.f32 [%0], {%1,%2,%3,%4};"
                 :: "l"(p), "f"(m0), "f"(m1), "f"(m2), "f"(m3) : "memory");
}

// out = leaky(skip + (macc + coef*We)/(denom+eps))
__global__ void finish_conv(
    float* __restrict__ out, const float* __restrict__ macc,
    const float* __restrict__ coef, const float* __restrict__ We,
    const float* __restrict__ denom)
{
    int idx = blockIdx.x * blockDim.x + threadIdx.x;
    if (idx >= NN * 32) return;
    int n = idx >> 5;
    int c4 = (idx & 31) << 2;
    float4 sk = *(const float4*)(out + ((size_t)n * HID + c4));
    float4 mc = *(const float4*)(macc + ((size_t)n * HID + c4));
    float4 we = *(const float4*)(We + c4);
    float cf = coef[n];
    float inv = 1.0f / (denom[n] + 1e-16f);
    float4 o;
    o.x = sk.x + (mc.x + cf * we.x) * inv;
    o.y = sk.y + (mc.y + cf * we.y) * inv;
    o.z = sk.z + (mc.z + cf * we.z) * inv;
    o.w = sk.w + (mc.w + cf * we.w) * inv;
    o.x = o.x > 0.f ? o.x : 0.01f * o.x;
    o.y = o.y > 0.f ? o.y : 0.01f * o.y;
    o.z = o.z > 0.f ? o.z : 0.01f * o.z;
    o.w = o.w > 0.f ? o.w : 0.01f * o.w;
    *(float4*)(out + ((size_t)n * HID + c4)) = o;
}

// --------------------- temporal attention + top-k (warp/node) ---------------
__global__ void __launch_bounds__(256) attn_topk(
    const float* __restrict__ h, const float* __restrict__ W,
    const float* __restrict__ b, float* __restrict__ hattn)
{
    int n = (blockIdx.x * blockDim.x + threadIdx.x) >> 5;
    int lane = threadIdx.x & 31;
    if (n >= NN) return;
    float s[T_STEPS];
#pragma unroll
    for (int t = 0; t < T_STEPS; t++) {
        const float* row = h + ((size_t)t * NN + n) * HID;
        float p = 0.0f;
#pragma unroll
        for (int i = lane; i < HID; i += 32) p = fmaf(row[i], W[i], p);
        s[t] = warp_sum(p) + b[0];
    }
    float mx = s[0];
#pragma unroll
    for (int t = 1; t < T_STEPS; t++) mx = fmaxf(mx, s[t]);
    float aw[T_STEPS]; float tot = 0.0f;
#pragma unroll
    for (int t = 0; t < T_STEPS; t++) { aw[t] = expf(s[t] - mx); tot += aw[t]; }
    float inv = 1.0f / tot;
#pragma unroll
    for (int t = 0; t < T_STEPS; t++) aw[t] *= inv;
    bool sel[T_STEPS];
#pragma unroll
    for (int t = 0; t < T_STEPS; t++) sel[t] = false;
    float sum3 = 0.0f;
#pragma unroll
    for (int r = 0; r < 3; r++) {
        float best = -1.0f; int bi = 0;
#pragma unroll
        for (int t = 0; t < T_STEPS; t++)
            if (!sel[t] && aw[t] > best) { best = aw[t]; bi = t; }
        sel[bi] = true; sum3 += best;
    }
    float winv = 1.0f / (sum3 + 1e-8f);
    float w[T_STEPS];
#pragma unroll
    for (int t = 0; t < T_STEPS; t++) w[t] = sel[t] ? aw[t] * winv : 0.0f;
#pragma unroll
    for (int i = lane; i < HID; i += 32) {
        float acc = 0.0f;
#pragma unroll
        for (int t = 0; t < T_STEPS; t++)
            acc = fmaf(w[t], h[((size_t)t * NN + n) * HID + i], acc);
        hattn[(size_t)n * HID + i] = acc;
    }
}

// ------------------------- output conv (C_out = 1) --------------------------
__global__ void init_seg(int* __restrict__ amax, float* __restrict__ denom)
{
    int i = blockIdx.x * blockDim.x + threadIdx.x;
    if (i < NN) { amax[i] = f2ord(-INFINITY); denom[i] = 0.0f; }
}

__global__ void __launch_bounds__(256) outconv_node(
    const float* __restrict__ x,
    const float* __restrict__ Wq, const float* __restrict__ bq,
    const float* __restrict__ Wk, const float* __restrict__ bk,
    const float* __restrict__ Wv, const float* __restrict__ bv,
    const float* __restrict__ Ws, const float* __restrict__ bs,
    float* __restrict__ qs, float* __restrict__ ks,
    float* __restrict__ vs, float* __restrict__ outp)
{
    int n = (blockIdx.x * blockDim.x + threadIdx.x) >> 5;
    int lane = threadIdx.x & 31;
    if (n >= NN) return;
    const float* xr = x + (size_t)n * HID;
    float pq = 0.f, pk = 0.f, pv = 0.f, ps = 0.f;
#pragma unroll
    for (int i = lane; i < HID; i += 32) {
        float xv = xr[i];
        pq = fmaf(xv, Wq[i], pq);
        pk = fmaf(xv, Wk[i], pk);
        pv = fmaf(xv, Wv[i], pv);
        ps = fmaf(xv, Ws[i], ps);
    }
    pq = warp_sum(pq); pk = warp_sum(pk); pv = warp_sum(pv); ps = warp_sum(ps);
    if (lane == 0) {
        qs[n] = pq + bq[0];
        ks[n] = pk + bk[0];
        vs[n] = pv + bv[0];
        outp[n] = ps + bs[0];
    }
}

__global__ void oc_alpha(const float* __restrict__ qs, const float* __restrict__ ks,
                         const int* __restrict__ src, const int* __restrict__ dst,
                         const float* __restrict__ ea, const float* __restrict__ We,
                         float* __restrict__ alpha, int* __restrict__ amax)
{
    int e = blockIdx.x * blockDim.x + threadIdx.x;
    if (e >= EE) return;
    int s = src[e], d = dst[e];
    float a = qs[d] * (ks[s] + ea[e] * We[0]);
    alpha[e] = a;
    atomicMax(&amax[d], f2ord(a));
}

__global__ void edge_ex(const int* __restrict__ dst, float* __restrict__ alpha,
                        const int* __restrict__ amax, float* __restrict__ denom)
{
    int e = blockIdx.x * blockDim.x + threadIdx.x;
    if (e >= EE) return;
    int d = dst[e];
    float ex = expf(alpha[e] - ord2f(amax[d]));
    alpha[e] = ex;
    atomicAdd(&denom[d], ex);
}

__global__ void oc_msg(const float* __restrict__ vs,
                       const int* __restrict__ src, const int* __restrict__ dst,
                       const float* __restrict__ ea, const float* __restrict__ We,
                       const float* __restrict__ ex, const float* __restrict__ denom,
                       float* __restrict__ outp)
{
    int e = blockIdx.x * blockDim.x + threadIdx.x;
    if (e >= EE) return;
    int s = src[e], d = dst[e];
    float a = ex[e] / (denom[d] + 1e-16f);
    atomicAdd(&outp[d], a * (vs[s] + ea[e] * We[0]));
}

// --------------------------------- host -------------------------------------
static float* symf(const void* sym) { void* p = nullptr; cudaGetSymbolAddress(&p, sym); return (float*)p; }

extern "C" void kernel_launch(void* const* d_in, const int* in_sizes, int n_in,
                              void* d_out, int out_size)
{
    const float* x_seq = (const float*)d_in[0];
    const int*   ei    = (const int*)d_in[1];
    const float* ea    = (const float*)d_in[2];
    const float* W_ih  = (const float*)d_in[3];
    const float* W_hh  = (const float*)d_in[4];
    const float* b_ih  = (const float*)d_in[5];
    const float* b_hh  = (const float*)d_in[6];
    const float* cWq = (const float*)d_in[7];  const float* cbq = (const float*)d_in[8];
    const float* cWk = (const float*)d_in[9];  const float* cbk = (const float*)d_in[10];
    const float* cWv = (const float*)d_in[11]; const float* cbv = (const float*)d_in[12];
    const float* cWe = (const float*)d_in[13];
    const float* cWs = (const float*)d_in[14]; const float* cbs = (const float*)d_in[15];
    const float* oWq = (const float*)d_in[16]; const float* obq = (const float*)d_in[17];
    const float* oWk = (const float*)d_in[18]; const float* obk = (const float*)d_in[19];
    const float* oWv = (const float*)d_in[20]; const float* obv = (const float*)d_in[21];
    const float* oWe = (const float*)d_in[22];
    const float* oWs = (const float*)d_in[23]; const float* obs = (const float*)d_in[24];
    const float* aW  = (const float*)d_in[25]; const float* ab  = (const float*)d_in[26];
    float* outp = (float*)d_out;

    float* ph     = symf(g_h);
    float* ptmp   = symf(g_tmp);
    float* pq     = symf(g_q);
    float* pk     = symf(g_k);
    float* pv     = symf(g_v);
    float* pmacc  = symf(g_macc);
    float* pgi    = symf(g_gi);
    float* pgh    = symf(g_gh);
    float* phprev = symf(g_hprev);
    float* palpha = symf(g_alpha);
    int*   pamax  = (int*)symf(g_amax);
    float* pdenom = symf(g_denom);
    float* pcoef  = symf(g_coef);
    float* pqwe   = symf(g_qwe);
    float* phattn = symf(g_hattn);

    const int nwblk = (NN + 7) / 8;            // warp-per-node
    const int ewblk = (EE + 7) / 8;            // warp-per-edge
    const int esblk = (EE + 255) / 256;        // thread-per-edge
    const int nsblk = (NN + 255) / 256;
    const int nhblk = (NN * HID + 255) / 256;
    const int fnblk = (NN * 32 + 255) / 256;   // finish (float4/thread)

    // ---------------- GRU ----------------
    cudaMemsetAsync(phprev, 0, (size_t)NN * HID * sizeof(float));
    // all T input gates at once: [T*N, 32] @ W_ih^T
    sgemm128<<<dim3(G3 / 128, (T_STEPS * NN + 127) / 128), 256>>>(
        x_seq, W_ih, b_ih, pgi, T_STEPS * NN, FIN_DIM, G3);
    for (int t = 0; t < T_STEPS; t++) {
        sgemm128<<<dim3(G3 / 128, (NN + 127) / 128), 256>>>(
            phprev, W_hh, b_hh, pgh, NN, HID, G3);
        gru_gate<<<nhblk, 256>>>(pgi + (size_t)t * NN * G3, pgh, phprev,
                                 ph + (size_t)t * NN * HID);
    }

    // ---------------- GNN: 2 TransformerConv layers per t ----------------
    for (int t = 0; t < T_STEPS; t++) {
        const int* src = ei + (size_t)t * 2 * EE;
        const int* dst = src + EE;
        const float* eat = ea + (size_t)t * EE;
        float* xt = ph + (size_t)t * NN * HID;

        for (int l = 0; l < 2; l++) {
            const float* in  = (l == 0) ? xt : ptmp;
            float*       out = (l == 0) ? ptmp : xt;
            const float* Wq = cWq + (size_t)l * HID * HID; const float* bq = cbq + (size_t)l * HID;
            const float* Wk = cWk + (size_t)l * HID * HID; const float* bk = cbk + (size_t)l * HID;
            const float* Wv = cWv + (size_t)l * HID * HID; const float* bv = cbv + (size_t)l * HID;
            const float* We = cWe + (size_t)l * HID;
            const float* Ws = cWs + (size_t)l * HID * HID; const float* bs = cbs + (size_t)l * HID;

            cudaMemsetAsync(pmacc, 0, (size_t)NN * HID * sizeof(float));
            sgemm_conv4<<<dim3(4, (NN + 127) / 128), 256>>>(
                in, Wq, bq, Wk, bk, Wv, bv, Ws, bs, pq, pk, pv, out, NN);
            prep_seg<<<nwblk, 256>>>(pq, We, pqwe, pamax, pdenom, pcoef);
            edge_alpha2<<<ewblk, 256>>>(pq, pk, src, dst, eat, pqwe, palpha, pamax);
            edge_msg2<<<ewblk, 256>>>(pv, src, dst, eat, palpha, pamax, pdenom, pcoef, pmacc);
            finish_conv<<<fnblk, 256>>>(out, pmacc, pcoef, We, pdenom);
        }
    }

    // ---------------- temporal attention + top-3 ----------------
    attn_topk<<<nwblk, 256>>>(ph, aW, ab, phattn);

    // ---------------- output TransformerConv (128 -> 1) ----------------
    {
        const int* src = ei + (size_t)(T_STEPS - 1) * 2 * EE;
        const int* dst = src + EE;
        const float* eat = ea + (size_t)(T_STEPS - 1) * EE;
        outconv_node<<<nwblk, 256>>>(phattn, oWq, obq, oWk, obk, oWv, obv, oWs, obs,
                                     pq, pk, pv, outp);
        init_seg<<<nsblk, 256>>>(pamax, pdenom);
        oc_alpha<<<esblk, 256>>>(pq, pk, src, dst, eat, oWe, palpha, pamax);
        edge_ex<<<esblk, 256>>>(dst, palpha, pamax, pdenom);
        oc_msg<<<esblk, 256>>>(pv, src, dst, eat, oWe, palpha, pdenom, outp);
    }
}

// round 3
// speedup vs baseline: 1.0059x; 1.0059x over previous
#include <cuda_runtime.h>
#include <math.h>

#define T_STEPS 8
#define NN      20000
#define FIN_DIM 32
#define EE      160000
#define HID     128
#define G3      384
#define TN      (T_STEPS * NN)
#define TE      (T_STEPS * EE)

typedef unsigned long long u64;

// ------------------------- scratch (device globals) -------------------------
__device__ float g_h[(size_t)TN * HID];     // gru_out then h_stack
__device__ float g_tmp[(size_t)TN * HID];   // conv layer-0 output
__device__ float g_q[(size_t)TN * HID];
__device__ float g_k[(size_t)TN * HID];
__device__ float g_v[(size_t)TN * HID];
__device__ float g_macc[(size_t)TN * HID];
__device__ float g_gi[(size_t)TN * G3];
__device__ float g_gh[(size_t)NN * G3];
__device__ float g_hprev[(size_t)NN * HID];
__device__ float g_alpha[TE];
__device__ int   g_amax[TN];
__device__ float g_denom[TN];
__device__ float g_coef[TN];
__device__ float g_qwe[TN];
__device__ float g_hattn[(size_t)NN * HID];

// ------------------------------- helpers ------------------------------------
__device__ __forceinline__ float warp_sum(float v) {
#pragma unroll
    for (int o = 16; o; o >>= 1) v += __shfl_xor_sync(0xffffffffu, v, o);
    return v;
}
__device__ __forceinline__ int f2ord(float f) { int i = __float_as_int(f); return i >= 0 ? i : i ^ 0x7fffffff; }
__device__ __forceinline__ float ord2f(int i) { return __int_as_float(i >= 0 ? i : i ^ 0x7fffffff); }
__device__ __forceinline__ u64 pk2(float lo, float hi) {
    u64 r; asm("mov.b64 %0,{%1,%2};" : "=l"(r) : "f"(lo), "f"(hi)); return r;
}
__device__ __forceinline__ void ffma2(u64& d, u64 a, u64 b) {
    asm("fma.rn.f32x2 %0,%1,%2,%0;" : "+l"(d) : "l"(a), "l"(b));
}
__device__ __forceinline__ void lds2(u64& x, u64& y, const float* p) {
    unsigned a = (unsigned)__cvta_generic_to_shared(p);
    asm volatile("ld.shared.v2.u64 {%0,%1},[%2];" : "=l"(x), "=l"(y) : "r"(a));
}
__device__ __forceinline__ float half_lo(u64 v) { return __int_as_float((int)(unsigned)v); }
__device__ __forceinline__ float half_hi(u64 v) { return __int_as_float((int)(unsigned)(v >> 32)); }
__device__ __forceinline__ float sigf(float x) { return 1.0f / (1.0f + expf(-x)); }

// --------------------------- SGEMM core (128x64 tile) ------------------------
// Cb[r, 0..63] = A[r,:K] . Wb[c,:K] + bb[c].  256 threads, 4x8 microtile.
__device__ __forceinline__ void gemm_body64(
    const float* __restrict__ A, const float* __restrict__ Wb,
    const float* __restrict__ bb, float* __restrict__ Cb,
    int nrows, int K, int ldC)
{
    __shared__ float As[2][8][128];
    __shared__ float Bs[2][8][72];

    const int tid = threadIdx.x;
    const int ty = tid >> 3;        // 0..31 -> rows ty*4
    const int tx = tid & 7;         // cols tx*8
    const int brow = blockIdx.y << 7;

    const int lrA = tid >> 1, kqA = (tid & 1) << 2;
    const int lrB = tid >> 2, kqB = (tid & 3) << 1;
    const int arow = brow + lrA;
    const bool av = arow < nrows;
    const float* Ap = A + (size_t)arow * K + kqA;
    const float* Wp = Wb + (size_t)lrB * K + kqB;

    u64 acc[4][4];
#pragma unroll
    for (int i = 0; i < 4; i++)
#pragma unroll
        for (int j = 0; j < 4; j++) acc[i][j] = 0ull;

    float4 af = av ? *(const float4*)Ap : make_float4(0.f, 0.f, 0.f, 0.f);
    float2 wf = *(const float2*)Wp;
    {
        const float* a = (const float*)&af;
#pragma unroll
        for (int j = 0; j < 4; j++) As[0][kqA + j][lrA] = a[j];
        Bs[0][kqB + 0][lrB] = wf.x;
        Bs[0][kqB + 1][lrB] = wf.y;
    }
    __syncthreads();

    int buf = 0;
    for (int k0 = 0; k0 < K; k0 += 8) {
        const bool more = (k0 + 8) < K;
        if (more) {
            af = av ? *(const float4*)(Ap + k0 + 8) : make_float4(0.f, 0.f, 0.f, 0.f);
            wf = *(const float2*)(Wp + k0 + 8);
        }
#pragma unroll
        for (int kk = 0; kk < 8; kk++) {
            float4 a4 = *(const float4*)&As[buf][kk][ty * 4];
            u64 b0, b1, b2, b3;
            lds2(b0, b1, &Bs[buf][kk][tx * 8]);
            lds2(b2, b3, &Bs[buf][kk][tx * 8 + 4]);
            u64 ap;
            ap = pk2(a4.x, a4.x);
            ffma2(acc[0][0], ap, b0); ffma2(acc[0][1], ap, b1);
            ffma2(acc[0][2], ap, b2); ffma2(acc[0][3], ap, b3);
            ap = pk2(a4.y, a4.y);
            ffma2(acc[1][0], ap, b0); ffma2(acc[1][1], ap, b1);
            ffma2(acc[1][2], ap, b2); ffma2(acc[1][3], ap, b3);
            ap = pk2(a4.z, a4.z);
            ffma2(acc[2][0], ap, b0); ffma2(acc[2][1], ap, b1);
            ffma2(acc[2][2], ap, b2); ffma2(acc[2][3], ap, b3);
            ap = pk2(a4.w, a4.w);
            ffma2(acc[3][0], ap, b0); ffma2(acc[3][1], ap, b1);
            ffma2(acc[3][2], ap, b2); ffma2(acc[3][3], ap, b3);
        }
        if (more) {
            const int nb = buf ^ 1;
            const float* a = (const float*)&af;
#pragma unroll
            for (int j = 0; j < 4; j++) As[nb][kqA + j][lrA] = a[j];
            Bs[nb][kqB + 0][lrB] = wf.x;
            Bs[nb][kqB + 1][lrB] = wf.y;
            __syncthreads();
            buf = nb;
        }
    }

    float bv[8];
#pragma unroll
    for (int j = 0; j < 8; j++) bv[j] = bb[tx * 8 + j];
#pragma unroll
    for (int r = 0; r < 4; r++) {
        const int row = brow + ty * 4 + r;
        if (row >= nrows) continue;
        float4 o0 = make_float4(half_lo(acc[r][0]) + bv[0], half_hi(acc[r][0]) + bv[1],
                                half_lo(acc[r][1]) + bv[2], half_hi(acc[r][1]) + bv[3]);
        float4 o1 = make_float4(half_lo(acc[r][2]) + bv[4], half_hi(acc[r][2]) + bv[5],
                                half_lo(acc[r][3]) + bv[6], half_hi(acc[r][3]) + bv[7]);
        *(float4*)&Cb[(size_t)row * ldC + tx * 8] = o0;
        *(float4*)&Cb[(size_t)row * ldC + tx * 8 + 4] = o1;
    }
}

// generic: grid (M/64, ceil(nrows/128))
__global__ void __launch_bounds__(256, 3) sgemm64(
    const float* __restrict__ A, const float* __restrict__ W,
    const float* __restrict__ bias, float* __restrict__ C,
    int nrows, int K, int M)
{
    const int cb = blockIdx.x << 6;
    gemm_body64(A, W + (size_t)cb * K, bias + cb, C + cb, nrows, K, M);
}

// fused conv projections: grid (8, ceil(nrows/128)); x = proj*2 + colblock
__global__ void __launch_bounds__(256, 3) sgemm_conv4(
    const float* __restrict__ A,
    const float* __restrict__ Wq, const float* __restrict__ bq,
    const float* __restrict__ Wk, const float* __restrict__ bk,
    const float* __restrict__ Wv, const float* __restrict__ bv,
    const float* __restrict__ Ws, const float* __restrict__ bs,
    float* __restrict__ q, float* __restrict__ k,
    float* __restrict__ v, float* __restrict__ o, int nrows)
{
    const int proj = blockIdx.x >> 1;
    const int cb = (blockIdx.x & 1) << 6;
    const float* W; const float* b; float* C;
    switch (proj) {
        case 0:  W = Wq; b = bq; C = q; break;
        case 1:  W = Wk; b = bk; C = k; break;
        case 2:  W = Wv; b = bv; C = v; break;
        default: W = Ws; b = bs; C = o; break;
    }
    gemm_body64(A, W + (size_t)cb * HID, b + cb, C + cb, nrows, HID, HID);
}

// ------------------------------- GRU gates ----------------------------------
__global__ void gru_gate(const float* __restrict__ gi, const float* __restrict__ gh,
                         float* __restrict__ hprev, float* __restrict__ hout)
{
    int idx = blockIdx.x * blockDim.x + threadIdx.x;
    if (idx >= NN * HID) return;
    int n = idx / HID, c = idx % HID;
    const float* gin = gi + (size_t)n * G3;
    const float* ghn = gh + (size_t)n * G3;
    float r = sigf(gin[c] + ghn[c]);
    float z = sigf(gin[HID + c] + ghn[HID + c]);
    float nn = tanhf(gin[2 * HID + c] + r * ghn[2 * HID + c]);
    float hp = hprev[idx];
    float hn = (1.0f - z) * nn + z * hp;
    hprev[idx] = hn;
    hout[idx] = hn;
}

// ------------------------- conv edge phase (batched over T) -----------------
__global__ void __launch_bounds__(256) prep_seg(
    const float* __restrict__ q, const float* __restrict__ We,
    float* __restrict__ qwe, int* __restrict__ amax,
    float* __restrict__ denom, float* __restrict__ coef)
{
    int n = (blockIdx.x * blockDim.x + threadIdx.x) >> 5;
    int lane = threadIdx.x & 31;
    if (n >= TN) return;
    float4 qq = *(const float4*)(q + (size_t)n * HID + lane * 4);
    float4 ww = *(const float4*)(We + lane * 4);
    float p = qq.x * ww.x + qq.y * ww.y + qq.z * ww.z + qq.w * ww.w;
    p = warp_sum(p);
    if (lane == 0) {
        qwe[n] = p * 0.08838834764831845f;
        amax[n] = f2ord(-INFINITY);
        denom[n] = 0.0f;
        coef[n] = 0.0f;
    }
}

__global__ void __launch_bounds__(256) edge_alpha_b(
    const float* __restrict__ q, const float* __restrict__ k,
    const int* __restrict__ ei, const float* __restrict__ ea,
    const float* __restrict__ qwe,
    float* __restrict__ alpha, int* __restrict__ amax)
{
    int w = (blockIdx.x * blockDim.x + threadIdx.x) >> 5;
    int lane = threadIdx.x & 31;
    if (w >= TE) return;
    int t = w / EE, e = w - t * EE;
    const int* eib = ei + (size_t)t * 2 * EE;
    int s = eib[e] + t * NN;
    int d = eib[EE + e] + t * NN;
    float4 qd = *(const float4*)(q + (size_t)d * HID + lane * 4);
    float4 ks = *(const float4*)(k + (size_t)s * HID + lane * 4);
    float p = qd.x * ks.x + qd.y * ks.y + qd.z * ks.z + qd.w * ks.w;
    p = warp_sum(p);
    if (lane == 0) {
        float al = p * 0.08838834764831845f + ea[w] * qwe[d];
        alpha[w] = al;
        atomicMax(&amax[d], f2ord(al));
    }
}

__global__ void __launch_bounds__(256) edge_msg_b(
    const float* __restrict__ v,
    const int* __restrict__ ei, const float* __restrict__ ea,
    const float* __restrict__ alpha, const int* __restrict__ amax,
    float* __restrict__ denom, float* __restrict__ coef,
    float* __restrict__ macc)
{
    int w = (blockIdx.x * blockDim.x + threadIdx.x) >> 5;
    int lane = threadIdx.x & 31;
    if (w >= TE) return;
    int t = w / EE, e = w - t * EE;
    const int* eib = ei + (size_t)t * 2 * EE;
    int s = eib[e] + t * NN;
    int d = eib[EE + e] + t * NN;
    float a = expf(alpha[w] - ord2f(amax[d]));
    if (lane == 0) {
        atomicAdd(&denom[d], a);
        atomicAdd(&coef[d], a * ea[w]);
    }
    int i = lane << 2;
    float4 vv = *(const float4*)(v + (size_t)s * HID + i);
    float m0 = a * vv.x, m1 = a * vv.y, m2 = a * vv.z, m3 = a * vv.w;
    float* p = macc + (size_t)d * HID + i;
    asm volatile("red.global.add.v4.f32 [%0], {%1,%2,%3,%4};"
                 :: "l"(p), "f"(m0), "f"(m1), "f"(m2), "f"(m3) : "memory");
}

__global__ void finish_conv(
    float* __restrict__ out, const float* __restrict__ macc,
    const float* __restrict__ coef, const float* __restrict__ We,
    const float* __restrict__ denom)
{
    int idx = blockIdx.x * blockDim.x + threadIdx.x;
    if (idx >= TN * 32) return;
    int n = idx >> 5;
    int c4 = (idx & 31) << 2;
    float4 sk = *(const float4*)(out + ((size_t)n * HID + c4));
    float4 mc = *(const float4*)(macc + ((size_t)n * HID + c4));
    float4 we = *(const float4*)(We + c4);
    float cf = coef[n];
    float inv = 1.0f / (denom[n] + 1e-16f);
    float4 o;
    o.x = sk.x + (mc.x + cf * we.x) * inv;
    o.y = sk.y + (mc.y + cf * we.y) * inv;
    o.z = sk.z + (mc.z + cf * we.z) * inv;
    o.w = sk.w + (mc.w + cf * we.w) * inv;
    o.x = o.x > 0.f ? o.x : 0.01f * o.x;
    o.y = o.y > 0.f ? o.y : 0.01f * o.y;
    o.z = o.z > 0.f ? o.z : 0.01f * o.z;
    o.w = o.w > 0.f ? o.w : 0.01f * o.w;
    *(float4*)(out + ((size_t)n * HID + c4)) = o;
}

// --------------------- temporal attention + top-k (warp/node) ---------------
__global__ void __launch_bounds__(256) attn_topk(
    const float* __restrict__ h, const float* __restrict__ W,
    const float* __restrict__ b, float* __restrict__ hattn)
{
    int n = (blockIdx.x * blockDim.x + threadIdx.x) >> 5;
    int lane = threadIdx.x & 31;
    if (n >= NN) return;
    float s[T_STEPS];
#pragma unroll
    for (int t = 0; t < T_STEPS; t++) {
        const float* row = h + ((size_t)t * NN + n) * HID;
        float p = 0.0f;
#pragma unroll
        for (int i = lane; i < HID; i += 32) p = fmaf(row[i], W[i], p);
        s[t] = warp_sum(p) + b[0];
    }
    float mx = s[0];
#pragma unroll
    for (int t = 1; t < T_STEPS; t++) mx = fmaxf(mx, s[t]);
    float aw[T_STEPS]; float tot = 0.0f;
#pragma unroll
    for (int t = 0; t < T_STEPS; t++) { aw[t] = expf(s[t] - mx); tot += aw[t]; }
    float inv = 1.0f / tot;
#pragma unroll
    for (int t = 0; t < T_STEPS; t++) aw[t] *= inv;
    bool sel[T_STEPS];
#pragma unroll
    for (int t = 0; t < T_STEPS; t++) sel[t] = false;
    float sum3 = 0.0f;
#pragma unroll
    for (int r = 0; r < 3; r++) {
        float best = -1.0f; int bi = 0;
#pragma unroll
        for (int t = 0; t < T_STEPS; t++)
            if (!sel[t] && aw[t] > best) { best = aw[t]; bi = t; }
        sel[bi] = true; sum3 += best;
    }
    float winv = 1.0f / (sum3 + 1e-8f);
    float w[T_STEPS];
#pragma unroll
    for (int t = 0; t < T_STEPS; t++) w[t] = sel[t] ? aw[t] * winv : 0.0f;
#pragma unroll
    for (int i = lane; i < HID; i += 32) {
        float acc = 0.0f;
#pragma unroll
        for (int t = 0; t < T_STEPS; t++)
            acc = fmaf(w[t], h[((size_t)t * NN + n) * HID + i], acc);
        hattn[(size_t)n * HID + i] = acc;
    }
}

// ------------------------- output conv (C_out = 1) --------------------------
__global__ void init_seg(int* __restrict__ amax, float* __restrict__ denom)
{
    int i = blockIdx.x * blockDim.x + threadIdx.x;
    if (i < NN) { amax[i] = f2ord(-INFINITY); denom[i] = 0.0f; }
}

__global__ void __launch_bounds__(256) outconv_node(
    const float* __restrict__ x,
    const float* __restrict__ Wq, const float* __restrict__ bq,
    const float* __restrict__ Wk, const float* __restrict__ bk,
    const float* __restrict__ Wv, const float* __restrict__ bv,
    const float* __restrict__ Ws, const float* __restrict__ bs,
    float* __restrict__ qs, float* __restrict__ ks,
    float* __restrict__ vs, float* __restrict__ outp)
{
    int n = (blockIdx.x * blockDim.x + threadIdx.x) >> 5;
    int lane = threadIdx.x & 31;
    if (n >= NN) return;
    const float* xr = x + (size_t)n * HID;
    float pq = 0.f, pk = 0.f, pv = 0.f, ps = 0.f;
#pragma unroll
    for (int i = lane; i < HID; i += 32) {
        float xv = xr[i];
        pq = fmaf(xv, Wq[i], pq);
        pk = fmaf(xv, Wk[i], pk);
        pv = fmaf(xv, Wv[i], pv);
        ps = fmaf(xv, Ws[i], ps);
    }
    pq = warp_sum(pq); pk = warp_sum(pk); pv = warp_sum(pv); ps = warp_sum(ps);
    if (lane == 0) {
        qs[n] = pq + bq[0];
        ks[n] = pk + bk[0];
        vs[n] = pv + bv[0];
        outp[n] = ps + bs[0];
    }
}

__global__ void oc_alpha(const float* __restrict__ qs, const float* __restrict__ ks,
                         const int* __restrict__ src, const int* __restrict__ dst,
                         const float* __restrict__ ea, const float* __restrict__ We,
                         float* __restrict__ alpha, int* __restrict__ amax)
{
    int e = blockIdx.x * blockDim.x + threadIdx.x;
    if (e >= EE) return;
    int s = src[e], d = dst[e];
    float a = qs[d] * (ks[s] + ea[e] * We[0]);
    alpha[e] = a;
    atomicMax(&amax[d], f2ord(a));
}

__global__ void edge_ex(const int* __restrict__ dst, float* __restrict__ alpha,
                        const int* __restrict__ amax, float* __restrict__ denom)
{
    int e = blockIdx.x * blockDim.x + threadIdx.x;
    if (e >= EE) return;
    int d = dst[e];
    float ex = expf(alpha[e] - ord2f(amax[d]));
    alpha[e] = ex;
    atomicAdd(&denom[d], ex);
}

__global__ void oc_msg(const float* __restrict__ vs,
                       const int* __restrict__ src, const int* __restrict__ dst,
                       const float* __restrict__ ea, const float* __restrict__ We,
                       const float* __restrict__ ex, const float* __restrict__ denom,
                       float* __restrict__ outp)
{
    int e = blockIdx.x * blockDim.x + threadIdx.x;
    if (e >= EE) return;
    int s = src[e], d = dst[e];
    float a = ex[e] / (denom[d] + 1e-16f);
    atomicAdd(&outp[d], a * (vs[s] + ea[e] * We[0]));
}

// --------------------------------- host -------------------------------------
static float* symf(const void* sym) { void* p = nullptr; cudaGetSymbolAddress(&p, sym); return (float*)p; }

extern "C" void kernel_launch(void* const* d_in, const int* in_sizes, int n_in,
                              void* d_out, int out_size)
{
    const float* x_seq = (const float*)d_in[0];
    const int*   ei    = (const int*)d_in[1];
    const float* ea    = (const float*)d_in[2];
    const float* W_ih  = (const float*)d_in[3];
    const float* W_hh  = (const float*)d_in[4];
    const float* b_ih  = (const float*)d_in[5];
    const float* b_hh  = (const float*)d_in[6];
    const float* cWq = (const float*)d_in[7];  const float* cbq = (const float*)d_in[8];
    const float* cWk = (const float*)d_in[9];  const float* cbk = (const float*)d_in[10];
    const float* cWv = (const float*)d_in[11]; const float* cbv = (const float*)d_in[12];
    const float* cWe = (const float*)d_in[13];
    const float* cWs = (const float*)d_in[14]; const float* cbs = (const float*)d_in[15];
    const float* oWq = (const float*)d_in[16]; const float* obq = (const float*)d_in[17];
    const float* oWk = (const float*)d_in[18]; const float* obk = (const float*)d_in[19];
    const float* oWv = (const float*)d_in[20]; const float* obv = (const float*)d_in[21];
    const float* oWe = (const float*)d_in[22];
    const float* oWs = (const float*)d_in[23]; const float* obs = (const float*)d_in[24];
    const float* aW  = (const float*)d_in[25]; const float* ab  = (const float*)d_in[26];
    float* outp = (float*)d_out;

    float* ph     = symf(g_h);
    float* ptmp   = symf(g_tmp);
    float* pq     = symf(g_q);
    float* pk     = symf(g_k);
    float* pv     = symf(g_v);
    float* pmacc  = symf(g_macc);
    float* pgi    = symf(g_gi);
    float* pgh    = symf(g_gh);
    float* phprev = symf(g_hprev);
    float* palpha = symf(g_alpha);
    int*   pamax  = (int*)symf(g_amax);
    float* pdenom = symf(g_denom);
    float* pcoef  = symf(g_coef);
    float* pqwe   = symf(g_qwe);
    float* phattn = symf(g_hattn);

    const int nwblk  = (NN + 7) / 8;
    const int tnwblk = (TN + 7) / 8;
    const int tewblk = (TE + 7) / 8;
    const int esblk  = (EE + 255) / 256;
    const int nsblk  = (NN + 255) / 256;
    const int nhblk  = (NN * HID + 255) / 256;
    const int fnblk  = (TN * 32 + 255) / 256;

    // ---------------- GRU ----------------
    cudaMemsetAsync(phprev, 0, (size_t)NN * HID * sizeof(float));
    sgemm64<<<dim3(G3 / 64, (TN + 127) / 128), 256>>>(
        x_seq, W_ih, b_ih, pgi, TN, FIN_DIM, G3);
    for (int t = 0; t < T_STEPS; t++) {
        sgemm64<<<dim3(G3 / 64, (NN + 127) / 128), 256>>>(
            phprev, W_hh, b_hh, pgh, NN, HID, G3);
        gru_gate<<<nhblk, 256>>>(pgi + (size_t)t * NN * G3, pgh, phprev,
                                 ph + (size_t)t * NN * HID);
    }

    // ---------------- GNN: 2 layers, batched over all T ----------------
    for (int l = 0; l < 2; l++) {
        const float* in  = (l == 0) ? ph : ptmp;
        float*       out = (l == 0) ? ptmp : ph;
        const float* Wq = cWq + (size_t)l * HID * HID; const float* bq = cbq + (size_t)l * HID;
        const float* Wk = cWk + (size_t)l * HID * HID; const float* bk = cbk + (size_t)l * HID;
        const float* Wv = cWv + (size_t)l * HID * HID; const float* bv = cbv + (size_t)l * HID;
        const float* We = cWe + (size_t)l * HID;
        const float* Ws = cWs + (size_t)l * HID * HID; const float* bs = cbs + (size_t)l * HID;

        cudaMemsetAsync(pmacc, 0, (size_t)TN * HID * sizeof(float));
        sgemm_conv4<<<dim3(8, (TN + 127) / 128), 256>>>(
            in, Wq, bq, Wk, bk, Wv, bv, Ws, bs, pq, pk, pv, out, TN);
        prep_seg<<<tnwblk, 256>>>(pq, We, pqwe, pamax, pdenom, pcoef);
        edge_alpha_b<<<tewblk, 256>>>(pq, pk, ei, ea, pqwe, palpha, pamax);
        edge_msg_b<<<tewblk, 256>>>(pv, ei, ea, palpha, pamax, pdenom, pcoef, pmacc);
        finish_conv<<<fnblk, 256>>>(out, pmacc, pcoef, We, pdenom);
    }

    // ---------------- temporal attention + top-3 ----------------
    attn_topk<<<nwblk, 256>>>(ph, aW, ab, phattn);

    // ---------------- output TransformerConv (128 -> 1) ----------------
    {
        const int* src = ei + (size_t)(T_STEPS - 1) * 2 * EE;
        const int* dst = src + EE;
        const float* eat = ea + (size_t)(T_STEPS - 1) * EE;
        outconv_node<<<nwblk, 256>>>(phattn, oWq, obq, oWk, obk, oWv, obv, oWs, obs,
                                     pq, pk, pv, outp);
        init_seg<<<nsblk, 256>>>(pamax, pdenom);
        oc_alpha<<<esblk, 256>>>(pq, pk, src, dst, eat, oWe, palpha, pamax);
        edge_ex<<<esblk, 256>>>(dst, palpha, pamax, pdenom);
        oc_msg<<<esblk, 256>>>(pv, src, dst, eat, oWe, palpha, pdenom, outp);
    }
}

// round 6
// speedup vs baseline: 1.3215x; 1.3138x over previous
#include <cuda_runtime.h>
#include <cuda_bf16.h>
#include <math.h>
#include <stdint.h>

#define T_STEPS 8
#define NN      20000
#define FIN_DIM 32
#define EE      160000
#define HID     128
#define G3      384
#define TN      (T_STEPS * NN)
#define TE      (T_STEPS * EE)

typedef unsigned long long u64;

// ------------------------- scratch (device globals) -------------------------
__device__ float g_h[(size_t)TN * HID];
__device__ float g_tmp[(size_t)TN * HID];
__device__ float g_q[(size_t)TN * HID];
__device__ float g_k[(size_t)TN * HID];
__device__ float g_v[(size_t)TN * HID];
__device__ float g_macc[(size_t)TN * HID];
__device__ float g_gi[(size_t)TN * G3];
__device__ float g_gh[(size_t)NN * G3];
__device__ float g_hprev[(size_t)NN * HID];
__device__ float g_alpha[TE];
__device__ int   g_amax[TN];
__device__ float g_denom[TN];
__device__ float g_coef[TN];
__device__ float g_qwe[TN];
__device__ float g_hattn[(size_t)NN * HID];
__device__ __align__(16) __nv_bfloat16 g_wprep[577536];  // 3-level split weights

// prepped-weight base offsets (bf16 elements); 3 levels contiguous per weight
#define WIH 0        // level stride 12288
#define WHH 36864    // level stride 49152
#define WQ  184320   // level stride 32768
#define WK  282624
#define WV  380928
#define WS  479232

// ------------------------------- helpers ------------------------------------
__device__ __forceinline__ float warp_sum(float v) {
#pragma unroll
    for (int o = 16; o; o >>= 1) v += __shfl_xor_sync(0xffffffffu, v, o);
    return v;
}
__device__ __forceinline__ int f2ord(float f) { int i = __float_as_int(f); return i >= 0 ? i : i ^ 0x7fffffff; }
__device__ __forceinline__ float ord2f(int i) { return __int_as_float(i >= 0 ? i : i ^ 0x7fffffff); }
__device__ __forceinline__ float sigf(float x) { return 1.0f / (1.0f + expf(-x)); }

// --------------------------- mma.sync GEMM -----------------------------------
// C[:, proj p] = A @ W_p^T + b_p.  3-level bf16 split, 6 passes, fp32 accum.
// Block 256 thr, tile 128x128, warp tile 64x32 (m16n8k16).

#define ASTR 20
#define SMBUF 2560               // bf16 elems per buffer (128 rows * ASTR)
#define SM_BYTES (12 * SMBUF * 2)

struct PArgs {
    const __nv_bfloat16* w[4];   // level-0 base; levels at +lvl, +2*lvl
    int lvl[4];
    const float* bias[4];
    float* out[4];
    int col[4];
    int ldc[4];
};

__device__ __forceinline__ void mma16816(float* c, const uint32_t* a, const uint32_t* b) {
    asm volatile(
        "mma.sync.aligned.m16n8k16.row.col.f32.bf16.bf16.f32 "
        "{%0,%1,%2,%3},{%4,%5,%6,%7},{%8,%9},{%0,%1,%2,%3};"
        : "+f"(c[0]), "+f"(c[1]), "+f"(c[2]), "+f"(c[3])
        : "r"(a[0]), "r"(a[1]), "r"(a[2]), "r"(a[3]), "r"(b[0]), "r"(b[1]));
}
__device__ __forceinline__ uint32_t lds32(const __nv_bfloat16* p) {
    return *(const uint32_t*)p;
}

__global__ void __launch_bounds__(256) mma_gemm(
    PArgs pa, const float* __restrict__ A, int nrows, int K)
{
    extern __shared__ __nv_bfloat16 sm[];
    // buffers: idx*SMBUF ; idx = which*2 + dbuf ; which: 0..2 = A lvl, 3..5 = B lvl
#define SBUF(which, db) (sm + (size_t)(((which) << 1) + (db)) * SMBUF)

    const int tid = threadIdx.x, wid = tid >> 5, lane = tid & 31;
    const int p = blockIdx.x;
    const int brow = blockIdx.y << 7;
    const __nv_bfloat16* W0 = pa.w[p];
    const int lvl = pa.lvl[p];

    const int wm = (wid & 1) * 64;
    const int wn = (wid >> 1) * 32;
    const int gr = lane >> 2;
    const int gc = (lane & 3) * 2;

    const int srow = tid >> 1;
    const int scol = (tid & 1) * 8;
    const int garow = brow + srow;
    const bool arowv = garow < nrows;
    const float* Agp = A + (size_t)garow * K + scol;
    const __nv_bfloat16* Wp0 = W0 + (size_t)srow * K + scol;

    float acc[4][4][4];
#pragma unroll
    for (int i = 0; i < 4; i++)
#pragma unroll
        for (int j = 0; j < 4; j++)
#pragma unroll
            for (int r = 0; r < 4; r++) acc[i][j][r] = 0.0f;

    const int nk = K >> 4;

    float4 a0, a1;
    uint4 w0s, w1s, w2s;
    a0 = make_float4(0.f, 0.f, 0.f, 0.f); a1 = a0;
    if (arowv) { a0 = *(const float4*)Agp; a1 = *(const float4*)(Agp + 4); }
    w0s = *(const uint4*)Wp0;
    w1s = *(const uint4*)(Wp0 + lvl);
    w2s = *(const uint4*)(Wp0 + 2 * lvl);

    for (int ks = 0; ks < nk; ks++) {
        const int cur = ks & 1;
        // ---- stage into smem (split A 3 levels; W levels pre-split) ----
        {
            __nv_bfloat16* A0r = SBUF(0, cur) + srow * ASTR + scol;
            __nv_bfloat16* A1r = SBUF(1, cur) + srow * ASTR + scol;
            __nv_bfloat16* A2r = SBUF(2, cur) + srow * ASTR + scol;
            const float av[8] = {a0.x, a0.y, a0.z, a0.w, a1.x, a1.y, a1.z, a1.w};
#pragma unroll
            for (int j = 0; j < 4; j++) {
                float x0 = av[2 * j], x1 = av[2 * j + 1];
                __nv_bfloat16 h0 = __float2bfloat16(x0), h1 = __float2bfloat16(x1);
                float r0 = x0 - __bfloat162float(h0), r1 = x1 - __bfloat162float(h1);
                __nv_bfloat16 m0 = __float2bfloat16(r0), m1 = __float2bfloat16(r1);
                float s0 = r0 - __bfloat162float(m0), s1 = r1 - __bfloat162float(m1);
                __nv_bfloat16 l0 = __float2bfloat16(s0), l1 = __float2bfloat16(s1);
                *(__nv_bfloat162*)(A0r + 2 * j) = __nv_bfloat162(h0, h1);
                *(__nv_bfloat162*)(A1r + 2 * j) = __nv_bfloat162(m0, m1);
                *(__nv_bfloat162*)(A2r + 2 * j) = __nv_bfloat162(l0, l1);
            }
            __nv_bfloat16* B0r = SBUF(3, cur) + srow * ASTR + scol;
            __nv_bfloat16* B1r = SBUF(4, cur) + srow * ASTR + scol;
            __nv_bfloat16* B2r = SBUF(5, cur) + srow * ASTR + scol;
            *(uint2*)B0r = make_uint2(w0s.x, w0s.y);
            *(uint2*)(B0r + 4) = make_uint2(w0s.z, w0s.w);
            *(uint2*)B1r = make_uint2(w1s.x, w1s.y);
            *(uint2*)(B1r + 4) = make_uint2(w1s.z, w1s.w);
            *(uint2*)B2r = make_uint2(w2s.x, w2s.y);
            *(uint2*)(B2r + 4) = make_uint2(w2s.z, w2s.w);
        }
        __syncthreads();

        // ---- prefetch next k-step ----
        if (ks + 1 < nk) {
            const int k0 = (ks + 1) << 4;
            a0 = make_float4(0.f, 0.f, 0.f, 0.f); a1 = a0;
            if (arowv) { a0 = *(const float4*)(Agp + k0); a1 = *(const float4*)(Agp + k0 + 4); }
            w0s = *(const uint4*)(Wp0 + k0);
            w1s = *(const uint4*)(Wp0 + lvl + k0);
            w2s = *(const uint4*)(Wp0 + 2 * lvl + k0);
        }

        // ---- compute: 6 passes ----
        uint32_t bfr[3][4][2];
#pragma unroll
        for (int lv = 0; lv < 3; lv++) {
            const __nv_bfloat16* Bb = SBUF(3 + lv, cur);
#pragma unroll
            for (int nt = 0; nt < 4; nt++) {
                const int r = wn + nt * 8 + gr;
                bfr[lv][nt][0] = lds32(Bb + r * ASTR + gc);
                bfr[lv][nt][1] = lds32(Bb + r * ASTR + gc + 8);
            }
        }
        uint32_t af[4][4];
        {   // A level 0 x B levels 0,1,2
            const __nv_bfloat16* Ab = SBUF(0, cur);
#pragma unroll
            for (int mt = 0; mt < 4; mt++) {
                const int r = wm + mt * 16 + gr;
                af[mt][0] = lds32(Ab + r * ASTR + gc);
                af[mt][1] = lds32(Ab + (r + 8) * ASTR + gc);
                af[mt][2] = lds32(Ab + r * ASTR + gc + 8);
                af[mt][3] = lds32(Ab + (r + 8) * ASTR + gc + 8);
            }
#pragma unroll
            for (int mt = 0; mt < 4; mt++)
#pragma unroll
                for (int nt = 0; nt < 4; nt++) {
                    mma16816(acc[mt][nt], af[mt], bfr[0][nt]);
                    mma16816(acc[mt][nt], af[mt], bfr[1][nt]);
                    mma16816(acc[mt][nt], af[mt], bfr[2][nt]);
                }
        }
        {   // A level 1 x B levels 0,1
            const __nv_bfloat16* Ab = SBUF(1, cur);
#pragma unroll
            for (int mt = 0; mt < 4; mt++) {
                const int r = wm + mt * 16 + gr;
                af[mt][0] = lds32(Ab + r * ASTR + gc);
                af[mt][1] = lds32(Ab + (r + 8) * ASTR + gc);
                af[mt][2] = lds32(Ab + r * ASTR + gc + 8);
                af[mt][3] = lds32(Ab + (r + 8) * ASTR + gc + 8);
            }
#pragma unroll
            for (int mt = 0; mt < 4; mt++)
#pragma unroll
                for (int nt = 0; nt < 4; nt++) {
                    mma16816(acc[mt][nt], af[mt], bfr[0][nt]);
                    mma16816(acc[mt][nt], af[mt], bfr[1][nt]);
                }
        }
        {   // A level 2 x B level 0
            const __nv_bfloat16* Ab = SBUF(2, cur);
#pragma unroll
            for (int mt = 0; mt < 4; mt++) {
                const int r = wm + mt * 16 + gr;
                af[mt][0] = lds32(Ab + r * ASTR + gc);
                af[mt][1] = lds32(Ab + (r + 8) * ASTR + gc);
                af[mt][2] = lds32(Ab + r * ASTR + gc + 8);
                af[mt][3] = lds32(Ab + (r + 8) * ASTR + gc + 8);
            }
#pragma unroll
            for (int mt = 0; mt < 4; mt++)
#pragma unroll
                for (int nt = 0; nt < 4; nt++)
                    mma16816(acc[mt][nt], af[mt], bfr[0][nt]);
        }
        __syncthreads();
    }

    // ---- epilogue ----
    float* Co = pa.out[p];
    const float* bs = pa.bias[p];
    const int ld = pa.ldc[p], cb = pa.col[p];
#pragma unroll
    for (int nt = 0; nt < 4; nt++) {
        const int cloc = wn + nt * 8 + (lane & 3) * 2;
        const float b0 = bs[cloc], b1 = bs[cloc + 1];
#pragma unroll
        for (int mt = 0; mt < 4; mt++) {
            const int r0 = brow + wm + mt * 16 + (lane >> 2);
            if (r0 < nrows) {
                float2 o = make_float2(acc[mt][nt][0] + b0, acc[mt][nt][1] + b1);
                *(float2*)(Co + (size_t)r0 * ld + cb + cloc) = o;
            }
            const int r1 = r0 + 8;
            if (r1 < nrows) {
                float2 o = make_float2(acc[mt][nt][2] + b0, acc[mt][nt][3] + b1);
                *(float2*)(Co + (size_t)r1 * ld + cb + cloc) = o;
            }
        }
    }
}

// ---------------------- weight split prep (fp32 -> 3x bf16) ------------------
__global__ void wprep3(const float* __restrict__ src, __nv_bfloat16* __restrict__ w0,
                       __nv_bfloat16* __restrict__ w1, __nv_bfloat16* __restrict__ w2, int n)
{
    int i = blockIdx.x * blockDim.x + threadIdx.x;
    if (i >= n) return;
    float x = src[i];
    __nv_bfloat16 h = __float2bfloat16(x);
    float r = x - __bfloat162float(h);
    __nv_bfloat16 m = __float2bfloat16(r);
    float s = r - __bfloat162float(m);
    w0[i] = h; w1[i] = m; w2[i] = __float2bfloat16(s);
}

// ------------------------------- GRU gates ----------------------------------
__global__ void gru_gate(const float* __restrict__ gi, const float* __restrict__ gh,
                         float* __restrict__ hprev, float* __restrict__ hout)
{
    int idx = blockIdx.x * blockDim.x + threadIdx.x;
    if (idx >= NN * HID) return;
    int n = idx / HID, c = idx % HID;
    const float* gin = gi + (size_t)n * G3;
    const float* ghn = gh + (size_t)n * G3;
    float r = sigf(gin[c] + ghn[c]);
    float z = sigf(gin[HID + c] + ghn[HID + c]);
    float nn = tanhf(gin[2 * HID + c] + r * ghn[2 * HID + c]);
    float hp = hprev[idx];
    float hn = (1.0f - z) * nn + z * hp;
    hprev[idx] = hn;
    hout[idx] = hn;
}

// ------------------------- conv edge phase (batched over T) ------------------
__global__ void __launch_bounds__(256) prep_seg(
    const float* __restrict__ q, const float* __restrict__ We,
    float* __restrict__ qwe, int* __restrict__ amax,
    float* __restrict__ denom, float* __restrict__ coef)
{
    int n = (blockIdx.x * blockDim.x + threadIdx.x) >> 5;
    int lane = threadIdx.x & 31;
    if (n >= TN) return;
    float4 qq = *(const float4*)(q + (size_t)n * HID + lane * 4);
    float4 ww = *(const float4*)(We + lane * 4);
    float p = qq.x * ww.x + qq.y * ww.y + qq.z * ww.z + qq.w * ww.w;
    p = warp_sum(p);
    if (lane == 0) {
        qwe[n] = p * 0.08838834764831845f;
        amax[n] = f2ord(-INFINITY);
        denom[n] = 0.0f;
        coef[n] = 0.0f;
    }
}

__global__ void __launch_bounds__(256) edge_alpha_b(
    const float* __restrict__ q, const float* __restrict__ k,
    const int* __restrict__ ei, const float* __restrict__ ea,
    const float* __restrict__ qwe,
    float* __restrict__ alpha, int* __restrict__ amax)
{
    int w = (blockIdx.x * blockDim.x + threadIdx.x) >> 5;
    int lane = threadIdx.x & 31;
    if (w >= TE) return;
    int t = w / EE, e = w - t * EE;
    const int* eib = ei + (size_t)t * 2 * EE;
    int s = eib[e] + t * NN;
    int d = eib[EE + e] + t * NN;
    float4 qd = *(const float4*)(q + (size_t)d * HID + lane * 4);
    float4 ks = *(const float4*)(k + (size_t)s * HID + lane * 4);
    float p = qd.x * ks.x + qd.y * ks.y + qd.z * ks.z + qd.w * ks.w;
    p = warp_sum(p);
    if (lane == 0) {
        float al = p * 0.08838834764831845f + ea[w] * qwe[d];
        alpha[w] = al;
        atomicMax(&amax[d], f2ord(al));
    }
}

__global__ void __launch_bounds__(256) edge_msg_b(
    const float* __restrict__ v,
    const int* __restrict__ ei, const float* __restrict__ ea,
    const float* __restrict__ alpha, const int* __restrict__ amax,
    float* __restrict__ denom, float* __restrict__ coef,
    float* __restrict__ macc)
{
    int w = (blockIdx.x * blockDim.x + threadIdx.x) >> 5;
    int lane = threadIdx.x & 31;
    if (w >= TE) return;
    int t = w / EE, e = w - t * EE;
    const int* eib = ei + (size_t)t * 2 * EE;
    int s = eib[e] + t * NN;
    int d = eib[EE + e] + t * NN;
    float a = expf(alpha[w] - ord2f(amax[d]));
    if (lane == 0) {
        atomicAdd(&denom[d], a);
        atomicAdd(&coef[d], a * ea[w]);
    }
    int i = lane << 2;
    float4 vv = *(const float4*)(v + (size_t)s * HID + i);
    float m0 = a * vv.x, m1 = a * vv.y, m2 = a * vv.z, m3 = a * vv.w;
    float* p = macc + (size_t)d * HID + i;
    asm volatile("red.global.add.v4.f32 [%0], {%1,%2,%3,%4};"
                 :: "l"(p), "f"(m0), "f"(m1), "f"(m2), "f"(m3) : "memory");
}

__global__ void finish_conv(
    float* __restrict__ out, const float* __restrict__ macc,
    const float* __restrict__ coef, const float* __restrict__ We,
    const float* __restrict__ denom)
{
    int idx = blockIdx.x * blockDim.x + threadIdx.x;
    if (idx >= TN * 32) return;
    int n = idx >> 5;
    int c4 = (idx & 31) << 2;
    float4 sk = *(const float4*)(out + ((size_t)n * HID + c4));
    float4 mc = *(const float4*)(macc + ((size_t)n * HID + c4));
    float4 we = *(const float4*)(We + c4);
    float cf = coef[n];
    float inv = 1.0f / (denom[n] + 1e-16f);
    float4 o;
    o.x = sk.x + (mc.x + cf * we.x) * inv;
    o.y = sk.y + (mc.y + cf * we.y) * inv;
    o.z = sk.z + (mc.z + cf * we.z) * inv;
    o.w = sk.w + (mc.w + cf * we.w) * inv;
    o.x = o.x > 0.f ? o.x : 0.01f * o.x;
    o.y = o.y > 0.f ? o.y : 0.01f * o.y;
    o.z = o.z > 0.f ? o.z : 0.01f * o.z;
    o.w = o.w > 0.f ? o.w : 0.01f * o.w;
    *(float4*)(out + ((size_t)n * HID + c4)) = o;
}

// --------------------- temporal attention + top-k (warp/node) ----------------
__global__ void __launch_bounds__(256) attn_topk(
    const float* __restrict__ h, const float* __restrict__ W,
    const float* __restrict__ b, float* __restrict__ hattn)
{
    int n = (blockIdx.x * blockDim.x + threadIdx.x) >> 5;
    int lane = threadIdx.x & 31;
    if (n >= NN) return;
    float s[T_STEPS];
#pragma unroll
    for (int t = 0; t < T_STEPS; t++) {
        const float* row = h + ((size_t)t * NN + n) * HID;
        float p = 0.0f;
#pragma unroll
        for (int i = lane; i < HID; i += 32) p = fmaf(row[i], W[i], p);
        s[t] = warp_sum(p) + b[0];
    }
    float mx = s[0];
#pragma unroll
    for (int t = 1; t < T_STEPS; t++) mx = fmaxf(mx, s[t]);
    float aw[T_STEPS]; float tot = 0.0f;
#pragma unroll
    for (int t = 0; t < T_STEPS; t++) { aw[t] = expf(s[t] - mx); tot += aw[t]; }
    float inv = 1.0f / tot;
#pragma unroll
    for (int t = 0; t < T_STEPS; t++) aw[t] *= inv;
    bool sel[T_STEPS];
#pragma unroll
    for (int t = 0; t < T_STEPS; t++) sel[t] = false;
    float sum3 = 0.0f;
#pragma unroll
    for (int r = 0; r < 3; r++) {
        float best = -1.0f; int bi = 0;
#pragma unroll
        for (int t = 0; t < T_STEPS; t++)
            if (!sel[t] && aw[t] > best) { best = aw[t]; bi = t; }
        sel[bi] = true; sum3 += best;
    }
    float winv = 1.0f / (sum3 + 1e-8f);
    float w[T_STEPS];
#pragma unroll
    for (int t = 0; t < T_STEPS; t++) w[t] = sel[t] ? aw[t] * winv : 0.0f;
#pragma unroll
    for (int i = lane; i < HID; i += 32) {
        float acc = 0.0f;
#pragma unroll
        for (int t = 0; t < T_STEPS; t++)
            acc = fmaf(w[t], h[((size_t)t * NN + n) * HID + i], acc);
        hattn[(size_t)n * HID + i] = acc;
    }
}

// ------------------------- output conv (C_out = 1) ---------------------------
__global__ void init_seg(int* __restrict__ amax, float* __restrict__ denom)
{
    int i = blockIdx.x * blockDim.x + threadIdx.x;
    if (i < NN) { amax[i] = f2ord(-INFINITY); denom[i] = 0.0f; }
}

__global__ void __launch_bounds__(256) outconv_node(
    const float* __restrict__ x,
    const float* __restrict__ Wq, const float* __restrict__ bq,
    const float* __restrict__ Wk, const float* __restrict__ bk,
    const float* __restrict__ Wv, const float* __restrict__ bv,
    const float* __restrict__ Ws, const float* __restrict__ bs,
    float* __restrict__ qs, float* __restrict__ ks,
    float* __restrict__ vs, float* __restrict__ outp)
{
    int n = (blockIdx.x * blockDim.x + threadIdx.x) >> 5;
    int lane = threadIdx.x & 31;
    if (n >= NN) return;
    const float* xr = x + (size_t)n * HID;
    float pq = 0.f, pk = 0.f, pv = 0.f, ps = 0.f;
#pragma unroll
    for (int i = lane; i < HID; i += 32) {
        float xv = xr[i];
        pq = fmaf(xv, Wq[i], pq);
        pk = fmaf(xv, Wk[i], pk);
        pv = fmaf(xv, Wv[i], pv);
        ps = fmaf(xv, Ws[i], ps);
    }
    pq = warp_sum(pq); pk = warp_sum(pk); pv = warp_sum(pv); ps = warp_sum(ps);
    if (lane == 0) {
        qs[n] = pq + bq[0];
        ks[n] = pk + bk[0];
        vs[n] = pv + bv[0];
        outp[n] = ps + bs[0];
    }
}

__global__ void oc_alpha(const float* __restrict__ qs, const float* __restrict__ ks,
                         const int* __restrict__ src, const int* __restrict__ dst,
                         const float* __restrict__ ea, const float* __restrict__ We,
                         float* __restrict__ alpha, int* __restrict__ amax)
{
    int e = blockIdx.x * blockDim.x + threadIdx.x;
    if (e >= EE) return;
    int s = src[e], d = dst[e];
    float a = qs[d] * (ks[s] + ea[e] * We[0]);
    alpha[e] = a;
    atomicMax(&amax[d], f2ord(a));
}

__global__ void edge_ex(const int* __restrict__ dst, float* __restrict__ alpha,
                        const int* __restrict__ amax, float* __restrict__ denom)
{
    int e = blockIdx.x * blockDim.x + threadIdx.x;
    if (e >= EE) return;
    int d = dst[e];
    float ex = expf(alpha[e] - ord2f(amax[d]));
    alpha[e] = ex;
    atomicAdd(&denom[d], ex);
}

__global__ void oc_msg(const float* __restrict__ vs,
                       const int* __restrict__ src, const int* __restrict__ dst,
                       const float* __restrict__ ea, const float* __restrict__ We,
                       const float* __restrict__ ex, const float* __restrict__ denom,
                       float* __restrict__ outp)
{
    int e = blockIdx.x * blockDim.x + threadIdx.x;
    if (e >= EE) return;
    int s = src[e], d = dst[e];
    float a = ex[e] / (denom[d] + 1e-16f);
    atomicAdd(&outp[d], a * (vs[s] + ea[e] * We[0]));
}

// --------------------------------- host --------------------------------------
static float* symf(const void* sym) { void* p = nullptr; cudaGetSymbolAddress(&p, sym); return (float*)p; }

extern "C" void kernel_launch(void* const* d_in, const int* in_sizes, int n_in,
                              void* d_out, int out_size)
{
    const float* x_seq = (const float*)d_in[0];
    const int*   ei    = (const int*)d_in[1];
    const float* ea    = (const float*)d_in[2];
    const float* W_ih  = (const float*)d_in[3];
    const float* W_hh  = (const float*)d_in[4];
    const float* b_ih  = (const float*)d_in[5];
    const float* b_hh  = (const float*)d_in[6];
    const float* cWq = (const float*)d_in[7];  const float* cbq = (const float*)d_in[8];
    const float* cWk = (const float*)d_in[9];  const float* cbk = (const float*)d_in[10];
    const float* cWv = (const float*)d_in[11]; const float* cbv = (const float*)d_in[12];
    const float* cWe = (const float*)d_in[13];
    const float* cWs = (const float*)d_in[14]; const float* cbs = (const float*)d_in[15];
    const float* oWq = (const float*)d_in[16]; const float* obq = (const float*)d_in[17];
    const float* oWk = (const float*)d_in[18]; const float* obk = (const float*)d_in[19];
    const float* oWv = (const float*)d_in[20]; const float* obv = (const float*)d_in[21];
    const float* oWe = (const float*)d_in[22];
    const float* oWs = (const float*)d_in[23]; const float* obs = (const float*)d_in[24];
    const float* aW  = (const float*)d_in[25]; const float* ab  = (const float*)d_in[26];
    float* outp = (float*)d_out;

    float* ph     = symf(g_h);
    float* ptmp   = symf(g_tmp);
    float* pq     = symf(g_q);
    float* pk     = symf(g_k);
    float* pv     = symf(g_v);
    float* pmacc  = symf(g_macc);
    float* pgi    = symf(g_gi);
    float* pgh    = symf(g_gh);
    float* phprev = symf(g_hprev);
    float* palpha = symf(g_alpha);
    int*   pamax  = (int*)symf(g_amax);
    float* pdenom = symf(g_denom);
    float* pcoef  = symf(g_coef);
    float* pqwe   = symf(g_qwe);
    float* phattn = symf(g_hattn);
    __nv_bfloat16* wp = (__nv_bfloat16*)symf(g_wprep);

    cudaFuncSetAttribute(mma_gemm, cudaFuncAttributeMaxDynamicSharedMemorySize, SM_BYTES);

    const int nwblk  = (NN + 7) / 8;
    const int tnwblk = (TN + 7) / 8;
    const int tewblk = (TE + 7) / 8;
    const int esblk  = (EE + 255) / 256;
    const int nsblk  = (NN + 255) / 256;
    const int nhblk  = (NN * HID + 255) / 256;
    const int fnblk  = (TN * 32 + 255) / 256;

    // ---------------- weight prep (3-level bf16 split) ----------------
    wprep3<<<(12288 + 255) / 256, 256>>>(W_ih, wp + WIH, wp + WIH + 12288, wp + WIH + 24576, 12288);
    wprep3<<<(49152 + 255) / 256, 256>>>(W_hh, wp + WHH, wp + WHH + 49152, wp + WHH + 98304, 49152);
    wprep3<<<(32768 + 255) / 256, 256>>>(cWq, wp + WQ, wp + WQ + 32768, wp + WQ + 65536, 32768);
    wprep3<<<(32768 + 255) / 256, 256>>>(cWk, wp + WK, wp + WK + 32768, wp + WK + 65536, 32768);
    wprep3<<<(32768 + 255) / 256, 256>>>(cWv, wp + WV, wp + WV + 32768, wp + WV + 65536, 32768);
    wprep3<<<(32768 + 255) / 256, 256>>>(cWs, wp + WS, wp + WS + 32768, wp + WS + 65536, 32768);

    // ---------------- GRU ----------------
    cudaMemsetAsync(phprev, 0, (size_t)NN * HID * sizeof(float));
    {
        PArgs pa;
        for (int p = 0; p < 3; p++) {
            pa.w[p] = wp + WIH + (size_t)p * 128 * 32;
            pa.lvl[p] = 12288;
            pa.bias[p] = b_ih + p * 128;
            pa.out[p] = pgi; pa.col[p] = p * 128; pa.ldc[p] = G3;
        }
        pa.w[3] = pa.w[2]; pa.lvl[3] = 12288; pa.bias[3] = pa.bias[2];
        pa.out[3] = pgi; pa.col[3] = 256; pa.ldc[3] = G3;
        mma_gemm<<<dim3(3, (TN + 127) / 128), 256, SM_BYTES>>>(pa, x_seq, TN, 32);
    }
    {
        PArgs pa;
        for (int p = 0; p < 3; p++) {
            pa.w[p] = wp + WHH + (size_t)p * 128 * 128;
            pa.lvl[p] = 49152;
            pa.bias[p] = b_hh + p * 128;
            pa.out[p] = pgh; pa.col[p] = p * 128; pa.ldc[p] = G3;
        }
        pa.w[3] = pa.w[2]; pa.lvl[3] = 49152; pa.bias[3] = pa.bias[2];
        pa.out[3] = pgh; pa.col[3] = 256; pa.ldc[3] = G3;
        for (int t = 0; t < T_STEPS; t++) {
            mma_gemm<<<dim3(3, (NN + 127) / 128), 256, SM_BYTES>>>(pa, phprev, NN, 128);
            gru_gate<<<nhblk, 256>>>(pgi + (size_t)t * NN * G3, pgh, phprev,
                                     ph + (size_t)t * NN * HID);
        }
    }

    // ---------------- GNN: 2 layers, batched over all T ----------------
    for (int l = 0; l < 2; l++) {
        const float* in  = (l == 0) ? ph : ptmp;
        float*       out = (l == 0) ? ptmp : ph;
        const float* We = cWe + (size_t)l * HID;
        size_t lo = (size_t)l * 16384;

        cudaMemsetAsync(pmacc, 0, (size_t)TN * HID * sizeof(float));
        PArgs pa;
        pa.w[0] = wp + WQ + lo; pa.lvl[0] = 32768; pa.bias[0] = cbq + l * 128;
        pa.out[0] = pq;  pa.col[0] = 0; pa.ldc[0] = 128;
        pa.w[1] = wp + WK + lo; pa.lvl[1] = 32768; pa.bias[1] = cbk + l * 128;
        pa.out[1] = pk;  pa.col[1] = 0; pa.ldc[1] = 128;
        pa.w[2] = wp + WV + lo; pa.lvl[2] = 32768; pa.bias[2] = cbv + l * 128;
        pa.out[2] = pv;  pa.col[2] = 0; pa.ldc[2] = 128;
        pa.w[3] = wp + WS + lo; pa.lvl[3] = 32768; pa.bias[3] = cbs + l * 128;
        pa.out[3] = out; pa.col[3] = 0; pa.ldc[3] = 128;
        mma_gemm<<<dim3(4, (TN + 127) / 128), 256, SM_BYTES>>>(pa, in, TN, 128);

        prep_seg<<<tnwblk, 256>>>(pq, We, pqwe, pamax, pdenom, pcoef);
        edge_alpha_b<<<tewblk, 256>>>(pq, pk, ei, ea, pqwe, palpha, pamax);
        edge_msg_b<<<tewblk, 256>>>(pv, ei, ea, palpha, pamax, pdenom, pcoef, pmacc);
        finish_conv<<<fnblk, 256>>>(out, pmacc, pcoef, We, pdenom);
    }

    // ---------------- temporal attention + top-3 ----------------
    attn_topk<<<nwblk, 256>>>(ph, aW, ab, phattn);

    // ---------------- output TransformerConv (128 -> 1) ----------------
    {
        const int* src = ei + (size_t)(T_STEPS - 1) * 2 * EE;
        const int* dst = src + EE;
        const float* eat = ea + (size_t)(T_STEPS - 1) * EE;
        outconv_node<<<nwblk, 256>>>(phattn, oWq, obq, oWk, obk, oWv, obv, oWs, obs,
                                     pq, pk, pv, outp);
        init_seg<<<nsblk, 256>>>(pamax, pdenom);
        oc_alpha<<<esblk, 256>>>(pq, pk, src, dst, eat, oWe, palpha, pamax);
        edge_ex<<<esblk, 256>>>(dst, palpha, pamax, pdenom);
        oc_msg<<<esblk, 256>>>(pv, src, dst, eat, oWe, palpha, pdenom, outp);
    }
}

// round 7
// speedup vs baseline: 1.3940x; 1.0548x over previous
#include <cuda_runtime.h>
#include <cuda_bf16.h>
#include <math.h>
#include <stdint.h>

#define T_STEPS 8
#define NN      20000
#define FIN_DIM 32
#define EE      160000
#define HID     128
#define G3      384
#define TN      (T_STEPS * NN)
#define TE      (T_STEPS * EE)

typedef unsigned long long u64;

// ------------------------- scratch (device globals) -------------------------
__device__ float g_h[(size_t)TN * HID];
__device__ float g_tmp[(size_t)TN * HID];
__device__ float g_q[(size_t)TN * HID];
__device__ float g_k[(size_t)TN * HID];
__device__ float g_v[(size_t)TN * HID];
__device__ float g_macc[(size_t)TN * HID];
__device__ float g_gi[(size_t)TN * G3];
__device__ float g_gh[(size_t)NN * G3];
__device__ float g_hprev[(size_t)NN * HID];
__device__ float g_alpha[TE];
__device__ int   g_amax[TN];
__device__ float g_denom[TN];
__device__ float g_coef[TN];
__device__ float g_qwe[TN];
__device__ float g_hattn[(size_t)NN * HID];
__device__ __align__(16) __nv_bfloat16 g_wprep[577536];  // 3-level split weights

#define WIH 0        // level stride 12288
#define WHH 36864    // level stride 49152
#define WQ  184320   // level stride 32768
#define WK  282624
#define WV  380928
#define WS  479232

// ------------------------------- helpers ------------------------------------
__device__ __forceinline__ float warp_sum(float v) {
#pragma unroll
    for (int o = 16; o; o >>= 1) v += __shfl_xor_sync(0xffffffffu, v, o);
    return v;
}
__device__ __forceinline__ int f2ord(float f) { int i = __float_as_int(f); return i >= 0 ? i : i ^ 0x7fffffff; }
__device__ __forceinline__ float ord2f(int i) { return __int_as_float(i >= 0 ? i : i ^ 0x7fffffff); }
__device__ __forceinline__ float sigf(float x) { return 1.0f / (1.0f + expf(-x)); }

// --------------------------- mma.sync GEMM v2 --------------------------------
// A resident in smem (3 levels, full K); loop projections inside the CTA.
// Block 256 thr, tile 128 rows x 128 cols per proj; warp tile 64x32.

#define ROWB 272                    // bytes per smem row (136 bf16)
#define LVLB (128 * ROWB)           // 34816 bytes per level buffer
#define SB_OFF (3 * LVLB)           // B starts after 3 A levels
#define SM_BYTES (6 * LVLB)         // 208896

struct PArgs {
    const __nv_bfloat16* w[4];   // level-0 base; levels at +lvl, +2*lvl
    int lvl[4];
    const float* bias[4];
    float* out[4];
    int col[4];
    int ldc[4];
};

__device__ __forceinline__ void mma16816(float* c, const uint32_t* a, const uint32_t* b) {
    asm volatile(
        "mma.sync.aligned.m16n8k16.row.col.f32.bf16.bf16.f32 "
        "{%0,%1,%2,%3},{%4,%5,%6,%7},{%8,%9},{%0,%1,%2,%3};"
        : "+f"(c[0]), "+f"(c[1]), "+f"(c[2]), "+f"(c[3])
        : "r"(a[0]), "r"(a[1]), "r"(a[2]), "r"(a[3]), "r"(b[0]), "r"(b[1]));
}
__device__ __forceinline__ void ldsm_x4(uint32_t& r0, uint32_t& r1, uint32_t& r2, uint32_t& r3,
                                        uint32_t addr) {
    asm volatile("ldmatrix.sync.aligned.m8n8.x4.shared.b16 {%0,%1,%2,%3},[%4];"
                 : "=r"(r0), "=r"(r1), "=r"(r2), "=r"(r3) : "r"(addr));
}
__device__ __forceinline__ void ldsm_x2(uint32_t& r0, uint32_t& r1, uint32_t addr) {
    asm volatile("ldmatrix.sync.aligned.m8n8.x2.shared.b16 {%0,%1},[%2];"
                 : "=r"(r0), "=r"(r1) : "r"(addr));
}
__device__ __forceinline__ uint32_t smem_addr32(const void* p) {
    return (uint32_t)__cvta_generic_to_shared(p);
}

__global__ void __launch_bounds__(256) mma_gemm(
    PArgs pa, const float* __restrict__ A, int nrows, int K, int np)
{
    extern __shared__ char sm[];
    const uint32_t smu = smem_addr32(sm);
    const int tid = threadIdx.x, wid = tid >> 5, lane = tid & 31;
    const int brow = blockIdx.x << 7;
    const int kshift = (K == 32) ? 5 : 7;

    const int wm = (wid & 1) * 64;
    const int wn = (wid >> 1) * 32;

    // ldmatrix per-lane address offsets (derived to match R6 fragment layout)
    const uint32_t aoff = (uint32_t)((lane & 15) * ROWB + ((lane >> 4) & 1) * 16);
    const uint32_t boff = (uint32_t)((lane & 7) * ROWB + ((lane >> 3) & 1) * 16);

    // ---- stage A once: fp32 -> 3 bf16 levels ----
    for (int base = tid * 8; base < (128 << kshift); base += 2048) {
        const int row = base >> kshift;
        const int col = base & (K - 1);
        const int gr = brow + row;
        float4 x0 = make_float4(0.f, 0.f, 0.f, 0.f), x1 = x0;
        if (gr < nrows) {
            const float* src = A + (size_t)gr * K + col;
            x0 = *(const float4*)src;
            x1 = *(const float4*)(src + 4);
        }
        const float av[8] = {x0.x, x0.y, x0.z, x0.w, x1.x, x1.y, x1.z, x1.w};
        uint32_t p0[4], p1[4], p2[4];
#pragma unroll
        for (int j = 0; j < 4; j++) {
            float a0 = av[2 * j], a1 = av[2 * j + 1];
            __nv_bfloat16 h0 = __float2bfloat16(a0), h1 = __float2bfloat16(a1);
            float r0 = a0 - __bfloat162float(h0), r1 = a1 - __bfloat162float(h1);
            __nv_bfloat16 m0 = __float2bfloat16(r0), m1 = __float2bfloat16(r1);
            float s0 = r0 - __bfloat162float(m0), s1 = r1 - __bfloat162float(m1);
            union { __nv_bfloat162 b; uint32_t u; } uh, um, ul;
            uh.b = __nv_bfloat162(h0, h1);
            um.b = __nv_bfloat162(m0, m1);
            ul.b = __nv_bfloat162(__float2bfloat16(s0), __float2bfloat16(s1));
            p0[j] = uh.u; p1[j] = um.u; p2[j] = ul.u;
        }
        char* dst = sm + row * ROWB + col * 2;
        *(uint4*)(dst) = make_uint4(p0[0], p0[1], p0[2], p0[3]);
        *(uint4*)(dst + LVLB) = make_uint4(p1[0], p1[1], p1[2], p1[3]);
        *(uint4*)(dst + 2 * LVLB) = make_uint4(p2[0], p2[1], p2[2], p2[3]);
    }

    const int nb = (128 << kshift) >> 3;   // uint4 per level for B

    for (int p = 0; p < np; p++) {
        __syncthreads();   // A staged (p=0) / previous proj done reading B
        // ---- stage B for this projection (pre-split levels) ----
        const __nv_bfloat16* W0 = pa.w[p];
        const int lvl = pa.lvl[p];
#pragma unroll
        for (int lv = 0; lv < 3; lv++) {
            const __nv_bfloat16* Wl = W0 + (size_t)lv * lvl;
            char* dstb = sm + SB_OFF + lv * LVLB;
            for (int i = tid; i < nb; i += 256) {
                const int e = i * 8;
                const int row = e >> kshift;
                const int col = e & (K - 1);
                *(uint4*)(dstb + row * ROWB + col * 2) =
                    *(const uint4*)(Wl + (size_t)row * K + col);
            }
        }
        __syncthreads();

        float acc[4][4][4];
#pragma unroll
        for (int i = 0; i < 4; i++)
#pragma unroll
            for (int j = 0; j < 4; j++)
#pragma unroll
                for (int r = 0; r < 4; r++) acc[i][j][r] = 0.0f;

        const int nk = K >> 4;
        for (int ks = 0; ks < nk; ks++) {
            const uint32_t k2 = (uint32_t)(ks << 5);   // k0*2 bytes
            uint32_t bfr[3][4][2];
#pragma unroll
            for (int lv = 0; lv < 3; lv++) {
                const uint32_t bb = smu + SB_OFF + lv * LVLB + k2 + boff;
#pragma unroll
                for (int nt = 0; nt < 4; nt++)
                    ldsm_x2(bfr[lv][nt][0], bfr[lv][nt][1],
                            bb + (uint32_t)((wn + nt * 8) * ROWB));
            }
            uint32_t af[4][4];
            {   // A level 0 x B levels 0,1,2
                const uint32_t ab = smu + k2 + aoff;
#pragma unroll
                for (int mt = 0; mt < 4; mt++)
                    ldsm_x4(af[mt][0], af[mt][1], af[mt][2], af[mt][3],
                            ab + (uint32_t)((wm + mt * 16) * ROWB));
#pragma unroll
                for (int mt = 0; mt < 4; mt++)
#pragma unroll
                    for (int nt = 0; nt < 4; nt++) {
                        mma16816(acc[mt][nt], af[mt], bfr[0][nt]);
                        mma16816(acc[mt][nt], af[mt], bfr[1][nt]);
                        mma16816(acc[mt][nt], af[mt], bfr[2][nt]);
                    }
            }
            {   // A level 1 x B levels 0,1
                const uint32_t ab = smu + LVLB + k2 + aoff;
#pragma unroll
                for (int mt = 0; mt < 4; mt++)
                    ldsm_x4(af[mt][0], af[mt][1], af[mt][2], af[mt][3],
                            ab + (uint32_t)((wm + mt * 16) * ROWB));
#pragma unroll
                for (int mt = 0; mt < 4; mt++)
#pragma unroll
                    for (int nt = 0; nt < 4; nt++) {
                        mma16816(acc[mt][nt], af[mt], bfr[0][nt]);
                        mma16816(acc[mt][nt], af[mt], bfr[1][nt]);
                    }
            }
            {   // A level 2 x B level 0
                const uint32_t ab = smu + 2 * LVLB + k2 + aoff;
#pragma unroll
                for (int mt = 0; mt < 4; mt++)
                    ldsm_x4(af[mt][0], af[mt][1], af[mt][2], af[mt][3],
                            ab + (uint32_t)((wm + mt * 16) * ROWB));
#pragma unroll
                for (int mt = 0; mt < 4; mt++)
#pragma unroll
                    for (int nt = 0; nt < 4; nt++)
                        mma16816(acc[mt][nt], af[mt], bfr[0][nt]);
            }
        }

        // ---- epilogue for this projection ----
        float* Co = pa.out[p];
        const float* bs = pa.bias[p];
        const int ld = pa.ldc[p], cb = pa.col[p];
#pragma unroll
        for (int nt = 0; nt < 4; nt++) {
            const int cloc = wn + nt * 8 + (lane & 3) * 2;
            const float b0 = bs[cloc], b1 = bs[cloc + 1];
#pragma unroll
            for (int mt = 0; mt < 4; mt++) {
                const int r0 = brow + wm + mt * 16 + (lane >> 2);
                if (r0 < nrows) {
                    float2 o = make_float2(acc[mt][nt][0] + b0, acc[mt][nt][1] + b1);
                    *(float2*)(Co + (size_t)r0 * ld + cb + cloc) = o;
                }
                const int r1 = r0 + 8;
                if (r1 < nrows) {
                    float2 o = make_float2(acc[mt][nt][2] + b0, acc[mt][nt][3] + b1);
                    *(float2*)(Co + (size_t)r1 * ld + cb + cloc) = o;
                }
            }
        }
    }
}

// ---------------------- weight split prep (fp32 -> 3x bf16) ------------------
__global__ void wprep3(const float* __restrict__ src, __nv_bfloat16* __restrict__ w0,
                       __nv_bfloat16* __restrict__ w1, __nv_bfloat16* __restrict__ w2, int n)
{
    int i = blockIdx.x * blockDim.x + threadIdx.x;
    if (i >= n) return;
    float x = src[i];
    __nv_bfloat16 h = __float2bfloat16(x);
    float r = x - __bfloat162float(h);
    __nv_bfloat16 m = __float2bfloat16(r);
    float s = r - __bfloat162float(m);
    w0[i] = h; w1[i] = m; w2[i] = __float2bfloat16(s);
}

// ------------------------------- GRU gates ----------------------------------
__global__ void gru_gate(const float* __restrict__ gi, const float* __restrict__ gh,
                         float* __restrict__ hprev, float* __restrict__ hout)
{
    int idx = blockIdx.x * blockDim.x + threadIdx.x;
    if (idx >= NN * HID) return;
    int n = idx / HID, c = idx % HID;
    const float* gin = gi + (size_t)n * G3;
    const float* ghn = gh + (size_t)n * G3;
    float r = sigf(gin[c] + ghn[c]);
    float z = sigf(gin[HID + c] + ghn[HID + c]);
    float nn = tanhf(gin[2 * HID + c] + r * ghn[2 * HID + c]);
    float hp = hprev[idx];
    float hn = (1.0f - z) * nn + z * hp;
    hprev[idx] = hn;
    hout[idx] = hn;
}

// ------------------------- conv edge phase (batched over T) ------------------
__global__ void __launch_bounds__(256) prep_seg(
    const float* __restrict__ q, const float* __restrict__ We,
    float* __restrict__ qwe, int* __restrict__ amax,
    float* __restrict__ denom, float* __restrict__ coef)
{
    int n = (blockIdx.x * blockDim.x + threadIdx.x) >> 5;
    int lane = threadIdx.x & 31;
    if (n >= TN) return;
    float4 qq = *(const float4*)(q + (size_t)n * HID + lane * 4);
    float4 ww = *(const float4*)(We + lane * 4);
    float p = qq.x * ww.x + qq.y * ww.y + qq.z * ww.z + qq.w * ww.w;
    p = warp_sum(p);
    if (lane == 0) {
        qwe[n] = p * 0.08838834764831845f;
        amax[n] = f2ord(-INFINITY);
        denom[n] = 0.0f;
        coef[n] = 0.0f;
    }
}

__global__ void __launch_bounds__(256) edge_alpha_b(
    const float* __restrict__ q, const float* __restrict__ k,
    const int* __restrict__ ei, const float* __restrict__ ea,
    const float* __restrict__ qwe,
    float* __restrict__ alpha, int* __restrict__ amax)
{
    int w = (blockIdx.x * blockDim.x + threadIdx.x) >> 5;
    int lane = threadIdx.x & 31;
    if (w >= TE) return;
    int t = w / EE, e = w - t * EE;
    const int* eib = ei + (size_t)t * 2 * EE;
    int s = eib[e] + t * NN;
    int d = eib[EE + e] + t * NN;
    float4 qd = *(const float4*)(q + (size_t)d * HID + lane * 4);
    float4 ks = *(const float4*)(k + (size_t)s * HID + lane * 4);
    float p = qd.x * ks.x + qd.y * ks.y + qd.z * ks.z + qd.w * ks.w;
    p = warp_sum(p);
    if (lane == 0) {
        float al = p * 0.08838834764831845f + ea[w] * qwe[d];
        alpha[w] = al;
        atomicMax(&amax[d], f2ord(al));
    }
}

__global__ void __launch_bounds__(256) edge_msg_b(
    const float* __restrict__ v,
    const int* __restrict__ ei, const float* __restrict__ ea,
    const float* __restrict__ alpha, const int* __restrict__ amax,
    float* __restrict__ denom, float* __restrict__ coef,
    float* __restrict__ macc)
{
    int w = (blockIdx.x * blockDim.x + threadIdx.x) >> 5;
    int lane = threadIdx.x & 31;
    if (w >= TE) return;
    int t = w / EE, e = w - t * EE;
    const int* eib = ei + (size_t)t * 2 * EE;
    int s = eib[e] + t * NN;
    int d = eib[EE + e] + t * NN;
    float a = expf(alpha[w] - ord2f(amax[d]));
    if (lane == 0) {
        atomicAdd(&denom[d], a);
        atomicAdd(&coef[d], a * ea[w]);
    }
    int i = lane << 2;
    float4 vv = *(const float4*)(v + (size_t)s * HID + i);
    float m0 = a * vv.x, m1 = a * vv.y, m2 = a * vv.z, m3 = a * vv.w;
    float* p = macc + (size_t)d * HID + i;
    asm volatile("red.global.add.v4.f32 [%0], {%1,%2,%3,%4};"
                 :: "l"(p), "f"(m0), "f"(m1), "f"(m2), "f"(m3) : "memory");
}

__global__ void finish_conv(
    float* __restrict__ out, const float* __restrict__ macc,
    const float* __restrict__ coef, const float* __restrict__ We,
    const float* __restrict__ denom)
{
    int idx = blockIdx.x * blockDim.x + threadIdx.x;
    if (idx >= TN * 32) return;
    int n = idx >> 5;
    int c4 = (idx & 31) << 2;
    float4 sk = *(const float4*)(out + ((size_t)n * HID + c4));
    float4 mc = *(const float4*)(macc + ((size_t)n * HID + c4));
    float4 we = *(const float4*)(We + c4);
    float cf = coef[n];
    float inv = 1.0f / (denom[n] + 1e-16f);
    float4 o;
    o.x = sk.x + (mc.x + cf * we.x) * inv;
    o.y = sk.y + (mc.y + cf * we.y) * inv;
    o.z = sk.z + (mc.z + cf * we.z) * inv;
    o.w = sk.w + (mc.w + cf * we.w) * inv;
    o.x = o.x > 0.f ? o.x : 0.01f * o.x;
    o.y = o.y > 0.f ? o.y : 0.01f * o.y;
    o.z = o.z > 0.f ? o.z : 0.01f * o.z;
    o.w = o.w > 0.f ? o.w : 0.01f * o.w;
    *(float4*)(out + ((size_t)n * HID + c4)) = o;
}

// --------------------- temporal attention + top-k (warp/node) ----------------
__global__ void __launch_bounds__(256) attn_topk(
    const float* __restrict__ h, const float* __restrict__ W,
    const float* __restrict__ b, float* __restrict__ hattn)
{
    int n = (blockIdx.x * blockDim.x + threadIdx.x) >> 5;
    int lane = threadIdx.x & 31;
    if (n >= NN) return;
    float s[T_STEPS];
#pragma unroll
    for (int t = 0; t < T_STEPS; t++) {
        const float* row = h + ((size_t)t * NN + n) * HID;
        float p = 0.0f;
#pragma unroll
        for (int i = lane; i < HID; i += 32) p = fmaf(row[i], W[i], p);
        s[t] = warp_sum(p) + b[0];
    }
    float mx = s[0];
#pragma unroll
    for (int t = 1; t < T_STEPS; t++) mx = fmaxf(mx, s[t]);
    float aw[T_STEPS]; float tot = 0.0f;
#pragma unroll
    for (int t = 0; t < T_STEPS; t++) { aw[t] = expf(s[t] - mx); tot += aw[t]; }
    float inv = 1.0f / tot;
#pragma unroll
    for (int t = 0; t < T_STEPS; t++) aw[t] *= inv;
    bool sel[T_STEPS];
#pragma unroll
    for (int t = 0; t < T_STEPS; t++) sel[t] = false;
    float sum3 = 0.0f;
#pragma unroll
    for (int r = 0; r < 3; r++) {
        float best = -1.0f; int bi = 0;
#pragma unroll
        for (int t = 0; t < T_STEPS; t++)
            if (!sel[t] && aw[t] > best) { best = aw[t]; bi = t; }
        sel[bi] = true; sum3 += best;
    }
    float winv = 1.0f / (sum3 + 1e-8f);
    float w[T_STEPS];
#pragma unroll
    for (int t = 0; t < T_STEPS; t++) w[t] = sel[t] ? aw[t] * winv : 0.0f;
#pragma unroll
    for (int i = lane; i < HID; i += 32) {
        float acc = 0.0f;
#pragma unroll
        for (int t = 0; t < T_STEPS; t++)
            acc = fmaf(w[t], h[((size_t)t * NN + n) * HID + i], acc);
        hattn[(size_t)n * HID + i] = acc;
    }
}

// ------------------------- output conv (C_out = 1) ---------------------------
__global__ void init_seg(int* __restrict__ amax, float* __restrict__ denom)
{
    int i = blockIdx.x * blockDim.x + threadIdx.x;
    if (i < NN) { amax[i] = f2ord(-INFINITY); denom[i] = 0.0f; }
}

__global__ void __launch_bounds__(256) outconv_node(
    const float* __restrict__ x,
    const float* __restrict__ Wq, const float* __restrict__ bq,
    const float* __restrict__ Wk, const float* __restrict__ bk,
    const float* __restrict__ Wv, const float* __restrict__ bv,
    const float* __restrict__ Ws, const float* __restrict__ bs,
    float* __restrict__ qs, float* __restrict__ ks,
    float* __restrict__ vs, float* __restrict__ outp)
{
    int n = (blockIdx.x * blockDim.x + threadIdx.x) >> 5;
    int lane = threadIdx.x & 31;
    if (n >= NN) return;
    const float* xr = x + (size_t)n * HID;
    float pq = 0.f, pk = 0.f, pv = 0.f, ps = 0.f;
#pragma unroll
    for (int i = lane; i < HID; i += 32) {
        float xv = xr[i];
        pq = fmaf(xv, Wq[i], pq);
        pk = fmaf(xv, Wk[i], pk);
        pv = fmaf(xv, Wv[i], pv);
        ps = fmaf(xv, Ws[i], ps);
    }
    pq = warp_sum(pq); pk = warp_sum(pk); pv = warp_sum(pv); ps = warp_sum(ps);
    if (lane == 0) {
        qs[n] = pq + bq[0];
        ks[n] = pk + bk[0];
        vs[n] = pv + bv[0];
        outp[n] = ps + bs[0];
    }
}

__global__ void oc_alpha(const float* __restrict__ qs, const float* __restrict__ ks,
                         const int* __restrict__ src, const int* __restrict__ dst,
                         const float* __restrict__ ea, const float* __restrict__ We,
                         float* __restrict__ alpha, int* __restrict__ amax)
{
    int e = blockIdx.x * blockDim.x + threadIdx.x;
    if (e >= EE) return;
    int s = src[e], d = dst[e];
    float a = qs[d] * (ks[s] + ea[e] * We[0]);
    alpha[e] = a;
    atomicMax(&amax[d], f2ord(a));
}

__global__ void edge_ex(const int* __restrict__ dst, float* __restrict__ alpha,
                        const int* __restrict__ amax, float* __restrict__ denom)
{
    int e = blockIdx.x * blockDim.x + threadIdx.x;
    if (e >= EE) return;
    int d = dst[e];
    float ex = expf(alpha[e] - ord2f(amax[d]));
    alpha[e] = ex;
    atomicAdd(&denom[d], ex);
}

__global__ void oc_msg(const float* __restrict__ vs,
                       const int* __restrict__ src, const int* __restrict__ dst,
                       const float* __restrict__ ea, const float* __restrict__ We,
                       const float* __restrict__ ex, const float* __restrict__ denom,
                       float* __restrict__ outp)
{
    int e = blockIdx.x * blockDim.x + threadIdx.x;
    if (e >= EE) return;
    int s = src[e], d = dst[e];
    float a = ex[e] / (denom[d] + 1e-16f);
    atomicAdd(&outp[d], a * (vs[s] + ea[e] * We[0]));
}

// --------------------------------- host --------------------------------------
static float* symf(const void* sym) { void* p = nullptr; cudaGetSymbolAddress(&p, sym); return (float*)p; }

extern "C" void kernel_launch(void* const* d_in, const int* in_sizes, int n_in,
                              void* d_out, int out_size)
{
    const float* x_seq = (const float*)d_in[0];
    const int*   ei    = (const int*)d_in[1];
    const float* ea    = (const float*)d_in[2];
    const float* W_ih  = (const float*)d_in[3];
    const float* W_hh  = (const float*)d_in[4];
    const float* b_ih  = (const float*)d_in[5];
    const float* b_hh  = (const float*)d_in[6];
    const float* cWq = (const float*)d_in[7];  const float* cbq = (const float*)d_in[8];
    const float* cWk = (const float*)d_in[9];  const float* cbk = (const float*)d_in[10];
    const float* cWv = (const float*)d_in[11]; const float* cbv = (const float*)d_in[12];
    const float* cWe = (const float*)d_in[13];
    const float* cWs = (const float*)d_in[14]; const float* cbs = (const float*)d_in[15];
    const float* oWq = (const float*)d_in[16]; const float* obq = (const float*)d_in[17];
    const float* oWk = (const float*)d_in[18]; const float* obk = (const float*)d_in[19];
    const float* oWv = (const float*)d_in[20]; const float* obv = (const float*)d_in[21];
    const float* oWe = (const float*)d_in[22];
    const float* oWs = (const float*)d_in[23]; const float* obs = (const float*)d_in[24];
    const float* aW  = (const float*)d_in[25]; const float* ab  = (const float*)d_in[26];
    float* outp = (float*)d_out;

    float* ph     = symf(g_h);
    float* ptmp   = symf(g_tmp);
    float* pq     = symf(g_q);
    float* pk     = symf(g_k);
    float* pv     = symf(g_v);
    float* pmacc  = symf(g_macc);
    float* pgi    = symf(g_gi);
    float* pgh    = symf(g_gh);
    float* phprev = symf(g_hprev);
    float* palpha = symf(g_alpha);
    int*   pamax  = (int*)symf(g_amax);
    float* pdenom = symf(g_denom);
    float* pcoef  = symf(g_coef);
    float* pqwe   = symf(g_qwe);
    float* phattn = symf(g_hattn);
    __nv_bfloat16* wp = (__nv_bfloat16*)symf(g_wprep);

    cudaFuncSetAttribute(mma_gemm, cudaFuncAttributeMaxDynamicSharedMemorySize, SM_BYTES);

    const int nwblk  = (NN + 7) / 8;
    const int tnwblk = (TN + 7) / 8;
    const int tewblk = (TE + 7) / 8;
    const int esblk  = (EE + 255) / 256;
    const int nsblk  = (NN + 255) / 256;
    const int nhblk  = (NN * HID + 255) / 256;
    const int fnblk  = (TN * 32 + 255) / 256;

    // ---------------- weight prep (3-level bf16 split) ----------------
    wprep3<<<(12288 + 255) / 256, 256>>>(W_ih, wp + WIH, wp + WIH + 12288, wp + WIH + 24576, 12288);
    wprep3<<<(49152 + 255) / 256, 256>>>(W_hh, wp + WHH, wp + WHH + 49152, wp + WHH + 98304, 49152);
    wprep3<<<(32768 + 255) / 256, 256>>>(cWq, wp + WQ, wp + WQ + 32768, wp + WQ + 65536, 32768);
    wprep3<<<(32768 + 255) / 256, 256>>>(cWk, wp + WK, wp + WK + 32768, wp + WK + 65536, 32768);
    wprep3<<<(32768 + 255) / 256, 256>>>(cWv, wp + WV, wp + WV + 32768, wp + WV + 65536, 32768);
    wprep3<<<(32768 + 255) / 256, 256>>>(cWs, wp + WS, wp + WS + 32768, wp + WS + 65536, 32768);

    // ---------------- GRU ----------------
    cudaMemsetAsync(phprev, 0, (size_t)NN * HID * sizeof(float));
    {
        PArgs pa;
        for (int p = 0; p < 3; p++) {
            pa.w[p] = wp + WIH + (size_t)p * 128 * 32;
            pa.lvl[p] = 12288;
            pa.bias[p] = b_ih + p * 128;
            pa.out[p] = pgi; pa.col[p] = p * 128; pa.ldc[p] = G3;
        }
        pa.w[3] = pa.w[2]; pa.lvl[3] = 12288; pa.bias[3] = pa.bias[2];
        pa.out[3] = pgi; pa.col[3] = 256; pa.ldc[3] = G3;
        mma_gemm<<<(TN + 127) / 128, 256, SM_BYTES>>>(pa, x_seq, TN, 32, 3);
    }
    {
        PArgs pa;
        for (int p = 0; p < 3; p++) {
            pa.w[p] = wp + WHH + (size_t)p * 128 * 128;
            pa.lvl[p] = 49152;
            pa.bias[p] = b_hh + p * 128;
            pa.out[p] = pgh; pa.col[p] = p * 128; pa.ldc[p] = G3;
        }
        pa.w[3] = pa.w[2]; pa.lvl[3] = 49152; pa.bias[3] = pa.bias[2];
        pa.out[3] = pgh; pa.col[3] = 256; pa.ldc[3] = G3;
        for (int t = 0; t < T_STEPS; t++) {
            mma_gemm<<<(NN + 127) / 128, 256, SM_BYTES>>>(pa, phprev, NN, 128, 3);
            gru_gate<<<nhblk, 256>>>(pgi + (size_t)t * NN * G3, pgh, phprev,
                                     ph + (size_t)t * NN * HID);
        }
    }

    // ---------------- GNN: 2 layers, batched over all T ----------------
    for (int l = 0; l < 2; l++) {
        const float* in  = (l == 0) ? ph : ptmp;
        float*       out = (l == 0) ? ptmp : ph;
        const float* We = cWe + (size_t)l * HID;
        size_t lo = (size_t)l * 16384;

        cudaMemsetAsync(pmacc, 0, (size_t)TN * HID * sizeof(float));
        PArgs pa;
        pa.w[0] = wp + WQ + lo; pa.lvl[0] = 32768; pa.bias[0] = cbq + l * 128;
        pa.out[0] = pq;  pa.col[0] = 0; pa.ldc[0] = 128;
        pa.w[1] = wp + WK + lo; pa.lvl[1] = 32768; pa.bias[1] = cbk + l * 128;
        pa.out[1] = pk;  pa.col[1] = 0; pa.ldc[1] = 128;
        pa.w[2] = wp + WV + lo; pa.lvl[2] = 32768; pa.bias[2] = cbv + l * 128;
        pa.out[2] = pv;  pa.col[2] = 0; pa.ldc[2] = 128;
        pa.w[3] = wp + WS + lo; pa.lvl[3] = 32768; pa.bias[3] = cbs + l * 128;
        pa.out[3] = out; pa.col[3] = 0; pa.ldc[3] = 128;
        mma_gemm<<<(TN + 127) / 128, 256, SM_BYTES>>>(pa, in, TN, 128, 4);

        prep_seg<<<tnwblk, 256>>>(pq, We, pqwe, pamax, pdenom, pcoef);
        edge_alpha_b<<<tewblk, 256>>>(pq, pk, ei, ea, pqwe, palpha, pamax);
        edge_msg_b<<<tewblk, 256>>>(pv, ei, ea, palpha, pamax, pdenom, pcoef, pmacc);
        finish_conv<<<fnblk, 256>>>(out, pmacc, pcoef, We, pdenom);
    }

    // ---------------- temporal attention + top-3 ----------------
    attn_topk<<<nwblk, 256>>>(ph, aW, ab, phattn);

    // ---------------- output TransformerConv (128 -> 1) ----------------
    {
        const int* src = ei + (size_t)(T_STEPS - 1) * 2 * EE;
        const int* dst = src + EE;
        const float* eat = ea + (size_t)(T_STEPS - 1) * EE;
        outconv_node<<<nwblk, 256>>>(phattn, oWq, obq, oWk, obk, oWv, obv, oWs, obs,
                                     pq, pk, pv, outp);
        init_seg<<<nsblk, 256>>>(pamax, pdenom);
        oc_alpha<<<esblk, 256>>>(pq, pk, src, dst, eat, oWe, palpha, pamax);
        edge_ex<<<esblk, 256>>>(dst, palpha, pamax, pdenom);
        oc_msg<<<esblk, 256>>>(pv, src, dst, eat, oWe, palpha, pdenom, outp);
    }
}

// round 8
// speedup vs baseline: 1.5853x; 1.1373x over previous
#include <cuda_runtime.h>
#include <cuda_bf16.h>
#include <math.h>
#include <stdint.h>

#define T_STEPS 8
#define NN      20000
#define FIN_DIM 32
#define EE      160000
#define HID     128
#define G3      384
#define TN      (T_STEPS * NN)
#define TE      (T_STEPS * EE)
#define SCALE   0.08838834764831845f

typedef unsigned long long u64;

// ------------------------- scratch (device globals) -------------------------
__device__ float g_h[(size_t)TN * HID];
__device__ float g_tmp[(size_t)TN * HID];
__device__ float g_q[(size_t)TN * HID];
__device__ float g_k[(size_t)TN * HID];
__device__ float g_v[(size_t)TN * HID];
__device__ float g_gi[(size_t)TN * G3];
__device__ float g_gh[(size_t)NN * G3];
__device__ float g_hprev[(size_t)NN * HID];
__device__ float g_hattn[(size_t)NN * HID];
__device__ float g_qs[NN], g_ks[NN], g_vs[NN];
__device__ __align__(16) __nv_bfloat16 g_wprep[577536];
// CSR
__device__ int   g_cnt[TN];
__device__ int   g_start[TN];
__device__ int   g_cur[TN];
__device__ int   g_csrc[TE];
__device__ float g_cea[TE];

#define WIH 0        // level stride 12288
#define WHH 36864    // level stride 49152
#define WQ  184320   // level stride 32768
#define WK  282624
#define WV  380928
#define WS  479232

// ------------------------------- helpers ------------------------------------
__device__ __forceinline__ float warp_sum(float v) {
#pragma unroll
    for (int o = 16; o; o >>= 1) v += __shfl_xor_sync(0xffffffffu, v, o);
    return v;
}
__device__ __forceinline__ float warp_max(float v) {
#pragma unroll
    for (int o = 16; o; o >>= 1) v = fmaxf(v, __shfl_xor_sync(0xffffffffu, v, o));
    return v;
}
__device__ __forceinline__ float dot4(float4 a, float4 b) {
    return a.x * b.x + a.y * b.y + a.z * b.z + a.w * b.w;
}
__device__ __forceinline__ float sigf(float x) { return 1.0f / (1.0f + expf(-x)); }

// --------------------------- mma.sync GEMM (unchanged from R7) ---------------
#define ROWB 272
#define LVLB (128 * ROWB)
#define SB_OFF (3 * LVLB)
#define SM_BYTES (6 * LVLB)

struct PArgs {
    const __nv_bfloat16* w[4];
    int lvl[4];
    const float* bias[4];
    float* out[4];
    int col[4];
    int ldc[4];
};

__device__ __forceinline__ void mma16816(float* c, const uint32_t* a, const uint32_t* b) {
    asm volatile(
        "mma.sync.aligned.m16n8k16.row.col.f32.bf16.bf16.f32 "
        "{%0,%1,%2,%3},{%4,%5,%6,%7},{%8,%9},{%0,%1,%2,%3};"
        : "+f"(c[0]), "+f"(c[1]), "+f"(c[2]), "+f"(c[3])
        : "r"(a[0]), "r"(a[1]), "r"(a[2]), "r"(a[3]), "r"(b[0]), "r"(b[1]));
}
__device__ __forceinline__ void ldsm_x4(uint32_t& r0, uint32_t& r1, uint32_t& r2, uint32_t& r3,
                                        uint32_t addr) {
    asm volatile("ldmatrix.sync.aligned.m8n8.x4.shared.b16 {%0,%1,%2,%3},[%4];"
                 : "=r"(r0), "=r"(r1), "=r"(r2), "=r"(r3) : "r"(addr));
}
__device__ __forceinline__ void ldsm_x2(uint32_t& r0, uint32_t& r1, uint32_t addr) {
    asm volatile("ldmatrix.sync.aligned.m8n8.x2.shared.b16 {%0,%1},[%2];"
                 : "=r"(r0), "=r"(r1) : "r"(addr));
}
__device__ __forceinline__ uint32_t smem_addr32(const void* p) {
    return (uint32_t)__cvta_generic_to_shared(p);
}

__global__ void __launch_bounds__(256) mma_gemm(
    PArgs pa, const float* __restrict__ A, int nrows, int K, int np)
{
    extern __shared__ char sm[];
    const uint32_t smu = smem_addr32(sm);
    const int tid = threadIdx.x, wid = tid >> 5, lane = tid & 31;
    const int brow = blockIdx.x << 7;
    const int kshift = (K == 32) ? 5 : 7;

    const int wm = (wid & 1) * 64;
    const int wn = (wid >> 1) * 32;
    const uint32_t aoff = (uint32_t)((lane & 15) * ROWB + ((lane >> 4) & 1) * 16);
    const uint32_t boff = (uint32_t)((lane & 7) * ROWB + ((lane >> 3) & 1) * 16);

    for (int base = tid * 8; base < (128 << kshift); base += 2048) {
        const int row = base >> kshift;
        const int col = base & (K - 1);
        const int gr = brow + row;
        float4 x0 = make_float4(0.f, 0.f, 0.f, 0.f), x1 = x0;
        if (gr < nrows) {
            const float* src = A + (size_t)gr * K + col;
            x0 = *(const float4*)src;
            x1 = *(const float4*)(src + 4);
        }
        const float av[8] = {x0.x, x0.y, x0.z, x0.w, x1.x, x1.y, x1.z, x1.w};
        uint32_t p0[4], p1[4], p2[4];
#pragma unroll
        for (int j = 0; j < 4; j++) {
            float a0 = av[2 * j], a1 = av[2 * j + 1];
            __nv_bfloat16 h0 = __float2bfloat16(a0), h1 = __float2bfloat16(a1);
            float r0 = a0 - __bfloat162float(h0), r1 = a1 - __bfloat162float(h1);
            __nv_bfloat16 m0 = __float2bfloat16(r0), m1 = __float2bfloat16(r1);
            float s0 = r0 - __bfloat162float(m0), s1 = r1 - __bfloat162float(m1);
            union { __nv_bfloat162 b; uint32_t u; } uh, um, ul;
            uh.b = __nv_bfloat162(h0, h1);
            um.b = __nv_bfloat162(m0, m1);
            ul.b = __nv_bfloat162(__float2bfloat16(s0), __float2bfloat16(s1));
            p0[j] = uh.u; p1[j] = um.u; p2[j] = ul.u;
        }
        char* dst = sm + row * ROWB + col * 2;
        *(uint4*)(dst) = make_uint4(p0[0], p0[1], p0[2], p0[3]);
        *(uint4*)(dst + LVLB) = make_uint4(p1[0], p1[1], p1[2], p1[3]);
        *(uint4*)(dst + 2 * LVLB) = make_uint4(p2[0], p2[1], p2[2], p2[3]);
    }

    const int nb = (128 << kshift) >> 3;

    for (int p = 0; p < np; p++) {
        __syncthreads();
        const __nv_bfloat16* W0 = pa.w[p];
        const int lvl = pa.lvl[p];
#pragma unroll
        for (int lv = 0; lv < 3; lv++) {
            const __nv_bfloat16* Wl = W0 + (size_t)lv * lvl;
            char* dstb = sm + SB_OFF + lv * LVLB;
            for (int i = tid; i < nb; i += 256) {
                const int e = i * 8;
                const int row = e >> kshift;
                const int col = e & (K - 1);
                *(uint4*)(dstb + row * ROWB + col * 2) =
                    *(const uint4*)(Wl + (size_t)row * K + col);
            }
        }
        __syncthreads();

        float acc[4][4][4];
#pragma unroll
        for (int i = 0; i < 4; i++)
#pragma unroll
            for (int j = 0; j < 4; j++)
#pragma unroll
                for (int r = 0; r < 4; r++) acc[i][j][r] = 0.0f;

        const int nk = K >> 4;
        for (int ks = 0; ks < nk; ks++) {
            const uint32_t k2 = (uint32_t)(ks << 5);
            uint32_t bfr[3][4][2];
#pragma unroll
            for (int lv = 0; lv < 3; lv++) {
                const uint32_t bb = smu + SB_OFF + lv * LVLB + k2 + boff;
#pragma unroll
                for (int nt = 0; nt < 4; nt++)
                    ldsm_x2(bfr[lv][nt][0], bfr[lv][nt][1],
                            bb + (uint32_t)((wn + nt * 8) * ROWB));
            }
            uint32_t af[4][4];
            {
                const uint32_t ab = smu + k2 + aoff;
#pragma unroll
                for (int mt = 0; mt < 4; mt++)
                    ldsm_x4(af[mt][0], af[mt][1], af[mt][2], af[mt][3],
                            ab + (uint32_t)((wm + mt * 16) * ROWB));
#pragma unroll
                for (int mt = 0; mt < 4; mt++)
#pragma unroll
                    for (int nt = 0; nt < 4; nt++) {
                        mma16816(acc[mt][nt], af[mt], bfr[0][nt]);
                        mma16816(acc[mt][nt], af[mt], bfr[1][nt]);
                        mma16816(acc[mt][nt], af[mt], bfr[2][nt]);
                    }
            }
            {
                const uint32_t ab = smu + LVLB + k2 + aoff;
#pragma unroll
                for (int mt = 0; mt < 4; mt++)
                    ldsm_x4(af[mt][0], af[mt][1], af[mt][2], af[mt][3],
                            ab + (uint32_t)((wm + mt * 16) * ROWB));
#pragma unroll
                for (int mt = 0; mt < 4; mt++)
#pragma unroll
                    for (int nt = 0; nt < 4; nt++) {
                        mma16816(acc[mt][nt], af[mt], bfr[0][nt]);
                        mma16816(acc[mt][nt], af[mt], bfr[1][nt]);
                    }
            }
            {
                const uint32_t ab = smu + 2 * LVLB + k2 + aoff;
#pragma unroll
                for (int mt = 0; mt < 4; mt++)
                    ldsm_x4(af[mt][0], af[mt][1], af[mt][2], af[mt][3],
                            ab + (uint32_t)((wm + mt * 16) * ROWB));
#pragma unroll
                for (int mt = 0; mt < 4; mt++)
#pragma unroll
                    for (int nt = 0; nt < 4; nt++)
                        mma16816(acc[mt][nt], af[mt], bfr[0][nt]);
            }
        }

        float* Co = pa.out[p];
        const float* bs = pa.bias[p];
        const int ld = pa.ldc[p], cb = pa.col[p];
#pragma unroll
        for (int nt = 0; nt < 4; nt++) {
            const int cloc = wn + nt * 8 + (lane & 3) * 2;
            const float b0 = bs[cloc], b1 = bs[cloc + 1];
#pragma unroll
            for (int mt = 0; mt < 4; mt++) {
                const int r0 = brow + wm + mt * 16 + (lane >> 2);
                if (r0 < nrows) {
                    float2 o = make_float2(acc[mt][nt][0] + b0, acc[mt][nt][1] + b1);
                    *(float2*)(Co + (size_t)r0 * ld + cb + cloc) = o;
                }
                const int r1 = r0 + 8;
                if (r1 < nrows) {
                    float2 o = make_float2(acc[mt][nt][2] + b0, acc[mt][nt][3] + b1);
                    *(float2*)(Co + (size_t)r1 * ld + cb + cloc) = o;
                }
            }
        }
    }
}

// -------------------- merged weight prep (fp32 -> 3x bf16) -------------------
struct WPArgs { const float* src[6]; int n[6]; int base[6]; };

__global__ void wprep_all(WPArgs wa, __nv_bfloat16* __restrict__ wp)
{
    int seg = blockIdx.y;
    int i = blockIdx.x * blockDim.x + threadIdx.x;
    if (i >= wa.n[seg]) return;
    float x = wa.src[seg][i];
    __nv_bfloat16 h = __float2bfloat16(x);
    float r = x - __bfloat162float(h);
    __nv_bfloat16 m = __float2bfloat16(r);
    float s = r - __bfloat162float(m);
    __nv_bfloat16* w = wp + wa.base[seg];
    int n = wa.n[seg];
    w[i] = h; w[n + i] = m; w[2 * n + i] = __float2bfloat16(s);
}

// ------------------------------- CSR build -----------------------------------
__global__ void csr_count(const int* __restrict__ ei, int* __restrict__ cnt)
{
    int w = blockIdx.x * blockDim.x + threadIdx.x;
    if (w >= TE) return;
    int t = w / EE, e = w - t * EE;
    int d = ei[(size_t)t * 2 * EE + EE + e] + t * NN;
    atomicAdd(&cnt[d], 1);
}

__global__ void __launch_bounds__(1024) csr_scan(
    const int* __restrict__ cnt, int* __restrict__ start, int* __restrict__ cur)
{
    __shared__ int sh[1024];
    __shared__ int carry;
    const int tid = threadIdx.x;
    if (tid == 0) carry = 0;
    __syncthreads();
    for (int base = 0; base < TN; base += 1024) {
        int v = (base + tid < TN) ? cnt[base + tid] : 0;
        sh[tid] = v;
        __syncthreads();
#pragma unroll
        for (int off = 1; off < 1024; off <<= 1) {
            int add = (tid >= off) ? sh[tid - off] : 0;
            __syncthreads();
            sh[tid] += add;
            __syncthreads();
        }
        int excl = sh[tid] - v + carry;
        if (base + tid < TN) { start[base + tid] = excl; cur[base + tid] = excl; }
        int tot = sh[1023];
        __syncthreads();
        if (tid == 0) carry += tot;
        __syncthreads();
    }
}

__global__ void csr_scatter(const int* __restrict__ ei, const float* __restrict__ ea,
                            int* __restrict__ cur, int* __restrict__ csrc,
                            float* __restrict__ cea)
{
    int w = blockIdx.x * blockDim.x + threadIdx.x;
    if (w >= TE) return;
    int t = w / EE, e = w - t * EE;
    const int* eib = ei + (size_t)t * 2 * EE;
    int s = eib[e] + t * NN;
    int d = eib[EE + e] + t * NN;
    int pos = atomicAdd(&cur[d], 1);
    csrc[pos] = s;
    cea[pos] = ea[w];
}

// ------------------------------- GRU gates ----------------------------------
__global__ void gru_gate(const float* __restrict__ gi, const float* __restrict__ gh,
                         float* __restrict__ hprev, float* __restrict__ hout)
{
    int idx = blockIdx.x * blockDim.x + threadIdx.x;
    if (idx >= NN * HID) return;
    int n = idx / HID, c = idx % HID;
    const float* gin = gi + (size_t)n * G3;
    const float* ghn = gh + (size_t)n * G3;
    float r = sigf(gin[c] + ghn[c]);
    float z = sigf(gin[HID + c] + ghn[HID + c]);
    float nn = tanhf(gin[2 * HID + c] + r * ghn[2 * HID + c]);
    float hp = hprev[idx];
    float hn = (1.0f - z) * nn + z * hp;
    hprev[idx] = hn;
    hout[idx] = hn;
}

// -------------- fused conv edge phase: warp/dst, streaming softmax -----------
__global__ void __launch_bounds__(256) conv_edge(
    const float* __restrict__ q, const float* __restrict__ k,
    const float* __restrict__ v, const float* __restrict__ We,
    const int* __restrict__ start, const int* __restrict__ cnt,
    const int* __restrict__ csrc, const float* __restrict__ cea,
    float* __restrict__ out)
{
    int n = (blockIdx.x * blockDim.x + threadIdx.x) >> 5;
    int lane = threadIdx.x & 31;
    if (n >= TN) return;
    const int i4 = lane << 2;
    float4 qv = *(const float4*)(q + (size_t)n * HID + i4);
    float4 wev = *(const float4*)(We + i4);
    float qwe = warp_sum(dot4(qv, wev)) * SCALE;

    const int s0 = start[n], c = cnt[n];
    float mx = -INFINITY, denom = 0.0f, coef = 0.0f;
    float4 macc = make_float4(0.f, 0.f, 0.f, 0.f);

    for (int j = s0; j < s0 + c; j++) {
        int s = csrc[j];
        float eav = cea[j];
        float4 kv = *(const float4*)(k + (size_t)s * HID + i4);
        float p = warp_sum(dot4(qv, kv));
        float al = p * SCALE + eav * qwe;
        float4 vv = *(const float4*)(v + (size_t)s * HID + i4);
        if (al > mx) {
            float sc = expf(mx - al);
            denom *= sc; coef *= sc;
            macc.x *= sc; macc.y *= sc; macc.z *= sc; macc.w *= sc;
            mx = al;
        }
        float a = expf(al - mx);
        denom += a;
        coef += a * eav;
        macc.x += a * vv.x; macc.y += a * vv.y; macc.z += a * vv.z; macc.w += a * vv.w;
    }

    float inv = 1.0f / (denom + 1e-16f);
    float4 sk = *(const float4*)(out + (size_t)n * HID + i4);
    float4 o;
    o.x = sk.x + (macc.x + coef * wev.x) * inv;
    o.y = sk.y + (macc.y + coef * wev.y) * inv;
    o.z = sk.z + (macc.z + coef * wev.z) * inv;
    o.w = sk.w + (macc.w + coef * wev.w) * inv;
    o.x = o.x > 0.f ? o.x : 0.01f * o.x;
    o.y = o.y > 0.f ? o.y : 0.01f * o.y;
    o.z = o.z > 0.f ? o.z : 0.01f * o.z;
    o.w = o.w > 0.f ? o.w : 0.01f * o.w;
    *(float4*)(out + (size_t)n * HID + i4) = o;
}

// --------------------- temporal attention + top-k (warp/node) ----------------
__global__ void __launch_bounds__(256) attn_topk(
    const float* __restrict__ h, const float* __restrict__ W,
    const float* __restrict__ b, float* __restrict__ hattn)
{
    int n = (blockIdx.x * blockDim.x + threadIdx.x) >> 5;
    int lane = threadIdx.x & 31;
    if (n >= NN) return;
    float s[T_STEPS];
#pragma unroll
    for (int t = 0; t < T_STEPS; t++) {
        const float* row = h + ((size_t)t * NN + n) * HID;
        float p = 0.0f;
#pragma unroll
        for (int i = lane; i < HID; i += 32) p = fmaf(row[i], W[i], p);
        s[t] = warp_sum(p) + b[0];
    }
    float mx = s[0];
#pragma unroll
    for (int t = 1; t < T_STEPS; t++) mx = fmaxf(mx, s[t]);
    float aw[T_STEPS]; float tot = 0.0f;
#pragma unroll
    for (int t = 0; t < T_STEPS; t++) { aw[t] = expf(s[t] - mx); tot += aw[t]; }
    float inv = 1.0f / tot;
#pragma unroll
    for (int t = 0; t < T_STEPS; t++) aw[t] *= inv;
    bool sel[T_STEPS];
#pragma unroll
    for (int t = 0; t < T_STEPS; t++) sel[t] = false;
    float sum3 = 0.0f;
#pragma unroll
    for (int r = 0; r < 3; r++) {
        float best = -1.0f; int bi = 0;
#pragma unroll
        for (int t = 0; t < T_STEPS; t++)
            if (!sel[t] && aw[t] > best) { best = aw[t]; bi = t; }
        sel[bi] = true; sum3 += best;
    }
    float winv = 1.0f / (sum3 + 1e-8f);
    float w[T_STEPS];
#pragma unroll
    for (int t = 0; t < T_STEPS; t++) w[t] = sel[t] ? aw[t] * winv : 0.0f;
#pragma unroll
    for (int i = lane; i < HID; i += 32) {
        float acc = 0.0f;
#pragma unroll
        for (int t = 0; t < T_STEPS; t++)
            acc = fmaf(w[t], h[((size_t)t * NN + n) * HID + i], acc);
        hattn[(size_t)n * HID + i] = acc;
    }
}

// ------------------------- output conv (C_out = 1) ---------------------------
__global__ void __launch_bounds__(256) outconv_node(
    const float* __restrict__ x,
    const float* __restrict__ Wq, const float* __restrict__ bq,
    const float* __restrict__ Wk, const float* __restrict__ bk,
    const float* __restrict__ Wv, const float* __restrict__ bv,
    const float* __restrict__ Ws, const float* __restrict__ bs,
    float* __restrict__ qs, float* __restrict__ ks,
    float* __restrict__ vs, float* __restrict__ outp)
{
    int n = (blockIdx.x * blockDim.x + threadIdx.x) >> 5;
    int lane = threadIdx.x & 31;
    if (n >= NN) return;
    const float* xr = x + (size_t)n * HID;
    float pq = 0.f, pk = 0.f, pv = 0.f, ps = 0.f;
#pragma unroll
    for (int i = lane; i < HID; i += 32) {
        float xv = xr[i];
        pq = fmaf(xv, Wq[i], pq);
        pk = fmaf(xv, Wk[i], pk);
        pv = fmaf(xv, Wv[i], pv);
        ps = fmaf(xv, Ws[i], ps);
    }
    pq = warp_sum(pq); pk = warp_sum(pk); pv = warp_sum(pv); ps = warp_sum(ps);
    if (lane == 0) {
        qs[n] = pq + bq[0];
        ks[n] = pk + bk[0];
        vs[n] = pv + bv[0];
        outp[n] = ps + bs[0];
    }
}

// fused output-conv edge phase (warp/dst, lanes over edges, reuses t=7 CSR)
__global__ void __launch_bounds__(256) oc_edge(
    const float* __restrict__ qs, const float* __restrict__ ks,
    const float* __restrict__ vs, const float* __restrict__ We,
    const int* __restrict__ start, const int* __restrict__ cnt,
    const int* __restrict__ csrc, const float* __restrict__ cea,
    float* __restrict__ outp)
{
    int n = (blockIdx.x * blockDim.x + threadIdx.x) >> 5;
    int lane = threadIdx.x & 31;
    if (n >= NN) return;
    const int g = (T_STEPS - 1) * NN + n;
    const int s0 = start[g], c = cnt[g];
    if (c == 0) return;
    const float qsn = qs[n];
    const float we0 = We[0];

    float mx = -INFINITY;
    for (int j = s0 + lane; j < s0 + c; j += 32) {
        int sl = csrc[j] - (T_STEPS - 1) * NN;
        float al = qsn * (ks[sl] + cea[j] * we0);
        mx = fmaxf(mx, al);
    }
    mx = warp_max(mx);

    float dsum = 0.f, msum = 0.f;
    for (int j = s0 + lane; j < s0 + c; j += 32) {
        int sl = csrc[j] - (T_STEPS - 1) * NN;
        float eav = cea[j];
        float al = qsn * (ks[sl] + eav * we0);
        float a = expf(al - mx);
        dsum += a;
        msum += a * (vs[sl] + eav * we0);
    }
    dsum = warp_sum(dsum);
    msum = warp_sum(msum);
    if (lane == 0) outp[n] += msum / (dsum + 1e-16f);
}

// --------------------------------- host --------------------------------------
static float* symf(const void* sym) { void* p = nullptr; cudaGetSymbolAddress(&p, sym); return (float*)p; }

extern "C" void kernel_launch(void* const* d_in, const int* in_sizes, int n_in,
                              void* d_out, int out_size)
{
    const float* x_seq = (const float*)d_in[0];
    const int*   ei    = (const int*)d_in[1];
    const float* ea    = (const float*)d_in[2];
    const float* W_ih  = (const float*)d_in[3];
    const float* W_hh  = (const float*)d_in[4];
    const float* b_ih  = (const float*)d_in[5];
    const float* b_hh  = (const float*)d_in[6];
    const float* cWq = (const float*)d_in[7];  const float* cbq = (const float*)d_in[8];
    const float* cWk = (const float*)d_in[9];  const float* cbk = (const float*)d_in[10];
    const float* cWv = (const float*)d_in[11]; const float* cbv = (const float*)d_in[12];
    const float* cWe = (const float*)d_in[13];
    const float* cWs = (const float*)d_in[14]; const float* cbs = (const float*)d_in[15];
    const float* oWq = (const float*)d_in[16]; const float* obq = (const float*)d_in[17];
    const float* oWk = (const float*)d_in[18]; const float* obk = (const float*)d_in[19];
    const float* oWv = (const float*)d_in[20]; const float* obv = (const float*)d_in[21];
    const float* oWe = (const float*)d_in[22];
    const float* oWs = (const float*)d_in[23]; const float* obs = (const float*)d_in[24];
    const float* aW  = (const float*)d_in[25]; const float* ab  = (const float*)d_in[26];
    float* outp = (float*)d_out;

    float* ph     = symf(g_h);
    float* ptmp   = symf(g_tmp);
    float* pq     = symf(g_q);
    float* pk     = symf(g_k);
    float* pv     = symf(g_v);
    float* pgi    = symf(g_gi);
    float* pgh    = symf(g_gh);
    float* phprev = symf(g_hprev);
    float* phattn = symf(g_hattn);
    float* pqs    = symf(g_qs);
    float* pks    = symf(g_ks);
    float* pvs    = symf(g_vs);
    int*   pcnt   = (int*)symf(g_cnt);
    int*   pstart = (int*)symf(g_start);
    int*   pcur   = (int*)symf(g_cur);
    int*   pcsrc  = (int*)symf(g_csrc);
    float* pcea   = symf(g_cea);
    __nv_bfloat16* wp = (__nv_bfloat16*)symf(g_wprep);

    cudaFuncSetAttribute(mma_gemm, cudaFuncAttributeMaxDynamicSharedMemorySize, SM_BYTES);

    const int nwblk  = (NN + 7) / 8;
    const int tnwblk = (TN + 7) / 8;
    const int teblk  = (TE + 255) / 256;
    const int nhblk  = (NN * HID + 255) / 256;

    // ---------------- weight prep (single launch) ----------------
    {
        WPArgs wa;
        wa.src[0] = W_ih; wa.n[0] = 12288; wa.base[0] = WIH;
        wa.src[1] = W_hh; wa.n[1] = 49152; wa.base[1] = WHH;
        wa.src[2] = cWq;  wa.n[2] = 32768; wa.base[2] = WQ;
        wa.src[3] = cWk;  wa.n[3] = 32768; wa.base[3] = WK;
        wa.src[4] = cWv;  wa.n[4] = 32768; wa.base[4] = WV;
        wa.src[5] = cWs;  wa.n[5] = 32768; wa.base[5] = WS;
        wprep_all<<<dim3((49152 + 255) / 256, 6), 256>>>(wa, wp);
    }

    // ---------------- CSR build (shared by both conv layers + out conv) -----
    cudaMemsetAsync(pcnt, 0, TN * sizeof(int));
    csr_count<<<teblk, 256>>>(ei, pcnt);
    csr_scan<<<1, 1024>>>(pcnt, pstart, pcur);
    csr_scatter<<<teblk, 256>>>(ei, ea, pcur, pcsrc, pcea);

    // ---------------- GRU ----------------
    cudaMemsetAsync(phprev, 0, (size_t)NN * HID * sizeof(float));
    {
        PArgs pa;
        for (int p = 0; p < 3; p++) {
            pa.w[p] = wp + WIH + (size_t)p * 128 * 32;
            pa.lvl[p] = 12288;
            pa.bias[p] = b_ih + p * 128;
            pa.out[p] = pgi; pa.col[p] = p * 128; pa.ldc[p] = G3;
        }
        pa.w[3] = pa.w[2]; pa.lvl[3] = 12288; pa.bias[3] = pa.bias[2];
        pa.out[3] = pgi; pa.col[3] = 256; pa.ldc[3] = G3;
        mma_gemm<<<(TN + 127) / 128, 256, SM_BYTES>>>(pa, x_seq, TN, 32, 3);
    }
    {
        PArgs pa;
        for (int p = 0; p < 3; p++) {
            pa.w[p] = wp + WHH + (size_t)p * 128 * 128;
            pa.lvl[p] = 49152;
            pa.bias[p] = b_hh + p * 128;
            pa.out[p] = pgh; pa.col[p] = p * 128; pa.ldc[p] = G3;
        }
        pa.w[3] = pa.w[2]; pa.lvl[3] = 49152; pa.bias[3] = pa.bias[2];
        pa.out[3] = pgh; pa.col[3] = 256; pa.ldc[3] = G3;
        for (int t = 0; t < T_STEPS; t++) {
            mma_gemm<<<(NN + 127) / 128, 256, SM_BYTES>>>(pa, phprev, NN, 128, 3);
            gru_gate<<<nhblk, 256>>>(pgi + (size_t)t * NN * G3, pgh, phprev,
                                     ph + (size_t)t * NN * HID);
        }
    }

    // ---------------- GNN: 2 layers, batched over all T ----------------
    for (int l = 0; l < 2; l++) {
        const float* in  = (l == 0) ? ph : ptmp;
        float*       out = (l == 0) ? ptmp : ph;
        const float* We = cWe + (size_t)l * HID;
        size_t lo = (size_t)l * 16384;

        PArgs pa;
        pa.w[0] = wp + WQ + lo; pa.lvl[0] = 32768; pa.bias[0] = cbq + l * 128;
        pa.out[0] = pq;  pa.col[0] = 0; pa.ldc[0] = 128;
        pa.w[1] = wp + WK + lo; pa.lvl[1] = 32768; pa.bias[1] = cbk + l * 128;
        pa.out[1] = pk;  pa.col[1] = 0; pa.ldc[1] = 128;
        pa.w[2] = wp + WV + lo; pa.lvl[2] = 32768; pa.bias[2] = cbv + l * 128;
        pa.out[2] = pv;  pa.col[2] = 0; pa.ldc[2] = 128;
        pa.w[3] = wp + WS + lo; pa.lvl[3] = 32768; pa.bias[3] = cbs + l * 128;
        pa.out[3] = out; pa.col[3] = 0; pa.ldc[3] = 128;
        mma_gemm<<<(TN + 127) / 128, 256, SM_BYTES>>>(pa, in, TN, 128, 4);

        conv_edge<<<tnwblk, 256>>>(pq, pk, pv, We, pstart, pcnt, pcsrc, pcea, out);
    }

    // ---------------- temporal attention + top-3 ----------------
    attn_topk<<<nwblk, 256>>>(ph, aW, ab, phattn);

    // ---------------- output TransformerConv (128 -> 1) ----------------
    outconv_node<<<nwblk, 256>>>(phattn, oWq, obq, oWk, obk, oWv, obv, oWs, obs,
                                 pqs, pks, pvs, outp);
    oc_edge<<<nwblk, 256>>>(pqs, pks, pvs, oWe, pstart, pcnt, pcsrc, pcea, outp);
}

// round 9
// speedup vs baseline: 1.8659x; 1.1770x over previous
#include <cuda_runtime.h>
#include <cuda_fp16.h>
#include <math.h>
#include <stdint.h>

#define T_STEPS 8
#define NN      20000
#define FIN_DIM 32
#define EE      160000
#define HID     128
#define G3      384
#define TN      (T_STEPS * NN)
#define TE      (T_STEPS * EE)
#define SCALE   0.08838834764831845f
#define LVL_SC  2048.0f
#define LVL_INV (1.0f / 2048.0f)

typedef unsigned long long u64;

// ------------------------- scratch (device globals) -------------------------
__device__ float g_h[(size_t)TN * HID];
__device__ float g_tmp[(size_t)TN * HID];
__device__ float g_q[(size_t)TN * HID];
__device__ float g_k[(size_t)TN * HID];
__device__ float g_v[(size_t)TN * HID];
__device__ float g_gi[(size_t)TN * G3];
__device__ float g_gh[(size_t)NN * G3];
__device__ float g_hprev[(size_t)NN * HID];
__device__ float g_hattn[(size_t)NN * HID];
__device__ float g_qs[NN], g_ks[NN], g_vs[NN];
__device__ __align__(16) __half g_wprep[385024];   // 2-level fp16 split weights
// CSR
__device__ int   g_cnt[TN];
__device__ int   g_start[TN];
__device__ int   g_cur[TN];
__device__ int   g_csrc[TE];
__device__ float g_cea[TE];

#define WIH 0        // level stride 12288
#define WHH 24576    // level stride 49152
#define WQ  122880   // level stride 32768
#define WK  188416
#define WV  253952
#define WS  319488

// ------------------------------- helpers ------------------------------------
__device__ __forceinline__ float warp_sum(float v) {
#pragma unroll
    for (int o = 16; o; o >>= 1) v += __shfl_xor_sync(0xffffffffu, v, o);
    return v;
}
__device__ __forceinline__ float warp_max(float v) {
#pragma unroll
    for (int o = 16; o; o >>= 1) v = fmaxf(v, __shfl_xor_sync(0xffffffffu, v, o));
    return v;
}
__device__ __forceinline__ float dot4(float4 a, float4 b) {
    return a.x * b.x + a.y * b.y + a.z * b.z + a.w * b.w;
}
__device__ __forceinline__ float sigf(float x) { return 1.0f / (1.0f + expf(-x)); }

// --------------------------- mma.sync GEMM (fp16 2-level, 3-pass) ------------
#define ROWB 272
#define LVLB (128 * ROWB)        // 34816 B per level buffer
#define SB_OFF (2 * LVLB)        // B starts after 2 A levels
#define SM_BYTES (4 * LVLB)      // 139264

struct PArgs {
    const __half* w[4];          // level-0 base; level-1 at +lvl
    int lvl[4];
    const float* bias[4];
    float* out[4];
    int col[4];
    int ldc[4];
};

__device__ __forceinline__ void mma16816(float* c, const uint32_t* a, const uint32_t* b) {
    asm volatile(
        "mma.sync.aligned.m16n8k16.row.col.f32.f16.f16.f32 "
        "{%0,%1,%2,%3},{%4,%5,%6,%7},{%8,%9},{%0,%1,%2,%3};"
        : "+f"(c[0]), "+f"(c[1]), "+f"(c[2]), "+f"(c[3])
        : "r"(a[0]), "r"(a[1]), "r"(a[2]), "r"(a[3]), "r"(b[0]), "r"(b[1]));
}
__device__ __forceinline__ void ldsm_x4(uint32_t& r0, uint32_t& r1, uint32_t& r2, uint32_t& r3,
                                        uint32_t addr) {
    asm volatile("ldmatrix.sync.aligned.m8n8.x4.shared.b16 {%0,%1,%2,%3},[%4];"
                 : "=r"(r0), "=r"(r1), "=r"(r2), "=r"(r3) : "r"(addr));
}
__device__ __forceinline__ void ldsm_x2(uint32_t& r0, uint32_t& r1, uint32_t addr) {
    asm volatile("ldmatrix.sync.aligned.m8n8.x2.shared.b16 {%0,%1},[%2];"
                 : "=r"(r0), "=r"(r1) : "r"(addr));
}
__device__ __forceinline__ uint32_t smem_addr32(const void* p) {
    return (uint32_t)__cvta_generic_to_shared(p);
}

__global__ void __launch_bounds__(256) mma_gemm(
    PArgs pa, const float* __restrict__ A, int nrows, int K, int np)
{
    extern __shared__ char sm[];
    const uint32_t smu = smem_addr32(sm);
    const int tid = threadIdx.x, wid = tid >> 5, lane = tid & 31;
    const int brow = blockIdx.x << 7;
    const int kshift = (K == 32) ? 5 : 7;

    const int wm = (wid & 1) * 64;
    const int wn = (wid >> 1) * 32;
    const uint32_t aoff = (uint32_t)((lane & 15) * ROWB + ((lane >> 4) & 1) * 16);
    const uint32_t boff = (uint32_t)((lane & 7) * ROWB + ((lane >> 3) & 1) * 16);

    // ---- stage A once: fp32 -> 2 fp16 levels (level 1 scaled x2048) ----
    for (int base = tid * 8; base < (128 << kshift); base += 2048) {
        const int row = base >> kshift;
        const int col = base & (K - 1);
        const int gr = brow + row;
        float4 x0 = make_float4(0.f, 0.f, 0.f, 0.f), x1 = x0;
        if (gr < nrows) {
            const float* src = A + (size_t)gr * K + col;
            x0 = *(const float4*)src;
            x1 = *(const float4*)(src + 4);
        }
        const float av[8] = {x0.x, x0.y, x0.z, x0.w, x1.x, x1.y, x1.z, x1.w};
        uint32_t p0[4], p1[4];
#pragma unroll
        for (int j = 0; j < 4; j++) {
            float a0 = av[2 * j], a1 = av[2 * j + 1];
            __half h0 = __float2half_rn(a0), h1 = __float2half_rn(a1);
            float r0 = (a0 - __half2float(h0)) * LVL_SC;
            float r1 = (a1 - __half2float(h1)) * LVL_SC;
            union { __half2 h; uint32_t u; } uh, ul;
            uh.h = __halves2half2(h0, h1);
            ul.h = __halves2half2(__float2half_rn(r0), __float2half_rn(r1));
            p0[j] = uh.u; p1[j] = ul.u;
        }
        char* dst = sm + row * ROWB + col * 2;
        *(uint4*)(dst) = make_uint4(p0[0], p0[1], p0[2], p0[3]);
        *(uint4*)(dst + LVLB) = make_uint4(p1[0], p1[1], p1[2], p1[3]);
    }

    const int nb = (128 << kshift) >> 3;

    for (int p = 0; p < np; p++) {
        __syncthreads();
        // ---- stage B (2 pre-split levels) ----
        const __half* W0 = pa.w[p];
        const int lvl = pa.lvl[p];
#pragma unroll
        for (int lv = 0; lv < 2; lv++) {
            const __half* Wl = W0 + (size_t)lv * lvl;
            char* dstb = sm + SB_OFF + lv * LVLB;
            for (int i = tid; i < nb; i += 256) {
                const int e = i * 8;
                const int row = e >> kshift;
                const int col = e & (K - 1);
                *(uint4*)(dstb + row * ROWB + col * 2) =
                    *(const uint4*)(Wl + (size_t)row * K + col);
            }
        }
        __syncthreads();

        float acc0[4][4][4], acc1[4][4][4];
#pragma unroll
        for (int i = 0; i < 4; i++)
#pragma unroll
            for (int j = 0; j < 4; j++)
#pragma unroll
                for (int r = 0; r < 4; r++) { acc0[i][j][r] = 0.0f; acc1[i][j][r] = 0.0f; }

        const int nk = K >> 4;
        for (int ks = 0; ks < nk; ks++) {
            const uint32_t k2 = (uint32_t)(ks << 5);
            uint32_t bf0[4][2], bf1[4][2];
            {
                const uint32_t bb0 = smu + SB_OFF + k2 + boff;
                const uint32_t bb1 = bb0 + LVLB;
#pragma unroll
                for (int nt = 0; nt < 4; nt++) {
                    ldsm_x2(bf0[nt][0], bf0[nt][1], bb0 + (uint32_t)((wn + nt * 8) * ROWB));
                    ldsm_x2(bf1[nt][0], bf1[nt][1], bb1 + (uint32_t)((wn + nt * 8) * ROWB));
                }
            }
            uint32_t af[4][4];
            {   // A level 0: acc0 += A0*B0 ; acc1 += A0*B1'
                const uint32_t ab = smu + k2 + aoff;
#pragma unroll
                for (int mt = 0; mt < 4; mt++)
                    ldsm_x4(af[mt][0], af[mt][1], af[mt][2], af[mt][3],
                            ab + (uint32_t)((wm + mt * 16) * ROWB));
#pragma unroll
                for (int mt = 0; mt < 4; mt++)
#pragma unroll
                    for (int nt = 0; nt < 4; nt++) {
                        mma16816(acc0[mt][nt], af[mt], bf0[nt]);
                        mma16816(acc1[mt][nt], af[mt], bf1[nt]);
                    }
            }
            {   // A level 1': acc1 += A1'*B0
                const uint32_t ab = smu + LVLB + k2 + aoff;
#pragma unroll
                for (int mt = 0; mt < 4; mt++)
                    ldsm_x4(af[mt][0], af[mt][1], af[mt][2], af[mt][3],
                            ab + (uint32_t)((wm + mt * 16) * ROWB));
#pragma unroll
                for (int mt = 0; mt < 4; mt++)
#pragma unroll
                    for (int nt = 0; nt < 4; nt++)
                        mma16816(acc1[mt][nt], af[mt], bf0[nt]);
            }
        }

        // ---- epilogue: D = acc0 + acc1/2048 + bias ----
        float* Co = pa.out[p];
        const float* bs = pa.bias[p];
        const int ld = pa.ldc[p], cb = pa.col[p];
#pragma unroll
        for (int nt = 0; nt < 4; nt++) {
            const int cloc = wn + nt * 8 + (lane & 3) * 2;
            const float b0 = bs[cloc], b1 = bs[cloc + 1];
#pragma unroll
            for (int mt = 0; mt < 4; mt++) {
                const int r0 = brow + wm + mt * 16 + (lane >> 2);
                if (r0 < nrows) {
                    float2 o = make_float2(acc0[mt][nt][0] + acc1[mt][nt][0] * LVL_INV + b0,
                                           acc0[mt][nt][1] + acc1[mt][nt][1] * LVL_INV + b1);
                    *(float2*)(Co + (size_t)r0 * ld + cb + cloc) = o;
                }
                const int r1 = r0 + 8;
                if (r1 < nrows) {
                    float2 o = make_float2(acc0[mt][nt][2] + acc1[mt][nt][2] * LVL_INV + b0,
                                           acc0[mt][nt][3] + acc1[mt][nt][3] * LVL_INV + b1);
                    *(float2*)(Co + (size_t)r1 * ld + cb + cloc) = o;
                }
            }
        }
    }
}

// -------------------- merged weight prep (fp32 -> 2x fp16) -------------------
struct WPArgs { const float* src[6]; int n[6]; int base[6]; };

__global__ void wprep_all(WPArgs wa, __half* __restrict__ wp)
{
    int seg = blockIdx.y;
    int i = blockIdx.x * blockDim.x + threadIdx.x;
    if (i >= wa.n[seg]) return;
    float x = wa.src[seg][i];
    __half h = __float2half_rn(x);
    float r = (x - __half2float(h)) * LVL_SC;
    __half* w = wp + wa.base[seg];
    int n = wa.n[seg];
    w[i] = h;
    w[n + i] = __float2half_rn(r);
}

// ------------------------------- CSR build -----------------------------------
__global__ void csr_count(const int* __restrict__ ei, int* __restrict__ cnt)
{
    int w = blockIdx.x * blockDim.x + threadIdx.x;
    if (w >= TE) return;
    int t = w / EE, e = w - t * EE;
    int d = ei[(size_t)t * 2 * EE + EE + e] + t * NN;
    atomicAdd(&cnt[d], 1);
}

__global__ void __launch_bounds__(1024) csr_scan(
    const int* __restrict__ cnt, int* __restrict__ start, int* __restrict__ cur)
{
    __shared__ int sh[1024];
    __shared__ int carry;
    const int tid = threadIdx.x;
    if (tid == 0) carry = 0;
    __syncthreads();
    for (int base = 0; base < TN; base += 1024) {
        int v = (base + tid < TN) ? cnt[base + tid] : 0;
        sh[tid] = v;
        __syncthreads();
#pragma unroll
        for (int off = 1; off < 1024; off <<= 1) {
            int add = (tid >= off) ? sh[tid - off] : 0;
            __syncthreads();
            sh[tid] += add;
            __syncthreads();
        }
        int excl = sh[tid] - v + carry;
        if (base + tid < TN) { start[base + tid] = excl; cur[base + tid] = excl; }
        int tot = sh[1023];
        __syncthreads();
        if (tid == 0) carry += tot;
        __syncthreads();
    }
}

__global__ void csr_scatter(const int* __restrict__ ei, const float* __restrict__ ea,
                            int* __restrict__ cur, int* __restrict__ csrc,
                            float* __restrict__ cea)
{
    int w = blockIdx.x * blockDim.x + threadIdx.x;
    if (w >= TE) return;
    int t = w / EE, e = w - t * EE;
    const int* eib = ei + (size_t)t * 2 * EE;
    int s = eib[e] + t * NN;
    int d = eib[EE + e] + t * NN;
    int pos = atomicAdd(&cur[d], 1);
    csrc[pos] = s;
    cea[pos] = ea[w];
}

// ------------------------------- GRU gates ----------------------------------
__global__ void gru_gate(const float* __restrict__ gi, const float* __restrict__ gh,
                         float* __restrict__ hprev, float* __restrict__ hout)
{
    int idx = blockIdx.x * blockDim.x + threadIdx.x;
    if (idx >= NN * HID) return;
    int n = idx / HID, c = idx % HID;
    const float* gin = gi + (size_t)n * G3;
    const float* ghn = gh + (size_t)n * G3;
    float r = sigf(gin[c] + ghn[c]);
    float z = sigf(gin[HID + c] + ghn[HID + c]);
    float nn = tanhf(gin[2 * HID + c] + r * ghn[2 * HID + c]);
    float hp = hprev[idx];
    float hn = (1.0f - z) * nn + z * hp;
    hprev[idx] = hn;
    hout[idx] = hn;
}

// -------------- fused conv edge phase: warp/dst, streaming softmax -----------
__global__ void __launch_bounds__(256) conv_edge(
    const float* __restrict__ q, const float* __restrict__ k,
    const float* __restrict__ v, const float* __restrict__ We,
    const int* __restrict__ start, const int* __restrict__ cnt,
    const int* __restrict__ csrc, const float* __restrict__ cea,
    float* __restrict__ out)
{
    int n = (blockIdx.x * blockDim.x + threadIdx.x) >> 5;
    int lane = threadIdx.x & 31;
    if (n >= TN) return;
    const int i4 = lane << 2;
    float4 qv = *(const float4*)(q + (size_t)n * HID + i4);
    float4 wev = *(const float4*)(We + i4);
    float qwe = warp_sum(dot4(qv, wev)) * SCALE;

    const int s0 = start[n], c = cnt[n];
    float mx = -INFINITY, denom = 0.0f, coef = 0.0f;
    float4 macc = make_float4(0.f, 0.f, 0.f, 0.f);

    for (int j = s0; j < s0 + c; j++) {
        int s = csrc[j];
        float eav = cea[j];
        float4 kv = *(const float4*)(k + (size_t)s * HID + i4);
        float p = warp_sum(dot4(qv, kv));
        float al = p * SCALE + eav * qwe;
        float4 vv = *(const float4*)(v + (size_t)s * HID + i4);
        if (al > mx) {
            float sc = expf(mx - al);
            denom *= sc; coef *= sc;
            macc.x *= sc; macc.y *= sc; macc.z *= sc; macc.w *= sc;
            mx = al;
        }
        float a = expf(al - mx);
        denom += a;
        coef += a * eav;
        macc.x += a * vv.x; macc.y += a * vv.y; macc.z += a * vv.z; macc.w += a * vv.w;
    }

    float inv = 1.0f / (denom + 1e-16f);
    float4 sk = *(const float4*)(out + (size_t)n * HID + i4);
    float4 o;
    o.x = sk.x + (macc.x + coef * wev.x) * inv;
    o.y = sk.y + (macc.y + coef * wev.y) * inv;
    o.z = sk.z + (macc.z + coef * wev.z) * inv;
    o.w = sk.w + (macc.w + coef * wev.w) * inv;
    o.x = o.x > 0.f ? o.x : 0.01f * o.x;
    o.y = o.y > 0.f ? o.y : 0.01f * o.y;
    o.z = o.z > 0.f ? o.z : 0.01f * o.z;
    o.w = o.w > 0.f ? o.w : 0.01f * o.w;
    *(float4*)(out + (size_t)n * HID + i4) = o;
}

// --------------------- temporal attention + top-k (warp/node) ----------------
__global__ void __launch_bounds__(256) attn_topk(
    const float* __restrict__ h, const float* __restrict__ W,
    const float* __restrict__ b, float* __restrict__ hattn)
{
    int n = (blockIdx.x * blockDim.x + threadIdx.x) >> 5;
    int lane = threadIdx.x & 31;
    if (n >= NN) return;
    const int i4 = lane << 2;
    float4 wv = *(const float4*)(W + i4);
    float4 hv[T_STEPS];
    float s[T_STEPS];
#pragma unroll
    for (int t = 0; t < T_STEPS; t++) {
        hv[t] = *(const float4*)(h + ((size_t)t * NN + n) * HID + i4);
        s[t] = warp_sum(dot4(hv[t], wv)) + b[0];
    }
    float mx = s[0];
#pragma unroll
    for (int t = 1; t < T_STEPS; t++) mx = fmaxf(mx, s[t]);
    float aw[T_STEPS]; float tot = 0.0f;
#pragma unroll
    for (int t = 0; t < T_STEPS; t++) { aw[t] = expf(s[t] - mx); tot += aw[t]; }
    float inv = 1.0f / tot;
#pragma unroll
    for (int t = 0; t < T_STEPS; t++) aw[t] *= inv;
    bool sel[T_STEPS];
#pragma unroll
    for (int t = 0; t < T_STEPS; t++) sel[t] = false;
    float sum3 = 0.0f;
#pragma unroll
    for (int r = 0; r < 3; r++) {
        float best = -1.0f; int bi = 0;
#pragma unroll
        for (int t = 0; t < T_STEPS; t++)
            if (!sel[t] && aw[t] > best) { best = aw[t]; bi = t; }
        sel[bi] = true; sum3 += best;
    }
    float winv = 1.0f / (sum3 + 1e-8f);
    float4 acc = make_float4(0.f, 0.f, 0.f, 0.f);
#pragma unroll
    for (int t = 0; t < T_STEPS; t++) {
        float w = sel[t] ? aw[t] * winv : 0.0f;
        acc.x += w * hv[t].x; acc.y += w * hv[t].y;
        acc.z += w * hv[t].z; acc.w += w * hv[t].w;
    }
    *(float4*)(hattn + (size_t)n * HID + i4) = acc;
}

// ------------------------- output conv (C_out = 1) ---------------------------
__global__ void __launch_bounds__(256) outconv_node(
    const float* __restrict__ x,
    const float* __restrict__ Wq, const float* __restrict__ bq,
    const float* __restrict__ Wk, const float* __restrict__ bk,
    const float* __restrict__ Wv, const float* __restrict__ bv,
    const float* __restrict__ Ws, const float* __restrict__ bs,
    float* __restrict__ qs, float* __restrict__ ks,
    float* __restrict__ vs, float* __restrict__ outp)
{
    int n = (blockIdx.x * blockDim.x + threadIdx.x) >> 5;
    int lane = threadIdx.x & 31;
    if (n >= NN) return;
    const float* xr = x + (size_t)n * HID;
    float pq = 0.f, pk = 0.f, pv = 0.f, ps = 0.f;
#pragma unroll
    for (int i = lane; i < HID; i += 32) {
        float xv = xr[i];
        pq = fmaf(xv, Wq[i], pq);
        pk = fmaf(xv, Wk[i], pk);
        pv = fmaf(xv, Wv[i], pv);
        ps = fmaf(xv, Ws[i], ps);
    }
    pq = warp_sum(pq); pk = warp_sum(pk); pv = warp_sum(pv); ps = warp_sum(ps);
    if (lane == 0) {
        qs[n] = pq + bq[0];
        ks[n] = pk + bk[0];
        vs[n] = pv + bv[0];
        outp[n] = ps + bs[0];
    }
}

// fused output-conv edge phase (warp/dst, lanes over edges, reuses t=7 CSR)
__global__ void __launch_bounds__(256) oc_edge(
    const float* __restrict__ qs, const float* __restrict__ ks,
    const float* __restrict__ vs, const float* __restrict__ We,
    const int* __restrict__ start, const int* __restrict__ cnt,
    const int* __restrict__ csrc, const float* __restrict__ cea,
    float* __restrict__ outp)
{
    int n = (blockIdx.x * blockDim.x + threadIdx.x) >> 5;
    int lane = threadIdx.x & 31;
    if (n >= NN) return;
    const int g = (T_STEPS - 1) * NN + n;
    const int s0 = start[g], c = cnt[g];
    if (c == 0) return;
    const float qsn = qs[n];
    const float we0 = We[0];

    float mx = -INFINITY;
    for (int j = s0 + lane; j < s0 + c; j += 32) {
        int sl = csrc[j] - (T_STEPS - 1) * NN;
        float al = qsn * (ks[sl] + cea[j] * we0);
        mx = fmaxf(mx, al);
    }
    mx = warp_max(mx);

    float dsum = 0.f, msum = 0.f;
    for (int j = s0 + lane; j < s0 + c; j += 32) {
        int sl = csrc[j] - (T_STEPS - 1) * NN;
        float eav = cea[j];
        float al = qsn * (ks[sl] + eav * we0);
        float a = expf(al - mx);
        dsum += a;
        msum += a * (vs[sl] + eav * we0);
    }
    dsum = warp_sum(dsum);
    msum = warp_sum(msum);
    if (lane == 0) outp[n] += msum / (dsum + 1e-16f);
}

// --------------------------------- host --------------------------------------
static float* symf(const void* sym) { void* p = nullptr; cudaGetSymbolAddress(&p, sym); return (float*)p; }

extern "C" void kernel_launch(void* const* d_in, const int* in_sizes, int n_in,
                              void* d_out, int out_size)
{
    const float* x_seq = (const float*)d_in[0];
    const int*   ei    = (const int*)d_in[1];
    const float* ea    = (const float*)d_in[2];
    const float* W_ih  = (const float*)d_in[3];
    const float* W_hh  = (const float*)d_in[4];
    const float* b_ih  = (const float*)d_in[5];
    const float* b_hh  = (const float*)d_in[6];
    const float* cWq = (const float*)d_in[7];  const float* cbq = (const float*)d_in[8];
    const float* cWk = (const float*)d_in[9];  const float* cbk = (const float*)d_in[10];
    const float* cWv = (const float*)d_in[11]; const float* cbv = (const float*)d_in[12];
    const float* cWe = (const float*)d_in[13];
    const float* cWs = (const float*)d_in[14]; const float* cbs = (const float*)d_in[15];
    const float* oWq = (const float*)d_in[16]; const float* obq = (const float*)d_in[17];
    const float* oWk = (const float*)d_in[18]; const float* obk = (const float*)d_in[19];
    const float* oWv = (const float*)d_in[20]; const float* obv = (const float*)d_in[21];
    const float* oWe = (const float*)d_in[22];
    const float* oWs = (const float*)d_in[23]; const float* obs = (const float*)d_in[24];
    const float* aW  = (const float*)d_in[25]; const float* ab  = (const float*)d_in[26];
    float* outp = (float*)d_out;

    float* ph     = symf(g_h);
    float* ptmp   = symf(g_tmp);
    float* pq     = symf(g_q);
    float* pk     = symf(g_k);
    float* pv     = symf(g_v);
    float* pgi    = symf(g_gi);
    float* pgh    = symf(g_gh);
    float* phprev = symf(g_hprev);
    float* phattn = symf(g_hattn);
    float* pqs    = symf(g_qs);
    float* pks    = symf(g_ks);
    float* pvs    = symf(g_vs);
    int*   pcnt   = (int*)symf(g_cnt);
    int*   pstart = (int*)symf(g_start);
    int*   pcur   = (int*)symf(g_cur);
    int*   pcsrc  = (int*)symf(g_csrc);
    float* pcea   = symf(g_cea);
    __half* wp    = (__half*)symf(g_wprep);

    cudaFuncSetAttribute(mma_gemm, cudaFuncAttributeMaxDynamicSharedMemorySize, SM_BYTES);

    const int nwblk  = (NN + 7) / 8;
    const int tnwblk = (TN + 7) / 8;
    const int teblk  = (TE + 255) / 256;
    const int nhblk  = (NN * HID + 255) / 256;

    // ---------------- weight prep (single launch) ----------------
    {
        WPArgs wa;
        wa.src[0] = W_ih; wa.n[0] = 12288; wa.base[0] = WIH;
        wa.src[1] = W_hh; wa.n[1] = 49152; wa.base[1] = WHH;
        wa.src[2] = cWq;  wa.n[2] = 32768; wa.base[2] = WQ;
        wa.src[3] = cWk;  wa.n[3] = 32768; wa.base[3] = WK;
        wa.src[4] = cWv;  wa.n[4] = 32768; wa.base[4] = WV;
        wa.src[5] = cWs;  wa.n[5] = 32768; wa.base[5] = WS;
        wprep_all<<<dim3((49152 + 255) / 256, 6), 256>>>(wa, wp);
    }

    // ---------------- CSR build (shared by both conv layers + out conv) -----
    cudaMemsetAsync(pcnt, 0, TN * sizeof(int));
    csr_count<<<teblk, 256>>>(ei, pcnt);
    csr_scan<<<1, 1024>>>(pcnt, pstart, pcur);
    csr_scatter<<<teblk, 256>>>(ei, ea, pcur, pcsrc, pcea);

    // ---------------- GRU ----------------
    cudaMemsetAsync(phprev, 0, (size_t)NN * HID * sizeof(float));
    {
        PArgs pa;
        for (int p = 0; p < 3; p++) {
            pa.w[p] = wp + WIH + (size_t)p * 128 * 32;
            pa.lvl[p] = 12288;
            pa.bias[p] = b_ih + p * 128;
            pa.out[p] = pgi; pa.col[p] = p * 128; pa.ldc[p] = G3;
        }
        pa.w[3] = pa.w[2]; pa.lvl[3] = 12288; pa.bias[3] = pa.bias[2];
        pa.out[3] = pgi; pa.col[3] = 256; pa.ldc[3] = G3;
        mma_gemm<<<(TN + 127) / 128, 256, SM_BYTES>>>(pa, x_seq, TN, 32, 3);
    }
    {
        PArgs pa;
        for (int p = 0; p < 3; p++) {
            pa.w[p] = wp + WHH + (size_t)p * 128 * 128;
            pa.lvl[p] = 49152;
            pa.bias[p] = b_hh + p * 128;
            pa.out[p] = pgh; pa.col[p] = p * 128; pa.ldc[p] = G3;
        }
        pa.w[3] = pa.w[2]; pa.lvl[3] = 49152; pa.bias[3] = pa.bias[2];
        pa.out[3] = pgh; pa.col[3] = 256; pa.ldc[3] = G3;
        for (int t = 0; t < T_STEPS; t++) {
            mma_gemm<<<(NN + 127) / 128, 256, SM_BYTES>>>(pa, phprev, NN, 128, 3);
            gru_gate<<<nhblk, 256>>>(pgi + (size_t)t * NN * G3, pgh, phprev,
                                     ph + (size_t)t * NN * HID);
        }
    }

    // ---------------- GNN: 2 layers, batched over all T ----------------
    for (int l = 0; l < 2; l++) {
        const float* in  = (l == 0) ? ph : ptmp;
        float*       out = (l == 0) ? ptmp : ph;
        const float* We = cWe + (size_t)l * HID;
        size_t lo = (size_t)l * 16384;

        PArgs pa;
        pa.w[0] = wp + WQ + lo; pa.lvl[0] = 32768; pa.bias[0] = cbq + l * 128;
        pa.out[0] = pq;  pa.col[0] = 0; pa.ldc[0] = 128;
        pa.w[1] = wp + WK + lo; pa.lvl[1] = 32768; pa.bias[1] = cbk + l * 128;
        pa.out[1] = pk;  pa.col[1] = 0; pa.ldc[1] = 128;
        pa.w[2] = wp + WV + lo; pa.lvl[2] = 32768; pa.bias[2] = cbv + l * 128;
        pa.out[2] = pv;  pa.col[2] = 0; pa.ldc[2] = 128;
        pa.w[3] = wp + WS + lo; pa.lvl[3] = 32768; pa.bias[3] = cbs + l * 128;
        pa.out[3] = out; pa.col[3] = 0; pa.ldc[3] = 128;
        mma_gemm<<<(TN + 127) / 128, 256, SM_BYTES>>>(pa, in, TN, 128, 4);

        conv_edge<<<tnwblk, 256>>>(pq, pk, pv, We, pstart, pcnt, pcsrc, pcea, out);
    }

    // ---------------- temporal attention + top-3 ----------------
    attn_topk<<<nwblk, 256>>>(ph, aW, ab, phattn);

    // ---------------- output TransformerConv (128 -> 1) ----------------
    outconv_node<<<nwblk, 256>>>(phattn, oWq, obq, oWk, obk, oWv, obv, oWs, obs,
                                 pqs, pks, pvs, outp);
    oc_edge<<<nwblk, 256>>>(pqs, pks, pvs, oWe, pstart, pcnt, pcsrc, pcea, outp);
}

// round 10
// speedup vs baseline: 1.9563x; 1.0485x over previous
#include <cuda_runtime.h>
#include <cuda_fp16.h>
#include <math.h>
#include <stdint.h>

#define T_STEPS 8
#define NN      20000
#define FIN_DIM 32
#define EE      160000
#define HID     128
#define G3      384
#define TN      (T_STEPS * NN)
#define TE      (T_STEPS * EE)
#define SCALE   0.08838834764831845f
#define LVL_SC  2048.0f
#define LVL_INV (1.0f / 2048.0f)
#define SCAN_B  1024
#define NBLK_SCAN ((TN + SCAN_B - 1) / SCAN_B)

typedef unsigned long long u64;

// ------------------------- scratch (device globals) -------------------------
__device__ float g_h[(size_t)TN * HID];
__device__ float g_tmp[(size_t)TN * HID];
__device__ float g_q[(size_t)TN * HID];
__device__ float g_k[(size_t)TN * HID];
__device__ float g_v[(size_t)TN * HID];
__device__ float g_gi[(size_t)TN * G3];
__device__ float g_gh[(size_t)NN * G3];
__device__ float g_hprev[(size_t)NN * HID];
__device__ float g_qs[NN], g_ks[NN], g_vs[NN];
__device__ __align__(16) __half g_wprep[385024];   // 2-level fp16 split weights
// CSR
__device__ int   g_cnt[TN];
__device__ int   g_start[TN];
__device__ int   g_cur[TN];
__device__ int   g_bsum[NBLK_SCAN + 8];
__device__ int   g_csrc[TE];
__device__ float g_cea[TE];

#define WIH 0        // level stride 12288
#define WHH 24576    // level stride 49152
#define WQ  122880   // level stride 32768
#define WK  188416
#define WV  253952
#define WS  319488

// ------------------------------- helpers ------------------------------------
__device__ __forceinline__ float warp_sum(float v) {
#pragma unroll
    for (int o = 16; o; o >>= 1) v += __shfl_xor_sync(0xffffffffu, v, o);
    return v;
}
__device__ __forceinline__ float warp_max(float v) {
#pragma unroll
    for (int o = 16; o; o >>= 1) v = fmaxf(v, __shfl_xor_sync(0xffffffffu, v, o));
    return v;
}
__device__ __forceinline__ float dot4(float4 a, float4 b) {
    return a.x * b.x + a.y * b.y + a.z * b.z + a.w * b.w;
}
__device__ __forceinline__ float sigf(float x) { return 1.0f / (1.0f + expf(-x)); }

// --------------------------- mma.sync GEMM (fp16 2-level, 3-pass) ------------
#define ROWB 272
#define LVLB (128 * ROWB)
#define SB_OFF (2 * LVLB)
#define SM_BYTES (4 * LVLB)      // 139264

struct PArgs {
    const __half* w[4];
    int lvl[4];
    const float* bias[4];
    float* out[4];
    int col[4];
    int ldc[4];
};

__device__ __forceinline__ void mma16816(float* c, const uint32_t* a, const uint32_t* b) {
    asm volatile(
        "mma.sync.aligned.m16n8k16.row.col.f32.f16.f16.f32 "
        "{%0,%1,%2,%3},{%4,%5,%6,%7},{%8,%9},{%0,%1,%2,%3};"
        : "+f"(c[0]), "+f"(c[1]), "+f"(c[2]), "+f"(c[3])
        : "r"(a[0]), "r"(a[1]), "r"(a[2]), "r"(a[3]), "r"(b[0]), "r"(b[1]));
}
__device__ __forceinline__ void ldsm_x4(uint32_t& r0, uint32_t& r1, uint32_t& r2, uint32_t& r3,
                                        uint32_t addr) {
    asm volatile("ldmatrix.sync.aligned.m8n8.x4.shared.b16 {%0,%1,%2,%3},[%4];"
                 : "=r"(r0), "=r"(r1), "=r"(r2), "=r"(r3) : "r"(addr));
}
__device__ __forceinline__ void ldsm_x2(uint32_t& r0, uint32_t& r1, uint32_t addr) {
    asm volatile("ldmatrix.sync.aligned.m8n8.x2.shared.b16 {%0,%1},[%2];"
                 : "=r"(r0), "=r"(r1) : "r"(addr));
}
__device__ __forceinline__ uint32_t smem_addr32(const void* p) {
    return (uint32_t)__cvta_generic_to_shared(p);
}

// gi/hprev/hout non-null => GRU mode: after GEMM, fuse gate computation.
__global__ void __launch_bounds__(256) mma_gemm(
    PArgs pa, const float* __restrict__ A, int nrows, int K, int np,
    const float* __restrict__ gi, float* __restrict__ hprev, float* __restrict__ hout)
{
    extern __shared__ char sm[];
    const uint32_t smu = smem_addr32(sm);
    const int tid = threadIdx.x, wid = tid >> 5, lane = tid & 31;
    const int brow = blockIdx.x << 7;
    const int kshift = (K == 32) ? 5 : 7;

    const int wm = (wid & 1) * 64;
    const int wn = (wid >> 1) * 32;
    const uint32_t aoff = (uint32_t)((lane & 15) * ROWB + ((lane >> 4) & 1) * 16);
    const uint32_t boff = (uint32_t)((lane & 7) * ROWB + ((lane >> 3) & 1) * 16);

    // ---- stage A once: fp32 -> 2 fp16 levels (level 1 scaled x2048) ----
    for (int base = tid * 8; base < (128 << kshift); base += 2048) {
        const int row = base >> kshift;
        const int col = base & (K - 1);
        const int gr = brow + row;
        float4 x0 = make_float4(0.f, 0.f, 0.f, 0.f), x1 = x0;
        if (gr < nrows) {
            const float* src = A + (size_t)gr * K + col;
            x0 = *(const float4*)src;
            x1 = *(const float4*)(src + 4);
        }
        const float av[8] = {x0.x, x0.y, x0.z, x0.w, x1.x, x1.y, x1.z, x1.w};
        uint32_t p0[4], p1[4];
#pragma unroll
        for (int j = 0; j < 4; j++) {
            float a0 = av[2 * j], a1 = av[2 * j + 1];
            __half h0 = __float2half_rn(a0), h1 = __float2half_rn(a1);
            float r0 = (a0 - __half2float(h0)) * LVL_SC;
            float r1 = (a1 - __half2float(h1)) * LVL_SC;
            union { __half2 h; uint32_t u; } uh, ul;
            uh.h = __halves2half2(h0, h1);
            ul.h = __halves2half2(__float2half_rn(r0), __float2half_rn(r1));
            p0[j] = uh.u; p1[j] = ul.u;
        }
        char* dst = sm + row * ROWB + col * 2;
        *(uint4*)(dst) = make_uint4(p0[0], p0[1], p0[2], p0[3]);
        *(uint4*)(dst + LVLB) = make_uint4(p1[0], p1[1], p1[2], p1[3]);
    }

    const int nb = (128 << kshift) >> 3;

    for (int p = 0; p < np; p++) {
        __syncthreads();
        const __half* W0 = pa.w[p];
        const int lvl = pa.lvl[p];
#pragma unroll
        for (int lv = 0; lv < 2; lv++) {
            const __half* Wl = W0 + (size_t)lv * lvl;
            char* dstb = sm + SB_OFF + lv * LVLB;
            for (int i = tid; i < nb; i += 256) {
                const int e = i * 8;
                const int row = e >> kshift;
                const int col = e & (K - 1);
                *(uint4*)(dstb + row * ROWB + col * 2) =
                    *(const uint4*)(Wl + (size_t)row * K + col);
            }
        }
        __syncthreads();

        float acc0[4][4][4], acc1[4][4][4];
#pragma unroll
        for (int i = 0; i < 4; i++)
#pragma unroll
            for (int j = 0; j < 4; j++)
#pragma unroll
                for (int r = 0; r < 4; r++) { acc0[i][j][r] = 0.0f; acc1[i][j][r] = 0.0f; }

        const int nk = K >> 4;
        for (int ks = 0; ks < nk; ks++) {
            const uint32_t k2 = (uint32_t)(ks << 5);
            uint32_t bf0[4][2], bf1[4][2];
            {
                const uint32_t bb0 = smu + SB_OFF + k2 + boff;
                const uint32_t bb1 = bb0 + LVLB;
#pragma unroll
                for (int nt = 0; nt < 4; nt++) {
                    ldsm_x2(bf0[nt][0], bf0[nt][1], bb0 + (uint32_t)((wn + nt * 8) * ROWB));
                    ldsm_x2(bf1[nt][0], bf1[nt][1], bb1 + (uint32_t)((wn + nt * 8) * ROWB));
                }
            }
            uint32_t af[4][4];
            {
                const uint32_t ab = smu + k2 + aoff;
#pragma unroll
                for (int mt = 0; mt < 4; mt++)
                    ldsm_x4(af[mt][0], af[mt][1], af[mt][2], af[mt][3],
                            ab + (uint32_t)((wm + mt * 16) * ROWB));
#pragma unroll
                for (int mt = 0; mt < 4; mt++)
#pragma unroll
                    for (int nt = 0; nt < 4; nt++) {
                        mma16816(acc0[mt][nt], af[mt], bf0[nt]);
                        mma16816(acc1[mt][nt], af[mt], bf1[nt]);
                    }
            }
            {
                const uint32_t ab = smu + LVLB + k2 + aoff;
#pragma unroll
                for (int mt = 0; mt < 4; mt++)
                    ldsm_x4(af[mt][0], af[mt][1], af[mt][2], af[mt][3],
                            ab + (uint32_t)((wm + mt * 16) * ROWB));
#pragma unroll
                for (int mt = 0; mt < 4; mt++)
#pragma unroll
                    for (int nt = 0; nt < 4; nt++)
                        mma16816(acc1[mt][nt], af[mt], bf0[nt]);
            }
        }

        float* Co = pa.out[p];
        const float* bs = pa.bias[p];
        const int ld = pa.ldc[p], cb = pa.col[p];
#pragma unroll
        for (int nt = 0; nt < 4; nt++) {
            const int cloc = wn + nt * 8 + (lane & 3) * 2;
            const float b0 = bs[cloc], b1 = bs[cloc + 1];
#pragma unroll
            for (int mt = 0; mt < 4; mt++) {
                const int r0 = brow + wm + mt * 16 + (lane >> 2);
                if (r0 < nrows) {
                    float2 o = make_float2(acc0[mt][nt][0] + acc1[mt][nt][0] * LVL_INV + b0,
                                           acc0[mt][nt][1] + acc1[mt][nt][1] * LVL_INV + b1);
                    *(float2*)(Co + (size_t)r0 * ld + cb + cloc) = o;
                }
                const int r1 = r0 + 8;
                if (r1 < nrows) {
                    float2 o = make_float2(acc0[mt][nt][2] + acc1[mt][nt][2] * LVL_INV + b0,
                                           acc0[mt][nt][3] + acc1[mt][nt][3] * LVL_INV + b1);
                    *(float2*)(Co + (size_t)r1 * ld + cb + cloc) = o;
                }
            }
        }
    }

    // ---- fused GRU gate (CTA-local rows; gh just written is block-visible) ----
    if (gi != nullptr) {
        __syncthreads();
        const float* gh = pa.out[0];   // [nrows, G3], cols 0/128/256 from projections
        for (int i = tid; i < 128 * 32; i += 256) {
            const int row = i >> 5;
            const int n = brow + row;
            if (n >= nrows) break;
            const int c4 = (i & 31) << 2;
            const float* gin = gi + (size_t)n * G3;
            const float* ghn = gh + (size_t)n * G3;
            float4 ir = *(const float4*)(gin + c4);
            float4 iz = *(const float4*)(gin + 128 + c4);
            float4 in_ = *(const float4*)(gin + 256 + c4);
            float4 hr = *(const float4*)(ghn + c4);
            float4 hz = *(const float4*)(ghn + 128 + c4);
            float4 hn_ = *(const float4*)(ghn + 256 + c4);
            float4 hp = *(const float4*)(hprev + (size_t)n * HID + c4);
            float4 o;
            {
                float r = sigf(ir.x + hr.x), z = sigf(iz.x + hz.x);
                float nn = tanhf(in_.x + r * hn_.x);
                o.x = (1.0f - z) * nn + z * hp.x;
            }
            {
                float r = sigf(ir.y + hr.y), z = sigf(iz.y + hz.y);
                float nn = tanhf(in_.y + r * hn_.y);
                o.y = (1.0f - z) * nn + z * hp.y;
            }
            {
                float r = sigf(ir.z + hr.z), z = sigf(iz.z + hz.z);
                float nn = tanhf(in_.z + r * hn_.z);
                o.z = (1.0f - z) * nn + z * hp.z;
            }
            {
                float r = sigf(ir.w + hr.w), z = sigf(iz.w + hz.w);
                float nn = tanhf(in_.w + r * hn_.w);
                o.w = (1.0f - z) * nn + z * hp.w;
            }
            *(float4*)(hprev + (size_t)n * HID + c4) = o;
            *(float4*)(hout + (size_t)n * HID + c4) = o;
        }
    }
}

// -------------------- merged weight prep (fp32 -> 2x fp16) -------------------
struct WPArgs { const float* src[6]; int n[6]; int base[6]; };

__global__ void wprep_all(WPArgs wa, __half* __restrict__ wp)
{
    int seg = blockIdx.y;
    int i = blockIdx.x * blockDim.x + threadIdx.x;
    if (i >= wa.n[seg]) return;
    float x = wa.src[seg][i];
    __half h = __float2half_rn(x);
    float r = (x - __half2float(h)) * LVL_SC;
    __half* w = wp + wa.base[seg];
    int n = wa.n[seg];
    w[i] = h;
    w[n + i] = __float2half_rn(r);
}

// ------------------------------- CSR build -----------------------------------
__global__ void csr_count(const int* __restrict__ ei, int* __restrict__ cnt)
{
    int w = blockIdx.x * blockDim.x + threadIdx.x;
    if (w >= TE) return;
    int t = w / EE, e = w - t * EE;
    int d = ei[(size_t)t * 2 * EE + EE + e] + t * NN;
    atomicAdd(&cnt[d], 1);
}

// per-block inclusive scan; writes inclusive values + block sums
__global__ void __launch_bounds__(SCAN_B) scan1(
    const int* __restrict__ cnt, int* __restrict__ incl, int* __restrict__ bsum)
{
    __shared__ int sh[SCAN_B];
    int g = blockIdx.x * SCAN_B + threadIdx.x;
    int v = (g < TN) ? cnt[g] : 0;
    sh[threadIdx.x] = v;
    __syncthreads();
#pragma unroll
    for (int off = 1; off < SCAN_B; off <<= 1) {
        int add = (threadIdx.x >= off) ? sh[threadIdx.x - off] : 0;
        __syncthreads();
        sh[threadIdx.x] += add;
        __syncthreads();
    }
    if (g < TN) incl[g] = sh[threadIdx.x];
    if (threadIdx.x == SCAN_B - 1) bsum[blockIdx.x] = sh[SCAN_B - 1];
}

// 1-block exclusive scan of block sums (NBLK_SCAN <= 256)
__global__ void __launch_bounds__(256) scan2(int* __restrict__ bsum)
{
    __shared__ int sh[256];
    int v = (threadIdx.x < NBLK_SCAN) ? bsum[threadIdx.x] : 0;
    sh[threadIdx.x] = v;
    __syncthreads();
#pragma unroll
    for (int off = 1; off < 256; off <<= 1) {
        int add = (threadIdx.x >= off) ? sh[threadIdx.x - off] : 0;
        __syncthreads();
        sh[threadIdx.x] += add;
        __syncthreads();
    }
    if (threadIdx.x < NBLK_SCAN) bsum[threadIdx.x] = sh[threadIdx.x] - v;
}

__global__ void scan3(const int* __restrict__ cnt, const int* __restrict__ incl,
                      const int* __restrict__ bsum, int* __restrict__ start,
                      int* __restrict__ cur)
{
    int g = blockIdx.x * blockDim.x + threadIdx.x;
    if (g >= TN) return;
    int s = incl[g] - cnt[g] + bsum[g / SCAN_B];
    start[g] = s;
    cur[g] = s;
}

__global__ void csr_scatter(const int* __restrict__ ei, const float* __restrict__ ea,
                            int* __restrict__ cur, int* __restrict__ csrc,
                            float* __restrict__ cea)
{
    int w = blockIdx.x * blockDim.x + threadIdx.x;
    if (w >= TE) return;
    int t = w / EE, e = w - t * EE;
    const int* eib = ei + (size_t)t * 2 * EE;
    int s = eib[e] + t * NN;
    int d = eib[EE + e] + t * NN;
    int pos = atomicAdd(&cur[d], 1);
    csrc[pos] = s;
    cea[pos] = ea[w];
}

// -------------- fused conv edge phase: warp/dst, streaming softmax -----------
__global__ void __launch_bounds__(256) conv_edge(
    const float* __restrict__ q, const float* __restrict__ k,
    const float* __restrict__ v, const float* __restrict__ We,
    const int* __restrict__ start, const int* __restrict__ cnt,
    const int* __restrict__ csrc, const float* __restrict__ cea,
    float* __restrict__ out)
{
    int n = (blockIdx.x * blockDim.x + threadIdx.x) >> 5;
    int lane = threadIdx.x & 31;
    if (n >= TN) return;
    const int i4 = lane << 2;
    float4 qv = *(const float4*)(q + (size_t)n * HID + i4);
    float4 wev = *(const float4*)(We + i4);
    float qwe = warp_sum(dot4(qv, wev)) * SCALE;

    const int s0 = start[n], c = cnt[n];
    float mx = -INFINITY, denom = 0.0f, coef = 0.0f;
    float4 macc = make_float4(0.f, 0.f, 0.f, 0.f);

    for (int j = s0; j < s0 + c; j++) {
        int s = csrc[j];
        float eav = cea[j];
        float4 kv = *(const float4*)(k + (size_t)s * HID + i4);
        float p = warp_sum(dot4(qv, kv));
        float al = p * SCALE + eav * qwe;
        float4 vv = *(const float4*)(v + (size_t)s * HID + i4);
        if (al > mx) {
            float sc = expf(mx - al);
            denom *= sc; coef *= sc;
            macc.x *= sc; macc.y *= sc; macc.z *= sc; macc.w *= sc;
            mx = al;
        }
        float a = expf(al - mx);
        denom += a;
        coef += a * eav;
        macc.x += a * vv.x; macc.y += a * vv.y; macc.z += a * vv.z; macc.w += a * vv.w;
    }

    float inv = 1.0f / (denom + 1e-16f);
    float4 sk = *(const float4*)(out + (size_t)n * HID + i4);
    float4 o;
    o.x = sk.x + (macc.x + coef * wev.x) * inv;
    o.y = sk.y + (macc.y + coef * wev.y) * inv;
    o.z = sk.z + (macc.z + coef * wev.z) * inv;
    o.w = sk.w + (macc.w + coef * wev.w) * inv;
    o.x = o.x > 0.f ? o.x : 0.01f * o.x;
    o.y = o.y > 0.f ? o.y : 0.01f * o.y;
    o.z = o.z > 0.f ? o.z : 0.01f * o.z;
    o.w = o.w > 0.f ? o.w : 0.01f * o.w;
    *(float4*)(out + (size_t)n * HID + i4) = o;
}

// ------- fused temporal attention + top-3 + output-conv projections ----------
__global__ void __launch_bounds__(256) attn_outproj(
    const float* __restrict__ h, const float* __restrict__ W,
    const float* __restrict__ b,
    const float* __restrict__ Wq, const float* __restrict__ bq,
    const float* __restrict__ Wk, const float* __restrict__ bk,
    const float* __restrict__ Wv, const float* __restrict__ bv,
    const float* __restrict__ Ws, const float* __restrict__ bs,
    float* __restrict__ qs, float* __restrict__ ks,
    float* __restrict__ vs, float* __restrict__ outp)
{
    int n = (blockIdx.x * blockDim.x + threadIdx.x) >> 5;
    int lane = threadIdx.x & 31;
    if (n >= NN) return;
    const int i4 = lane << 2;
    float4 wv = *(const float4*)(W + i4);
    float4 hv[T_STEPS];
    float s[T_STEPS];
#pragma unroll
    for (int t = 0; t < T_STEPS; t++) {
        hv[t] = *(const float4*)(h + ((size_t)t * NN + n) * HID + i4);
        s[t] = warp_sum(dot4(hv[t], wv)) + b[0];
    }
    float mx = s[0];
#pragma unroll
    for (int t = 1; t < T_STEPS; t++) mx = fmaxf(mx, s[t]);
    float aw[T_STEPS]; float tot = 0.0f;
#pragma unroll
    for (int t = 0; t < T_STEPS; t++) { aw[t] = expf(s[t] - mx); tot += aw[t]; }
    float inv = 1.0f / tot;
#pragma unroll
    for (int t = 0; t < T_STEPS; t++) aw[t] *= inv;
    bool sel[T_STEPS];
#pragma unroll
    for (int t = 0; t < T_STEPS; t++) sel[t] = false;
    float sum3 = 0.0f;
#pragma unroll
    for (int r = 0; r < 3; r++) {
        float best = -1.0f; int bi = 0;
#pragma unroll
        for (int t = 0; t < T_STEPS; t++)
            if (!sel[t] && aw[t] > best) { best = aw[t]; bi = t; }
        sel[bi] = true; sum3 += best;
    }
    float winv = 1.0f / (sum3 + 1e-8f);
    float4 acc = make_float4(0.f, 0.f, 0.f, 0.f);
#pragma unroll
    for (int t = 0; t < T_STEPS; t++) {
        float w = sel[t] ? aw[t] * winv : 0.0f;
        acc.x += w * hv[t].x; acc.y += w * hv[t].y;
        acc.z += w * hv[t].z; acc.w += w * hv[t].w;
    }
    // output-conv projections directly from register-resident h_attn row
    float4 wq = *(const float4*)(Wq + i4);
    float4 wk = *(const float4*)(Wk + i4);
    float4 wvv = *(const float4*)(Wv + i4);
    float4 ws = *(const float4*)(Ws + i4);
    float pq = warp_sum(dot4(acc, wq));
    float pk = warp_sum(dot4(acc, wk));
    float pv = warp_sum(dot4(acc, wvv));
    float ps = warp_sum(dot4(acc, ws));
    if (lane == 0) {
        qs[n] = pq + bq[0];
        ks[n] = pk + bk[0];
        vs[n] = pv + bv[0];
        outp[n] = ps + bs[0];
    }
}

// fused output-conv edge phase (warp/dst, lanes over edges, reuses t=7 CSR)
__global__ void __launch_bounds__(256) oc_edge(
    const float* __restrict__ qs, const float* __restrict__ ks,
    const float* __restrict__ vs, const float* __restrict__ We,
    const int* __restrict__ start, const int* __restrict__ cnt,
    const int* __restrict__ csrc, const float* __restrict__ cea,
    float* __restrict__ outp)
{
    int n = (blockIdx.x * blockDim.x + threadIdx.x) >> 5;
    int lane = threadIdx.x & 31;
    if (n >= NN) return;
    const int g = (T_STEPS - 1) * NN + n;
    const int s0 = start[g], c = cnt[g];
    if (c == 0) return;
    const float qsn = qs[n];
    const float we0 = We[0];

    float mx = -INFINITY;
    for (int j = s0 + lane; j < s0 + c; j += 32) {
        int sl = csrc[j] - (T_STEPS - 1) * NN;
        float al = qsn * (ks[sl] + cea[j] * we0);
        mx = fmaxf(mx, al);
    }
    mx = warp_max(mx);

    float dsum = 0.f, msum = 0.f;
    for (int j = s0 + lane; j < s0 + c; j += 32) {
        int sl = csrc[j] - (T_STEPS - 1) * NN;
        float eav = cea[j];
        float al = qsn * (ks[sl] + eav * we0);
        float a = expf(al - mx);
        dsum += a;
        msum += a * (vs[sl] + eav * we0);
    }
    dsum = warp_sum(dsum);
    msum = warp_sum(msum);
    if (lane == 0) outp[n] += msum / (dsum + 1e-16f);
}

// --------------------------------- host --------------------------------------
static float* symf(const void* sym) { void* p = nullptr; cudaGetSymbolAddress(&p, sym); return (float*)p; }

extern "C" void kernel_launch(void* const* d_in, const int* in_sizes, int n_in,
                              void* d_out, int out_size)
{
    const float* x_seq = (const float*)d_in[0];
    const int*   ei    = (const int*)d_in[1];
    const float* ea    = (const float*)d_in[2];
    const float* W_ih  = (const float*)d_in[3];
    const float* W_hh  = (const float*)d_in[4];
    const float* b_ih  = (const float*)d_in[5];
    const float* b_hh  = (const float*)d_in[6];
    const float* cWq = (const float*)d_in[7];  const float* cbq = (const float*)d_in[8];
    const float* cWk = (const float*)d_in[9];  const float* cbk = (const float*)d_in[10];
    const float* cWv = (const float*)d_in[11]; const float* cbv = (const float*)d_in[12];
    const float* cWe = (const float*)d_in[13];
    const float* cWs = (const float*)d_in[14]; const float* cbs = (const float*)d_in[15];
    const float* oWq = (const float*)d_in[16]; const float* obq = (const float*)d_in[17];
    const float* oWk = (const float*)d_in[18]; const float* obk = (const float*)d_in[19];
    const float* oWv = (const float*)d_in[20]; const float* obv = (const float*)d_in[21];
    const float* oWe = (const float*)d_in[22];
    const float* oWs = (const float*)d_in[23]; const float* obs = (const float*)d_in[24];
    const float* aW  = (const float*)d_in[25]; const float* ab  = (const float*)d_in[26];
    float* outp = (float*)d_out;

    float* ph     = symf(g_h);
    float* ptmp   = symf(g_tmp);
    float* pq     = symf(g_q);
    float* pk     = symf(g_k);
    float* pv     = symf(g_v);
    float* pgi    = symf(g_gi);
    float* pgh    = symf(g_gh);
    float* phprev = symf(g_hprev);
    float* pqs    = symf(g_qs);
    float* pks    = symf(g_ks);
    float* pvs    = symf(g_vs);
    int*   pcnt   = (int*)symf(g_cnt);
    int*   pstart = (int*)symf(g_start);
    int*   pcur   = (int*)symf(g_cur);
    int*   pbsum  = (int*)symf(g_bsum);
    int*   pcsrc  = (int*)symf(g_csrc);
    float* pcea   = symf(g_cea);
    __half* wp    = (__half*)symf(g_wprep);

    cudaFuncSetAttribute(mma_gemm, cudaFuncAttributeMaxDynamicSharedMemorySize, SM_BYTES);

    const int nwblk  = (NN + 7) / 8;
    const int tnwblk = (TN + 7) / 8;
    const int teblk  = (TE + 255) / 256;
    const int tnblk  = (TN + 255) / 256;

    // ---------------- weight prep ----------------
    {
        WPArgs wa;
        wa.src[0] = W_ih; wa.n[0] = 12288; wa.base[0] = WIH;
        wa.src[1] = W_hh; wa.n[1] = 49152; wa.base[1] = WHH;
        wa.src[2] = cWq;  wa.n[2] = 32768; wa.base[2] = WQ;
        wa.src[3] = cWk;  wa.n[3] = 32768; wa.base[3] = WK;
        wa.src[4] = cWv;  wa.n[4] = 32768; wa.base[4] = WV;
        wa.src[5] = cWs;  wa.n[5] = 32768; wa.base[5] = WS;
        wprep_all<<<dim3((49152 + 255) / 256, 6), 256>>>(wa, wp);
    }

    // ---------------- GRU ----------------
    cudaMemsetAsync(phprev, 0, (size_t)NN * HID * sizeof(float));
    {
        PArgs pa;
        for (int p = 0; p < 3; p++) {
            pa.w[p] = wp + WIH + (size_t)p * 128 * 32;
            pa.lvl[p] = 12288;
            pa.bias[p] = b_ih + p * 128;
            pa.out[p] = pgi; pa.col[p] = p * 128; pa.ldc[p] = G3;
        }
        pa.w[3] = pa.w[2]; pa.lvl[3] = 12288; pa.bias[3] = pa.bias[2];
        pa.out[3] = pgi; pa.col[3] = 256; pa.ldc[3] = G3;
        mma_gemm<<<(TN + 127) / 128, 256, SM_BYTES>>>(pa, x_seq, TN, 32, 3,
                                                      nullptr, nullptr, nullptr);
    }
    {
        PArgs pa;
        for (int p = 0; p < 3; p++) {
            pa.w[p] = wp + WHH + (size_t)p * 128 * 128;
            pa.lvl[p] = 49152;
            pa.bias[p] = b_hh + p * 128;
            pa.out[p] = pgh; pa.col[p] = p * 128; pa.ldc[p] = G3;
        }
        pa.w[3] = pa.w[2]; pa.lvl[3] = 49152; pa.bias[3] = pa.bias[2];
        pa.out[3] = pgh; pa.col[3] = 256; pa.ldc[3] = G3;
        for (int t = 0; t < T_STEPS; t++) {
            // fused: GEMM + GRU gate (writes hprev and h_t)
            mma_gemm<<<(NN + 127) / 128, 256, SM_BYTES>>>(
                pa, phprev, NN, 128, 3,
                pgi + (size_t)t * NN * G3, phprev, ph + (size_t)t * NN * HID);
        }
    }

    // ---------------- CSR build (placed here; needed by first conv_edge) ----
    cudaMemsetAsync(pcnt, 0, TN * sizeof(int));
    csr_count<<<teblk, 256>>>(ei, pcnt);
    scan1<<<NBLK_SCAN, SCAN_B>>>(pcnt, pcur, pbsum);
    scan2<<<1, 256>>>(pbsum);
    scan3<<<tnblk, 256>>>(pcnt, pcur, pbsum, pstart, pcur);
    csr_scatter<<<teblk, 256>>>(ei, ea, pcur, pcsrc, pcea);

    // ---------------- GNN: 2 layers, batched over all T ----------------
    for (int l = 0; l < 2; l++) {
        const float* in  = (l == 0) ? ph : ptmp;
        float*       out = (l == 0) ? ptmp : ph;
        const float* We = cWe + (size_t)l * HID;
        size_t lo = (size_t)l * 16384;

        PArgs pa;
        pa.w[0] = wp + WQ + lo; pa.lvl[0] = 32768; pa.bias[0] = cbq + l * 128;
        pa.out[0] = pq;  pa.col[0] = 0; pa.ldc[0] = 128;
        pa.w[1] = wp + WK + lo; pa.lvl[1] = 32768; pa.bias[1] = cbk + l * 128;
        pa.out[1] = pk;  pa.col[1] = 0; pa.ldc[1] = 128;
        pa.w[2] = wp + WV + lo; pa.lvl[2] = 32768; pa.bias[2] = cbv + l * 128;
        pa.out[2] = pv;  pa.col[2] = 0; pa.ldc[2] = 128;
        pa.w[3] = wp + WS + lo; pa.lvl[3] = 32768; pa.bias[3] = cbs + l * 128;
        pa.out[3] = out; pa.col[3] = 0; pa.ldc[3] = 128;
        mma_gemm<<<(TN + 127) / 128, 256, SM_BYTES>>>(pa, in, TN, 128, 4,
                                                      nullptr, nullptr, nullptr);

        conv_edge<<<tnwblk, 256>>>(pq, pk, pv, We, pstart, pcnt, pcsrc, pcea, out);
    }

    // ---------------- temporal attention + top-3 + output conv ----------------
    attn_outproj<<<nwblk, 256>>>(ph, aW, ab, oWq, obq, oWk, obk, oWv, obv,
                                 oWs, obs, pqs, pks, pvs, outp);
    oc_edge<<<nwblk, 256>>>(pqs, pks, pvs, oWe, pstart, pcnt, pcsrc, pcea, outp);
}